// round 9
// baseline (speedup 1.0000x reference)
#include <cuda_runtime.h>
#include <cuda_bf16.h>
#include <math.h>
#include <stdint.h>

// ---------------- problem constants ----------------
#define BATCH 512
#define NPRIM 32
#define NCLASS 10

// ---------------- scratch (static device memory; no allocs allowed) ----------------
// conv1 output as bf16 hi/lo split, layout [b][pixel(400)][ic(256)]
__device__ __align__(256) unsigned short g_h1h[BATCH * 400 * 256];   // 100 MB
__device__ __align__(256) unsigned short g_h1l[BATCH * 400 * 256];   // 100 MB
// prim weights prepacked: [kpos25][chunk4][oc256][ic64] bf16 hi/lo
__device__ __align__(256) unsigned short g_Wph[25 * 4 * 256 * 64];   // 3.3 MB
__device__ __align__(256) unsigned short g_Wpl[25 * 4 * 256 * 64];   // 3.3 MB
__device__ float g_cwT[8 * 25 * 256];                    // conv_w transposed [c*25+k][oc]
__device__ float g_p[BATCH * NPRIM * 8 * 64];            // primary caps acts [b][i][a][pos]
__device__ float g_masked[BATCH * 160];
__device__ float g_r1[BATCH * 512];
__device__ float g_r2[BATCH * 1024];

// ---------------- f32x2 helpers ----------------
__device__ __forceinline__ unsigned long long bcast2(float v) {
    unsigned long long r;
    asm("mov.b64 %0, {%1, %1};" : "=l"(r) : "f"(v));
    return r;
}
__device__ __forceinline__ void fma2(unsigned long long& acc, unsigned long long a,
                                     unsigned long long b) {
    asm("fma.rn.f32x2 %0, %1, %2, %0;" : "+l"(acc) : "l"(a), "l"(b));
}
__device__ __forceinline__ float2 unpk(unsigned long long v) {
    float2 r;
    asm("mov.b64 {%0, %1}, %2;" : "=f"(r.x), "=f"(r.y) : "l"(v));
    return r;
}

// ---------------- cp.async helpers ----------------
__device__ __forceinline__ void cp16(void* smem, const void* g) {
    unsigned s;
    asm("{ .reg .u64 t; cvta.to.shared.u64 t, %1; cvt.u32.u64 %0, t; }"
        : "=r"(s) : "l"(smem));
    asm volatile("cp.async.cg.shared.global [%0], [%1], 16;" :: "r"(s), "l"(g));
}
__device__ __forceinline__ void cp_commit() { asm volatile("cp.async.commit_group;"); }
__device__ __forceinline__ void cp_wait0() {
    asm volatile("cp.async.wait_group 0;" ::: "memory");
}

// ---------------- mma.sync bf16 + ldmatrix (sm_80+ legacy tensor path) ----------------
__device__ __forceinline__ void mma_bf16(float* d, const uint32_t* a, uint32_t b0,
                                         uint32_t b1) {
    asm volatile(
        "mma.sync.aligned.m16n8k16.row.col.f32.bf16.bf16.f32 "
        "{%0,%1,%2,%3}, {%4,%5,%6,%7}, {%8,%9}, {%0,%1,%2,%3};"
        : "+f"(d[0]), "+f"(d[1]), "+f"(d[2]), "+f"(d[3])
        : "r"(a[0]), "r"(a[1]), "r"(a[2]), "r"(a[3]), "r"(b0), "r"(b1));
}
__device__ __forceinline__ void ldm_x4(uint32_t* r, uint32_t addr) {
    asm volatile("ldmatrix.sync.aligned.m8n8.x4.shared.b16 {%0,%1,%2,%3}, [%4];"
        : "=r"(r[0]), "=r"(r[1]), "=r"(r[2]), "=r"(r[3]) : "r"(addr));
}
__device__ __forceinline__ uint32_t smem_u32(const void* p) {
    uint32_t a;
    asm("{ .reg .u64 t; cvta.to.shared.u64 t, %1; cvt.u32.u64 %0, t; }" : "=r"(a) : "l"(p));
    return a;
}

// ---------------- weight transpose: w[oc][ick] -> wt[ick][oc] ----------------
__global__ void transpose_oc(const float* __restrict__ w, float* __restrict__ wt,
                             int OC, int ICK) {
    int idx = blockIdx.x * 256 + threadIdx.x;
    if (idx >= OC * ICK) return;
    int ick = idx / OC, oc = idx % OC;
    wt[idx] = w[oc * ICK + ick];
}

// ---------------- prepack prim weights: [kpos][chunk][oc][ic64] bf16 hi/lo ------------
__global__ void prepack_W(const float* __restrict__ w) {
    int idx = blockIdx.x * 256 + threadIdx.x;
    if (idx >= 25 * 4 * 256 * 64) return;
    int ic = idx & 63;
    int oc = (idx >> 6) & 255;
    int chunk = (idx >> 14) & 3;
    int kpos = idx >> 16;
    float v = w[oc * 6400 + (chunk * 64 + ic) * 25 + kpos];
    __nv_bfloat16 hi = __float2bfloat16(v);
    __nv_bfloat16 lo = __float2bfloat16(v - __bfloat162float(hi));
    g_Wph[idx] = __bfloat16_as_ushort(hi);
    g_Wpl[idx] = __bfloat16_as_ushort(lo);
}

// ---------------- conv1 + relu (f32x2), writes bf16 hi/lo [b][pix][ic] ----------------
__global__ __launch_bounds__(256) void conv1_kernel(
    const float* __restrict__ x, const float* __restrict__ w,
    const float* __restrict__ bias) {
    __shared__ float sx[784];
    __shared__ float sw2[81 * 16];
    __shared__ float sb[16];
    int b = blockIdx.x, g = blockIdx.y, tid = threadIdx.x;
    for (int i = tid; i < 784; i += 256) sx[i] = x[b * 784 + i];
    for (int i = tid; i < 81 * 16; i += 256) {
        int k = i >> 4, c = i & 15;
        sw2[i] = w[(g * 16 + c) * 81 + k];
    }
    if (tid < 16) sb[tid] = bias[g * 16 + tid];
    __syncthreads();

    int p0 = tid;
    int p1 = tid + 256;
    bool has1 = (p1 < 400);
    int p1c = has1 ? p1 : 0;
    int y0 = p0 / 20, x0 = p0 % 20;
    int y1 = p1c / 20, x1 = p1c % 20;
    unsigned long long a0[8], a1[8];
#pragma unroll
    for (int j = 0; j < 8; j++) { a0[j] = 0ULL; a1[j] = 0ULL; }
#pragma unroll
    for (int kh = 0; kh < 9; kh++) {
#pragma unroll
        for (int kw = 0; kw < 9; kw++) {
            unsigned long long d0 = bcast2(sx[(y0 + kh) * 28 + x0 + kw]);
            unsigned long long d1 = bcast2(sx[(y1 + kh) * 28 + x1 + kw]);
            int k = kh * 9 + kw;
            const ulonglong2* wp = (const ulonglong2*)&sw2[k * 16];
            ulonglong2 wA = wp[0], wB = wp[1], wC = wp[2], wD = wp[3];
            fma2(a0[0], d0, wA.x); fma2(a0[1], d0, wA.y);
            fma2(a0[2], d0, wB.x); fma2(a0[3], d0, wB.y);
            fma2(a0[4], d0, wC.x); fma2(a0[5], d0, wC.y);
            fma2(a0[6], d0, wD.x); fma2(a0[7], d0, wD.y);
            fma2(a1[0], d1, wA.x); fma2(a1[1], d1, wA.y);
            fma2(a1[2], d1, wB.x); fma2(a1[3], d1, wB.y);
            fma2(a1[4], d1, wC.x); fma2(a1[5], d1, wC.y);
            fma2(a1[6], d1, wD.x); fma2(a1[7], d1, wD.y);
        }
    }
#pragma unroll
    for (int half = 0; half < 2; half++) {
        if (half == 1 && !has1) break;
        int p = half ? p1 : p0;
        unsigned long long* A = half ? a1 : a0;
        uint32_t hw[8], lw[8];
#pragma unroll
        for (int j = 0; j < 8; j++) {
            float2 v = unpk(A[j]);
            float r0 = v.x + sb[2 * j];     r0 = r0 > 0.f ? r0 : 0.f;
            float r1 = v.y + sb[2 * j + 1]; r1 = r1 > 0.f ? r1 : 0.f;
            __nv_bfloat16 h0 = __float2bfloat16(r0);
            __nv_bfloat16 h1 = __float2bfloat16(r1);
            __nv_bfloat16 l0 = __float2bfloat16(r0 - __bfloat162float(h0));
            __nv_bfloat16 l1 = __float2bfloat16(r1 - __bfloat162float(h1));
            hw[j] = (uint32_t)__bfloat16_as_ushort(h0) |
                    ((uint32_t)__bfloat16_as_ushort(h1) << 16);
            lw[j] = (uint32_t)__bfloat16_as_ushort(l0) |
                    ((uint32_t)__bfloat16_as_ushort(l1) << 16);
        }
        size_t base = ((size_t)b * 400 + p) * 256 + g * 16;
        uint4* dh = (uint4*)&g_h1h[base];
        uint4* dl = (uint4*)&g_h1l[base];
        dh[0] = make_uint4(hw[0], hw[1], hw[2], hw[3]);
        dh[1] = make_uint4(hw[4], hw[5], hw[6], hw[7]);
        dl[0] = make_uint4(lw[0], lw[1], lw[2], lw[3]);
        dl[1] = make_uint4(lw[4], lw[5], lw[6], lw[7]);
    }
}

// ---------------- primary caps conv via mma.sync + ldmatrix (unchanged from R8) -------
#define PITCH 144
#define OFF_AH 0
#define OFF_AL 18432                   // 128*144
#define OFF_BH 36864
#define OFF_BL 73728                   // OFF_BH + 256*144
#define PBUF 110592
#define PRIM_SMEM (2 * PBUF)           // 221184

extern __shared__ char psmem[];

__device__ __forceinline__ void prim_load_step(int buf, int s, int tid, int b0) {
    int kpos = s >> 2, chunk = s & 3;
    int kh = kpos / 5, kw = kpos - kh * 5;
    char* base = psmem + buf * PBUF;
#pragma unroll
    for (int ii = 0; ii < 2; ii++) {
        int i = tid + ii * 512;
        int r = i >> 3, seg = i & 7;
        int batch = r >> 6, pos = r & 63;
        int y = pos >> 3, xx = pos & 7;
        int pix = (2 * y + kh) * 20 + 2 * xx + kw;
        size_t src = ((size_t)(b0 + batch) * 400 + pix) * 256 + chunk * 64 + seg * 8;
        char* d = base + r * PITCH + seg * 16;
        cp16(d + OFF_AH, &g_h1h[src]);
        cp16(d + OFF_AL, &g_h1l[src]);
    }
    size_t wbase = (size_t)s * 16384;
#pragma unroll
    for (int ii = 0; ii < 4; ii++) {
        int i = tid + ii * 512;
        int r = i >> 3, seg = i & 7;
        size_t src = wbase + r * 64 + seg * 8;
        char* d = base + r * PITCH + seg * 16;
        cp16(d + OFF_BH, &g_Wph[src]);
        cp16(d + OFF_BL, &g_Wpl[src]);
    }
}

__global__ __launch_bounds__(512, 1) void prim_mma_kernel(const float* __restrict__ prim_bias) {
    int tid = threadIdx.x;
    int b0 = blockIdx.x * 2;
    int wid = tid >> 5, lane = tid & 31;
    int g = lane >> 2, c = lane & 3;
    int warpM = wid & 1;
    int warpN = wid >> 1;

    uint32_t sbase = smem_u32(psmem);
    uint32_t aOff = (uint32_t)(warpM * 64 + (lane & 15)) * PITCH + ((lane >> 4) << 4);
    uint32_t bRow = (uint32_t)(warpN * 32 + (lane & 7) + ((lane & 16) >> 1));
    uint32_t bOff = bRow * PITCH + ((lane & 8) ? 16u : 0u);

    float acc[4][4][4];
#pragma unroll
    for (int mt = 0; mt < 4; mt++)
#pragma unroll
        for (int j = 0; j < 4; j++)
#pragma unroll
            for (int q = 0; q < 4; q++) acc[mt][j][q] = 0.f;

    prim_load_step(0, 0, tid, b0);
    cp_commit();

    for (int s = 0; s < 100; s++) {
        int buf = s & 1;
        cp_wait0();
        __syncthreads();
        if (s + 1 < 100) {
            prim_load_step(buf ^ 1, s + 1, tid, b0);
            cp_commit();
        }
        uint32_t tbase = sbase + buf * PBUF;
        uint32_t aBase = tbase + OFF_AH + aOff;
        uint32_t bBase = tbase + OFF_BH + bOff;
#pragma unroll
        for (int kk = 0; kk < 4; kk++) {
            uint32_t bh[2][4], bl[2][4];
#pragma unroll
            for (int np = 0; np < 2; np++) {
                ldm_x4(bh[np], bBase + np * (16 * PITCH) + kk * 32);
                ldm_x4(bl[np], bBase + (OFF_BL - OFF_BH) + np * (16 * PITCH) + kk * 32);
            }
#pragma unroll
            for (int mt = 0; mt < 4; mt++) {
                uint32_t ah[4], al[4];
                ldm_x4(ah, aBase + mt * (16 * PITCH) + kk * 32);
                ldm_x4(al, aBase + (OFF_AL - OFF_AH) + mt * (16 * PITCH) + kk * 32);
#pragma unroll
                for (int np = 0; np < 2; np++)
#pragma unroll
                    for (int nt = 0; nt < 2; nt++) {
                        float* d = acc[mt][np * 2 + nt];
                        mma_bf16(d, ah, bh[np][nt * 2], bh[np][nt * 2 + 1]);
                        mma_bf16(d, ah, bl[np][nt * 2], bl[np][nt * 2 + 1]);
                        mma_bf16(d, al, bh[np][nt * 2], bh[np][nt * 2 + 1]);
                    }
            }
        }
    }

    int b_ = b0 + warpM;
#pragma unroll
    for (int mt = 0; mt < 4; mt++) {
        int pos1 = mt * 16 + g;
        int pos2 = pos1 + 8;
#pragma unroll
        for (int j = 0; j < 4; j++) {
            int caps = warpN * 4 + j;
            float bv0 = __ldg(&prim_bias[caps * 8 + 2 * c]);
            float bv1 = __ldg(&prim_bias[caps * 8 + 2 * c + 1]);
            float v0 = acc[mt][j][0] * (1.f / 32.f) + bv0;
            float v1 = acc[mt][j][1] * (1.f / 32.f) + bv1;
            float v2 = acc[mt][j][2] * (1.f / 32.f) + bv0;
            float v3 = acc[mt][j][3] * (1.f / 32.f) + bv1;
            float na = v0 * v0 + v1 * v1;
            float nb = v2 * v2 + v3 * v3;
            na += __shfl_xor_sync(0xFFFFFFFFu, na, 1);
            na += __shfl_xor_sync(0xFFFFFFFFu, na, 2);
            nb += __shfl_xor_sync(0xFFFFFFFFu, nb, 1);
            nb += __shfl_xor_sync(0xFFFFFFFFu, nb, 2);
            float fa = (na / (1.f + na)) * rsqrtf(na + 1e-8f);
            float fb = (nb / (1.f + nb)) * rsqrtf(nb + 1e-8f);
            size_t base = ((size_t)(b_ * 32 + caps) * 8) * 64;
            g_p[base + (2 * c) * 64 + pos1] = v0 * fa;
            g_p[base + (2 * c + 1) * 64 + pos1] = v1 * fa;
            g_p[base + (2 * c) * 64 + pos2] = v2 * fb;
            g_p[base + (2 * c + 1) * 64 + pos2] = v3 * fb;
        }
    }
}

// ---------------- FUSED capsule tail: cc votes + cc routing + digit caps --------------
// One block per batch (512 blocks, 256 threads, 192 KB smem).
// smem: sv[4 pos][32 i][256 oc] = 32768 fl; sp/scratch = 16384 fl. Total 49152 fl.
#define CC_SMEM (49152 * 4)
__global__ __launch_bounds__(256) void cc_fused_kernel(
    const float* __restrict__ conv_bias,
    const float* __restrict__ digit_w, const float* __restrict__ digit_bias,
    const float* __restrict__ yin, float* __restrict__ out_dcap) {
    extern __shared__ float fs[];
    float* sv = fs;               // conv votes [pos][i][oc]
    float* sp = fs + 32768;       // prim acts during vote phase; scratch after
    int b = blockIdx.x, tid = threadIdx.x;
    for (int idx = tid; idx < 16384; idx += 256) sp[idx] = g_p[b * 16384 + idx];
    __syncthreads();

    // ---- conv-caps votes (f32x2, weights via L2) ----
    int ocg = tid & 7;
    int iin = tid >> 3;
#pragma unroll 1
    for (int occ = 0; occ < 4; occ++) {
        const float* wsrc = &g_cwT[occ * 64 + ocg * 8];
        unsigned long long acc[4][4];
#pragma unroll
        for (int p = 0; p < 4; p++)
#pragma unroll
            for (int j = 0; j < 4; j++) acc[p][j] = 0ULL;
#pragma unroll 1
        for (int cc = 0; cc < 8; cc++) {
            const float* spc = &sp[(iin * 8 + cc) * 64];
#pragma unroll
            for (int kh = 0; kh < 5; kh++) {
#pragma unroll
                for (int kw = 0; kw < 5; kw++) {
                    int k = cc * 25 + kh * 5 + kw;
                    float4 w0 = __ldg((const float4*)(wsrc + k * 256));
                    float4 w1 = __ldg((const float4*)(wsrc + k * 256 + 4));
                    unsigned long long wx, wy, wz, ww;
                    asm("mov.b64 %0, {%1, %2};" : "=l"(wx) : "f"(w0.x), "f"(w0.y));
                    asm("mov.b64 %0, {%1, %2};" : "=l"(wy) : "f"(w0.z), "f"(w0.w));
                    asm("mov.b64 %0, {%1, %2};" : "=l"(wz) : "f"(w1.x), "f"(w1.y));
                    asm("mov.b64 %0, {%1, %2};" : "=l"(ww) : "f"(w1.z), "f"(w1.w));
                    unsigned long long d00 = bcast2(spc[kh * 8 + kw]);
                    unsigned long long d01 = bcast2(spc[kh * 8 + kw + 2]);
                    unsigned long long d10 = bcast2(spc[(kh + 2) * 8 + kw]);
                    unsigned long long d11 = bcast2(spc[(kh + 2) * 8 + kw + 2]);
                    fma2(acc[0][0], d00, wx); fma2(acc[0][1], d00, wy);
                    fma2(acc[0][2], d00, wz); fma2(acc[0][3], d00, ww);
                    fma2(acc[1][0], d01, wx); fma2(acc[1][1], d01, wy);
                    fma2(acc[1][2], d01, wz); fma2(acc[1][3], d01, ww);
                    fma2(acc[2][0], d10, wx); fma2(acc[2][1], d10, wy);
                    fma2(acc[2][2], d10, wz); fma2(acc[2][3], d10, ww);
                    fma2(acc[3][0], d11, wx); fma2(acc[3][1], d11, wy);
                    fma2(acc[3][2], d11, wz); fma2(acc[3][3], d11, ww);
                }
            }
        }
#pragma unroll
        for (int p = 0; p < 4; p++) {
            float2 q0 = unpk(acc[p][0]), q1 = unpk(acc[p][1]);
            float2 q2 = unpk(acc[p][2]), q3 = unpk(acc[p][3]);
            float4* dst = (float4*)&sv[(p * 32 + iin) * 256 + occ * 64 + ocg * 8];
            dst[0] = make_float4(q0.x, q0.y, q1.x, q1.y);
            dst[1] = make_float4(q2.x, q2.y, q3.x, q3.y);
        }
    }
    __syncthreads();

    // ---- conv-caps routing (4 positions in parallel; sp region reused) ----
    float* slog = sp;            // 4096
    float* sroute = sp + 4096;   // 4096
    float* spre = sp + 8192;     // 1024
    float* sact = sp + 9216;     // 1024
    float* sc = sp + 10240;      // 1024
    float* sdw = sp + 11264;     // 5120 (digit weights)
    for (int e = tid; e < 4096; e += 256) slog[e] = 0.f;
    for (int e = tid; e < 5120; e += 256) sdw[e] = digit_w[e];
    __syncthreads();

    int pos = tid >> 6, t = tid & 63;
    float* svp = sv + pos * 8192;
    float* slg = slog + pos * 1024;
    float* srt = sroute + pos * 1024;
    float* spr = spre + pos * 256;
    float* sac = sact + pos * 256;

    for (int it = 0; it < 3; it++) {
        if (t < 32) {
            int ii = t;
            float m = slg[ii * 32];
            for (int o = 1; o < 32; o++) m = fmaxf(m, slg[ii * 32 + o]);
            float z = 0.f;
            for (int o = 0; o < 32; o++) {
                float e = expf(slg[ii * 32 + o] - m);
                srt[ii * 32 + o] = e;
                z += e;
            }
            float inv = 1.f / z;
            for (int o = 0; o < 32; o++) srt[ii * 32 + o] *= inv;
        }
        __syncthreads();
#pragma unroll
        for (int j = 0; j < 4; j++) {
            int idx = t * 4 + j;
            int o = idx >> 3;
            float s = __ldg(&conv_bias[idx]);
            for (int ii = 0; ii < 32; ii++)
                s += srt[ii * 32 + o] * svp[ii * 256 + idx];
            spr[idx] = s;
        }
        __syncthreads();
#pragma unroll
        for (int j = 0; j < 4; j++) {
            int idx = t * 4 + j;
            int o = idx >> 3;
            float n2 = 0.f;
#pragma unroll
            for (int a = 0; a < 8; a++) { float v = spr[o * 8 + a]; n2 += v * v; }
            float f = (n2 / (1.f + n2)) * rsqrtf(n2 + 1e-8f);
            sac[idx] = spr[idx] * f;
        }
        __syncthreads();
        if (it < 2) {
            for (int e = t; e < 1024; e += 64) {
                int o = e & 31;
                float d = 0.f;
#pragma unroll
                for (int a = 0; a < 8; a++) d += svp[e * 8 + a] * sac[o * 8 + a];
                slg[e] += d;
            }
            __syncthreads();
        }
    }

    // build digit input: sc[i*32 + c*4 + pos] = act[pos][i*8+c]
    for (int e = tid; e < 1024; e += 256) {
        int pp = e & 3, ic = e >> 2;
        sc[(ic >> 3) * 32 + (ic & 7) * 4 + pp] = sact[pp * 256 + ic];
    }
    __syncthreads();

    // ---- digit caps votes (sv region reused) ----
    float* dv = sv;              // [i32][o10][a16] = 5120
    float* slogd = sv + 5120;    // 320
    float* srtd = sv + 5440;     // 320
    float* sprd = sv + 5760;     // 160
    float* sacd = sv + 5920;     // 160
    for (int idx = tid; idx < 5120; idx += 256) {
        int ii = idx / 160, oa = idx % 160;
        float s = 0.f;
        const float* ci = &sc[ii * 32];
        const float* wv = &sdw[oa * 32];
#pragma unroll
        for (int z = 0; z < 32; z++) s += ci[z] * wv[z];
        dv[(ii * 10 + (oa >> 4)) * 16 + (oa & 15)] = s;
    }
    for (int e = tid; e < 320; e += 256) slogd[e] = 0.f;
    __syncthreads();

    // ---- digit routing (3 iters) ----
    for (int it = 0; it < 3; it++) {
        if (tid < 32) {
            int ii = tid;
            float m = slogd[ii * 10];
            for (int o = 1; o < 10; o++) m = fmaxf(m, slogd[ii * 10 + o]);
            float z = 0.f;
            for (int o = 0; o < 10; o++) {
                float e = expf(slogd[ii * 10 + o] - m);
                srtd[ii * 10 + o] = e;
                z += e;
            }
            float inv = 1.f / z;
            for (int o = 0; o < 10; o++) srtd[ii * 10 + o] *= inv;
        }
        __syncthreads();
        if (tid < 160) {
            int o = tid >> 4, a = tid & 15;
            float s = __ldg(&digit_bias[tid]);
            for (int ii = 0; ii < 32; ii++)
                s += srtd[ii * 10 + o] * dv[(ii * 10 + o) * 16 + a];
            sprd[tid] = s;
        }
        __syncthreads();
        if (tid < 160) {
            int o = tid >> 4;
            float n2 = 0.f;
#pragma unroll
            for (int a = 0; a < 16; a++) { float v = sprd[o * 16 + a]; n2 += v * v; }
            float f = (n2 / (1.f + n2)) * rsqrtf(n2 + 1e-8f);
            sacd[tid] = sprd[tid] * f;
        }
        __syncthreads();
        if (it < 2) {
            for (int e = tid; e < 320; e += 256) {
                int o = e % 10;
                float d = 0.f;
#pragma unroll
                for (int a = 0; a < 16; a++) d += dv[e * 16 + a] * sacd[o * 16 + a];
                slogd[e] += d;
            }
            __syncthreads();
        }
    }
    if (tid < 160) {
        int o = tid >> 4;
        float v = sacd[tid];
        out_dcap[b * 160 + tid] = v;
        g_masked[b * 160 + tid] = v * yin[b * 10 + o];
    }
}

// ---------------- FC: C = act(A @ W + bias) ----------------
template <int ACT>
__global__ __launch_bounds__(256) void fc_kernel(
    const float* __restrict__ A, const float* __restrict__ W,
    const float* __restrict__ bias, float* __restrict__ C,
    int M, int K, int N) {
    __shared__ float As[16][64];
    __shared__ float Ws[16][64];
    int m0 = blockIdx.y * 64, n0 = blockIdx.x * 64;
    int tid = threadIdx.x;
    int tr = tid >> 4, tc = tid & 15;
    float acc[4][4];
#pragma unroll
    for (int i = 0; i < 4; i++)
#pragma unroll
        for (int j = 0; j < 4; j++) acc[i][j] = 0.f;

    for (int k0 = 0; k0 < K; k0 += 16) {
        for (int l = tid; l < 1024; l += 256) {
            int ml = l >> 4, kl = l & 15;
            As[kl][ml] = A[(m0 + ml) * K + k0 + kl];
        }
        for (int l = tid; l < 1024; l += 256) {
            int kl = l >> 6, nl = l & 63;
            int n = n0 + nl;
            Ws[kl][nl] = (n < N) ? W[(k0 + kl) * N + n] : 0.f;
        }
        __syncthreads();
#pragma unroll
        for (int kk = 0; kk < 16; kk++) {
            float4 a4 = *(const float4*)&As[kk][tr * 4];
            float4 b4 = *(const float4*)&Ws[kk][tc * 4];
            float av[4] = {a4.x, a4.y, a4.z, a4.w};
            float bv[4] = {b4.x, b4.y, b4.z, b4.w};
#pragma unroll
            for (int i = 0; i < 4; i++)
#pragma unroll
                for (int j = 0; j < 4; j++) acc[i][j] += av[i] * bv[j];
        }
        __syncthreads();
    }
#pragma unroll
    for (int i = 0; i < 4; i++) {
        int m = m0 + tr * 4 + i;
#pragma unroll
        for (int j = 0; j < 4; j++) {
            int n = n0 + tc * 4 + j;
            if (n < N) {
                float v = acc[i][j] + bias[n];
                if (ACT == 1) v = v > 0.f ? v : 0.f;
                if (ACT == 2) v = 1.f / (1.f + expf(-v));
                C[m * N + n] = v;
            }
        }
    }
}

// ---------------- launcher ----------------
extern "C" void kernel_launch(void* const* d_in, const int* in_sizes, int n_in,
                              void* d_out, int out_size) {
    const float* x = (const float*)d_in[0];
    const float* y = (const float*)d_in[1];
    const float* conv1_w = (const float*)d_in[2];
    const float* conv1_b = (const float*)d_in[3];
    const float* prim_w = (const float*)d_in[4];
    const float* prim_bias = (const float*)d_in[5];
    const float* conv_w = (const float*)d_in[6];
    const float* conv_bias = (const float*)d_in[7];
    const float* digit_w = (const float*)d_in[8];
    const float* digit_bias = (const float*)d_in[9];
    const float* fc1_w = (const float*)d_in[10];
    const float* fc1_b = (const float*)d_in[11];
    const float* fc2_w = (const float*)d_in[12];
    const float* fc2_b = (const float*)d_in[13];
    const float* fc3_w = (const float*)d_in[14];
    const float* fc3_b = (const float*)d_in[15];
    float* out = (float*)d_out;              // [0:81920) dcap, [81920:483328) recon

    static float *p_masked = nullptr, *p_r1 = nullptr, *p_r2 = nullptr;
    static float *g_cwT_p = nullptr;
    static bool attrs_set = false;
    if (!p_masked) {
        cudaGetSymbolAddress((void**)&p_masked, g_masked);
        cudaGetSymbolAddress((void**)&p_r1, g_r1);
        cudaGetSymbolAddress((void**)&p_r2, g_r2);
        cudaGetSymbolAddress((void**)&g_cwT_p, g_cwT);
    }
    if (!attrs_set) {
        cudaFuncSetAttribute(prim_mma_kernel, cudaFuncAttributeMaxDynamicSharedMemorySize,
                             PRIM_SMEM);
        cudaFuncSetAttribute(cc_fused_kernel, cudaFuncAttributeMaxDynamicSharedMemorySize,
                             CC_SMEM);
        attrs_set = true;
    }

    // weight prep
    prepack_W<<<(25 * 4 * 256 * 64 + 255) / 256, 256>>>(prim_w);
    transpose_oc<<<200, 256>>>(conv_w, g_cwT_p, 256, 200);

    // conv1 + relu (writes bf16 hi/lo, pixel-major)
    conv1_kernel<<<dim3(512, 16), 256>>>(x, conv1_w, conv1_b);

    // primary caps conv via mma.sync + ldmatrix + fused squash
    prim_mma_kernel<<<256, 512, PRIM_SMEM>>>(prim_bias);

    // fused capsule tail: conv-caps votes + routing + digit caps + mask
    cc_fused_kernel<<<512, 256, CC_SMEM>>>(conv_bias, digit_w, digit_bias, y, out);

    // FC reconstruction chain
    fc_kernel<1><<<dim3(8, 8), 256>>>(p_masked, fc1_w, fc1_b, p_r1, 512, 160, 512);
    fc_kernel<1><<<dim3(16, 8), 256>>>(p_r1, fc2_w, fc2_b, p_r2, 512, 512, 1024);
    fc_kernel<2><<<dim3(13, 8), 256>>>(p_r2, fc3_w, fc3_b, out + 81920, 512, 1024, 784);
}

// round 10
// speedup vs baseline: 1.1178x; 1.1178x over previous
#include <cuda_runtime.h>
#include <cuda_bf16.h>
#include <math.h>
#include <stdint.h>

// ---------------- problem constants ----------------
#define BATCH 512
#define NPRIM 32
#define NCLASS 10

// ---------------- scratch (static device memory; no allocs allowed) ----------------
// conv1 output as bf16 hi/lo split, layout [b][pixel(400)][ic(256)]
__device__ __align__(256) unsigned short g_h1h[BATCH * 400 * 256];   // 100 MB
__device__ __align__(256) unsigned short g_h1l[BATCH * 400 * 256];   // 100 MB
// prim weights prepacked: [kpos25][chunk4][oc256][ic64] bf16 hi/lo
__device__ __align__(256) unsigned short g_Wph[25 * 4 * 256 * 64];   // 3.3 MB
__device__ __align__(256) unsigned short g_Wpl[25 * 4 * 256 * 64];   // 3.3 MB
__device__ float g_cwT[8 * 25 * 256];                    // conv_w transposed [c*25+k][oc]
__device__ float g_p[BATCH * NPRIM * 8 * 64];            // primary caps acts [b][i][a][pos]
__device__ float g_votes2[BATCH * 4 * 32 * 256];         // [b][pos][i][oc]
__device__ float g_c[BATCH * 32 * 8 * 4];                // [b][o][a][pos]
__device__ float g_masked[BATCH * 160];
__device__ float g_r1[BATCH * 512];
__device__ float g_r2[BATCH * 1024];

// ---------------- f32x2 helpers ----------------
__device__ __forceinline__ unsigned long long bcast2(float v) {
    unsigned long long r;
    asm("mov.b64 %0, {%1, %1};" : "=l"(r) : "f"(v));
    return r;
}
__device__ __forceinline__ void fma2(unsigned long long& acc, unsigned long long a,
                                     unsigned long long b) {
    asm("fma.rn.f32x2 %0, %1, %2, %0;" : "+l"(acc) : "l"(a), "l"(b));
}
__device__ __forceinline__ float2 unpk(unsigned long long v) {
    float2 r;
    asm("mov.b64 {%0, %1}, %2;" : "=f"(r.x), "=f"(r.y) : "l"(v));
    return r;
}

// ---------------- cp.async helpers ----------------
__device__ __forceinline__ void cp16(void* smem, const void* g) {
    unsigned s;
    asm("{ .reg .u64 t; cvta.to.shared.u64 t, %1; cvt.u32.u64 %0, t; }"
        : "=r"(s) : "l"(smem));
    asm volatile("cp.async.cg.shared.global [%0], [%1], 16;" :: "r"(s), "l"(g));
}
__device__ __forceinline__ void cp_commit() { asm volatile("cp.async.commit_group;"); }
__device__ __forceinline__ void cp_wait0() {
    asm volatile("cp.async.wait_group 0;" ::: "memory");
}

// ---------------- mma.sync bf16 + ldmatrix (sm_80+ legacy tensor path) ----------------
__device__ __forceinline__ void mma_bf16(float* d, const uint32_t* a, uint32_t b0,
                                         uint32_t b1) {
    asm volatile(
        "mma.sync.aligned.m16n8k16.row.col.f32.bf16.bf16.f32 "
        "{%0,%1,%2,%3}, {%4,%5,%6,%7}, {%8,%9}, {%0,%1,%2,%3};"
        : "+f"(d[0]), "+f"(d[1]), "+f"(d[2]), "+f"(d[3])
        : "r"(a[0]), "r"(a[1]), "r"(a[2]), "r"(a[3]), "r"(b0), "r"(b1));
}
__device__ __forceinline__ void ldm_x4(uint32_t* r, uint32_t addr) {
    asm volatile("ldmatrix.sync.aligned.m8n8.x4.shared.b16 {%0,%1,%2,%3}, [%4];"
        : "=r"(r[0]), "=r"(r[1]), "=r"(r[2]), "=r"(r[3]) : "r"(addr));
}
__device__ __forceinline__ uint32_t smem_u32(const void* p) {
    uint32_t a;
    asm("{ .reg .u64 t; cvta.to.shared.u64 t, %1; cvt.u32.u64 %0, t; }" : "=r"(a) : "l"(p));
    return a;
}

// ---------------- weight transpose: w[oc][ick] -> wt[ick][oc] ----------------
__global__ void transpose_oc(const float* __restrict__ w, float* __restrict__ wt,
                             int OC, int ICK) {
    int idx = blockIdx.x * 256 + threadIdx.x;
    if (idx >= OC * ICK) return;
    int ick = idx / OC, oc = idx % OC;
    wt[idx] = w[oc * ICK + ick];
}

// ---------------- prepack prim weights: [kpos][chunk][oc][ic64] bf16 hi/lo ------------
__global__ void prepack_W(const float* __restrict__ w) {
    int idx = blockIdx.x * 256 + threadIdx.x;
    if (idx >= 25 * 4 * 256 * 64) return;
    int ic = idx & 63;
    int oc = (idx >> 6) & 255;
    int chunk = (idx >> 14) & 3;
    int kpos = idx >> 16;
    float v = w[oc * 6400 + (chunk * 64 + ic) * 25 + kpos];
    __nv_bfloat16 hi = __float2bfloat16(v);
    __nv_bfloat16 lo = __float2bfloat16(v - __bfloat162float(hi));
    g_Wph[idx] = __bfloat16_as_ushort(hi);
    g_Wpl[idx] = __bfloat16_as_ushort(lo);
}

// ---------------- conv1 + relu (f32x2), writes bf16 hi/lo [b][pix][ic] ----------------
__global__ __launch_bounds__(256) void conv1_kernel(
    const float* __restrict__ x, const float* __restrict__ w,
    const float* __restrict__ bias) {
    __shared__ float sx[784];
    __shared__ float sw2[81 * 16];
    __shared__ float sb[16];
    int b = blockIdx.x, g = blockIdx.y, tid = threadIdx.x;
    for (int i = tid; i < 784; i += 256) sx[i] = x[b * 784 + i];
    for (int i = tid; i < 81 * 16; i += 256) {
        int k = i >> 4, c = i & 15;
        sw2[i] = w[(g * 16 + c) * 81 + k];
    }
    if (tid < 16) sb[tid] = bias[g * 16 + tid];
    __syncthreads();

    int p0 = tid;
    int p1 = tid + 256;
    bool has1 = (p1 < 400);
    int p1c = has1 ? p1 : 0;
    int y0 = p0 / 20, x0 = p0 % 20;
    int y1 = p1c / 20, x1 = p1c % 20;
    unsigned long long a0[8], a1[8];
#pragma unroll
    for (int j = 0; j < 8; j++) { a0[j] = 0ULL; a1[j] = 0ULL; }
#pragma unroll
    for (int kh = 0; kh < 9; kh++) {
#pragma unroll
        for (int kw = 0; kw < 9; kw++) {
            unsigned long long d0 = bcast2(sx[(y0 + kh) * 28 + x0 + kw]);
            unsigned long long d1 = bcast2(sx[(y1 + kh) * 28 + x1 + kw]);
            int k = kh * 9 + kw;
            const ulonglong2* wp = (const ulonglong2*)&sw2[k * 16];
            ulonglong2 wA = wp[0], wB = wp[1], wC = wp[2], wD = wp[3];
            fma2(a0[0], d0, wA.x); fma2(a0[1], d0, wA.y);
            fma2(a0[2], d0, wB.x); fma2(a0[3], d0, wB.y);
            fma2(a0[4], d0, wC.x); fma2(a0[5], d0, wC.y);
            fma2(a0[6], d0, wD.x); fma2(a0[7], d0, wD.y);
            fma2(a1[0], d1, wA.x); fma2(a1[1], d1, wA.y);
            fma2(a1[2], d1, wB.x); fma2(a1[3], d1, wB.y);
            fma2(a1[4], d1, wC.x); fma2(a1[5], d1, wC.y);
            fma2(a1[6], d1, wD.x); fma2(a1[7], d1, wD.y);
        }
    }
#pragma unroll
    for (int half = 0; half < 2; half++) {
        if (half == 1 && !has1) break;
        int p = half ? p1 : p0;
        unsigned long long* A = half ? a1 : a0;
        uint32_t hw[8], lw[8];
#pragma unroll
        for (int j = 0; j < 8; j++) {
            float2 v = unpk(A[j]);
            float r0 = v.x + sb[2 * j];     r0 = r0 > 0.f ? r0 : 0.f;
            float r1 = v.y + sb[2 * j + 1]; r1 = r1 > 0.f ? r1 : 0.f;
            __nv_bfloat16 h0 = __float2bfloat16(r0);
            __nv_bfloat16 h1 = __float2bfloat16(r1);
            __nv_bfloat16 l0 = __float2bfloat16(r0 - __bfloat162float(h0));
            __nv_bfloat16 l1 = __float2bfloat16(r1 - __bfloat162float(h1));
            hw[j] = (uint32_t)__bfloat16_as_ushort(h0) |
                    ((uint32_t)__bfloat16_as_ushort(h1) << 16);
            lw[j] = (uint32_t)__bfloat16_as_ushort(l0) |
                    ((uint32_t)__bfloat16_as_ushort(l1) << 16);
        }
        size_t base = ((size_t)b * 400 + p) * 256 + g * 16;
        uint4* dh = (uint4*)&g_h1h[base];
        uint4* dl = (uint4*)&g_h1l[base];
        dh[0] = make_uint4(hw[0], hw[1], hw[2], hw[3]);
        dh[1] = make_uint4(hw[4], hw[5], hw[6], hw[7]);
        dl[0] = make_uint4(lw[0], lw[1], lw[2], lw[3]);
        dl[1] = make_uint4(lw[4], lw[5], lw[6], lw[7]);
    }
}

// ---------------- primary caps conv via mma.sync + ldmatrix (R8 best: 1 sync/step) ----
#define PITCH 144
#define OFF_AH 0
#define OFF_AL 18432                   // 128*144
#define OFF_BH 36864
#define OFF_BL 73728                   // OFF_BH + 256*144
#define PBUF 110592
#define PRIM_SMEM (2 * PBUF)           // 221184

extern __shared__ char psmem[];

__device__ __forceinline__ void prim_load_step(int buf, int s, int tid, int b0) {
    int kpos = s >> 2, chunk = s & 3;
    int kh = kpos / 5, kw = kpos - kh * 5;
    char* base = psmem + buf * PBUF;
#pragma unroll
    for (int ii = 0; ii < 2; ii++) {
        int i = tid + ii * 512;
        int r = i >> 3, seg = i & 7;
        int batch = r >> 6, pos = r & 63;
        int y = pos >> 3, xx = pos & 7;
        int pix = (2 * y + kh) * 20 + 2 * xx + kw;
        size_t src = ((size_t)(b0 + batch) * 400 + pix) * 256 + chunk * 64 + seg * 8;
        char* d = base + r * PITCH + seg * 16;
        cp16(d + OFF_AH, &g_h1h[src]);
        cp16(d + OFF_AL, &g_h1l[src]);
    }
    size_t wbase = (size_t)s * 16384;
#pragma unroll
    for (int ii = 0; ii < 4; ii++) {
        int i = tid + ii * 512;
        int r = i >> 3, seg = i & 7;
        size_t src = wbase + r * 64 + seg * 8;
        char* d = base + r * PITCH + seg * 16;
        cp16(d + OFF_BH, &g_Wph[src]);
        cp16(d + OFF_BL, &g_Wpl[src]);
    }
}

__global__ __launch_bounds__(512, 1) void prim_mma_kernel(const float* __restrict__ prim_bias) {
    int tid = threadIdx.x;
    int b0 = blockIdx.x * 2;
    int wid = tid >> 5, lane = tid & 31;
    int g = lane >> 2, c = lane & 3;
    int warpM = wid & 1;
    int warpN = wid >> 1;

    uint32_t sbase = smem_u32(psmem);
    uint32_t aOff = (uint32_t)(warpM * 64 + (lane & 15)) * PITCH + ((lane >> 4) << 4);
    uint32_t bRow = (uint32_t)(warpN * 32 + (lane & 7) + ((lane & 16) >> 1));
    uint32_t bOff = bRow * PITCH + ((lane & 8) ? 16u : 0u);

    float acc[4][4][4];
#pragma unroll
    for (int mt = 0; mt < 4; mt++)
#pragma unroll
        for (int j = 0; j < 4; j++)
#pragma unroll
            for (int q = 0; q < 4; q++) acc[mt][j][q] = 0.f;

    prim_load_step(0, 0, tid, b0);
    cp_commit();

    for (int s = 0; s < 100; s++) {
        int buf = s & 1;
        cp_wait0();
        __syncthreads();
        if (s + 1 < 100) {
            prim_load_step(buf ^ 1, s + 1, tid, b0);
            cp_commit();
        }
        uint32_t tbase = sbase + buf * PBUF;
        uint32_t aBase = tbase + OFF_AH + aOff;
        uint32_t bBase = tbase + OFF_BH + bOff;
#pragma unroll
        for (int kk = 0; kk < 4; kk++) {
            uint32_t bh[2][4], bl[2][4];
#pragma unroll
            for (int np = 0; np < 2; np++) {
                ldm_x4(bh[np], bBase + np * (16 * PITCH) + kk * 32);
                ldm_x4(bl[np], bBase + (OFF_BL - OFF_BH) + np * (16 * PITCH) + kk * 32);
            }
#pragma unroll
            for (int mt = 0; mt < 4; mt++) {
                uint32_t ah[4], al[4];
                ldm_x4(ah, aBase + mt * (16 * PITCH) + kk * 32);
                ldm_x4(al, aBase + (OFF_AL - OFF_AH) + mt * (16 * PITCH) + kk * 32);
#pragma unroll
                for (int np = 0; np < 2; np++)
#pragma unroll
                    for (int nt = 0; nt < 2; nt++) {
                        float* d = acc[mt][np * 2 + nt];
                        mma_bf16(d, ah, bh[np][nt * 2], bh[np][nt * 2 + 1]);
                        mma_bf16(d, ah, bl[np][nt * 2], bl[np][nt * 2 + 1]);
                        mma_bf16(d, al, bh[np][nt * 2], bh[np][nt * 2 + 1]);
                    }
            }
        }
    }

    int b_ = b0 + warpM;
#pragma unroll
    for (int mt = 0; mt < 4; mt++) {
        int pos1 = mt * 16 + g;
        int pos2 = pos1 + 8;
#pragma unroll
        for (int j = 0; j < 4; j++) {
            int caps = warpN * 4 + j;
            float bv0 = __ldg(&prim_bias[caps * 8 + 2 * c]);
            float bv1 = __ldg(&prim_bias[caps * 8 + 2 * c + 1]);
            float v0 = acc[mt][j][0] * (1.f / 32.f) + bv0;
            float v1 = acc[mt][j][1] * (1.f / 32.f) + bv1;
            float v2 = acc[mt][j][2] * (1.f / 32.f) + bv0;
            float v3 = acc[mt][j][3] * (1.f / 32.f) + bv1;
            float na = v0 * v0 + v1 * v1;
            float nb = v2 * v2 + v3 * v3;
            na += __shfl_xor_sync(0xFFFFFFFFu, na, 1);
            na += __shfl_xor_sync(0xFFFFFFFFu, na, 2);
            nb += __shfl_xor_sync(0xFFFFFFFFu, nb, 1);
            nb += __shfl_xor_sync(0xFFFFFFFFu, nb, 2);
            float fa = (na / (1.f + na)) * rsqrtf(na + 1e-8f);
            float fb = (nb / (1.f + nb)) * rsqrtf(nb + 1e-8f);
            size_t base = ((size_t)(b_ * 32 + caps) * 8) * 64;
            g_p[base + (2 * c) * 64 + pos1] = v0 * fa;
            g_p[base + (2 * c + 1) * 64 + pos1] = v1 * fa;
            g_p[base + (2 * c) * 64 + pos2] = v2 * fb;
            g_p[base + (2 * c + 1) * 64 + pos2] = v3 * fb;
        }
    }
}

// ---------------- conv-caps votes (R6 best: f32x2, smem-staged weights) ----------------
__global__ __launch_bounds__(256) void cc_votes_kernel() {
    extern __shared__ float smem[];
    float* sp = smem;
    float* swc = smem + 16384;
    int b = blockIdx.x, tid = threadIdx.x;
    for (int idx = tid; idx < 16384; idx += 256) sp[idx] = g_p[b * 16384 + idx];

    int ocg = tid & 7;
    int i = tid >> 3;
    for (int occ = 0; occ < 4; occ++) {
        __syncthreads();
        for (int idx = tid; idx < 12800; idx += 256)
            swc[idx] = g_cwT[(idx >> 6) * 256 + occ * 64 + (idx & 63)];
        __syncthreads();
        unsigned long long acc[4][4];
#pragma unroll
        for (int p = 0; p < 4; p++)
#pragma unroll
            for (int j = 0; j < 4; j++) acc[p][j] = 0ULL;
#pragma unroll
        for (int cc = 0; cc < 8; cc++) {
            const float* spc = &sp[(i * 8 + cc) * 64];
#pragma unroll
            for (int kh = 0; kh < 5; kh++) {
#pragma unroll
                for (int kw = 0; kw < 5; kw++) {
                    unsigned long long d00 = bcast2(spc[kh * 8 + kw]);
                    unsigned long long d01 = bcast2(spc[kh * 8 + kw + 2]);
                    unsigned long long d10 = bcast2(spc[(kh + 2) * 8 + kw]);
                    unsigned long long d11 = bcast2(spc[(kh + 2) * 8 + kw + 2]);
                    const ulonglong2* wp =
                        (const ulonglong2*)&swc[(cc * 25 + kh * 5 + kw) * 64 + ocg * 8];
                    ulonglong2 wA = wp[0], wB = wp[1];
                    fma2(acc[0][0], d00, wA.x); fma2(acc[0][1], d00, wA.y);
                    fma2(acc[0][2], d00, wB.x); fma2(acc[0][3], d00, wB.y);
                    fma2(acc[1][0], d01, wA.x); fma2(acc[1][1], d01, wA.y);
                    fma2(acc[1][2], d01, wB.x); fma2(acc[1][3], d01, wB.y);
                    fma2(acc[2][0], d10, wA.x); fma2(acc[2][1], d10, wA.y);
                    fma2(acc[2][2], d10, wB.x); fma2(acc[2][3], d10, wB.y);
                    fma2(acc[3][0], d11, wA.x); fma2(acc[3][1], d11, wA.y);
                    fma2(acc[3][2], d11, wB.x); fma2(acc[3][3], d11, wB.y);
                }
            }
        }
#pragma unroll
        for (int p = 0; p < 4; p++) {
            float2 q0 = unpk(acc[p][0]), q1 = unpk(acc[p][1]);
            float2 q2 = unpk(acc[p][2]), q3 = unpk(acc[p][3]);
            float4* dst = (float4*)&g_votes2[((b * 4 + p) * 32 + i) * 256 + occ * 64 + ocg * 8];
            dst[0] = make_float4(q0.x, q0.y, q1.x, q1.y);
            dst[1] = make_float4(q2.x, q2.y, q3.x, q3.y);
        }
    }
}

// ---------------- conv-caps routing (3 iters) ----------------
__global__ __launch_bounds__(256) void cc_routing_kernel(const float* __restrict__ conv_bias) {
    __shared__ float sv[8192];
    __shared__ float slog[1024];
    __shared__ float sroute[1024];
    __shared__ float spre[256];
    __shared__ float sact[256];
    int blk = blockIdx.x;
    int b = blk >> 2, pos = blk & 3;
    int tid = threadIdx.x;
    for (int idx = tid; idx < 8192; idx += 256)
        sv[idx] = g_votes2[(b * 4 + pos) * 8192 + idx];
    for (int e = tid; e < 1024; e += 256) slog[e] = 0.f;
    __syncthreads();

    for (int it = 0; it < 3; it++) {
        if (tid < 32) {
            int i = tid;
            float m = slog[i * 32];
            for (int o = 1; o < 32; o++) m = fmaxf(m, slog[i * 32 + o]);
            float z = 0.f;
            for (int o = 0; o < 32; o++) {
                float e = expf(slog[i * 32 + o] - m);
                sroute[i * 32 + o] = e;
                z += e;
            }
            float inv = 1.f / z;
            for (int o = 0; o < 32; o++) sroute[i * 32 + o] *= inv;
        }
        __syncthreads();
        {
            int o = tid >> 3, a = tid & 7;
            float s = conv_bias[o * 8 + a];
            for (int i = 0; i < 32; i++)
                s += sroute[i * 32 + o] * sv[(i * 32 + o) * 8 + a];
            spre[tid] = s;
        }
        __syncthreads();
        {
            int o = tid >> 3;
            float n2 = 0.f;
#pragma unroll
            for (int a = 0; a < 8; a++) { float v = spre[o * 8 + a]; n2 += v * v; }
            float f = (n2 / (1.f + n2)) * rsqrtf(n2 + 1e-8f);
            sact[tid] = spre[tid] * f;
        }
        __syncthreads();
        if (it < 2) {
            for (int e = tid; e < 1024; e += 256) {
                int o = e & 31;
                float d = 0.f;
#pragma unroll
                for (int a = 0; a < 8; a++) d += sv[e * 8 + a] * sact[o * 8 + a];
                slog[e] += d;
            }
            __syncthreads();
        }
    }
    {
        int o = tid >> 3, a = tid & 7;
        g_c[((b * 32 + o) * 8 + a) * 4 + pos] = sact[tid];
    }
}

// ---------------- digit caps: votes + routing + mask ----------------
__global__ __launch_bounds__(256) void digit_kernel(
    const float* __restrict__ digit_w, const float* __restrict__ digit_bias,
    const float* __restrict__ y, float* __restrict__ out_dcap) {
    __shared__ float smem[11264];
    float* sc = smem;
    float* sdw = smem + 1024;
    float* sv = smem + 6144;
    int b = blockIdx.x, tid = threadIdx.x;
    for (int idx = tid; idx < 1024; idx += 256) sc[idx] = g_c[b * 1024 + idx];
    for (int idx = tid; idx < 5120; idx += 256) sdw[idx] = digit_w[idx];
    __syncthreads();
    for (int idx = tid; idx < 5120; idx += 256) {
        int i = idx / 160, oa = idx % 160;
        float s = 0.f;
        const float* ci = &sc[i * 32];
        const float* wv = &sdw[oa * 32];
#pragma unroll
        for (int z = 0; z < 32; z++) s += ci[z] * wv[z];
        sv[(i * 10 + (oa >> 4)) * 16 + (oa & 15)] = s;
    }
    __syncthreads();
    float* slog = smem;
    float* sroute = smem + 320;
    float* spre = smem + 640;
    float* sact = smem + 800;
    float* sbias = smem + 960;
    for (int e = tid; e < 320; e += 256) slog[e] = 0.f;
    if (tid < 160) sbias[tid] = digit_bias[tid];
    __syncthreads();

    for (int it = 0; it < 3; it++) {
        if (tid < 32) {
            int i = tid;
            float m = slog[i * 10];
            for (int o = 1; o < 10; o++) m = fmaxf(m, slog[i * 10 + o]);
            float z = 0.f;
            for (int o = 0; o < 10; o++) {
                float e = expf(slog[i * 10 + o] - m);
                sroute[i * 10 + o] = e;
                z += e;
            }
            float inv = 1.f / z;
            for (int o = 0; o < 10; o++) sroute[i * 10 + o] *= inv;
        }
        __syncthreads();
        if (tid < 160) {
            int o = tid >> 4, a = tid & 15;
            float s = sbias[tid];
            for (int i = 0; i < 32; i++)
                s += sroute[i * 10 + o] * sv[(i * 10 + o) * 16 + a];
            spre[tid] = s;
        }
        __syncthreads();
        if (tid < 160) {
            int o = tid >> 4;
            float n2 = 0.f;
#pragma unroll
            for (int a = 0; a < 16; a++) { float v = spre[o * 16 + a]; n2 += v * v; }
            float f = (n2 / (1.f + n2)) * rsqrtf(n2 + 1e-8f);
            sact[tid] = spre[tid] * f;
        }
        __syncthreads();
        if (it < 2) {
            for (int e = tid; e < 320; e += 256) {
                int o = e % 10;
                float d = 0.f;
#pragma unroll
                for (int a = 0; a < 16; a++) d += sv[e * 16 + a] * sact[o * 16 + a];
                slog[e] += d;
            }
            __syncthreads();
        }
    }
    if (tid < 160) {
        int o = tid >> 4;
        float v = sact[tid];
        out_dcap[b * 160 + tid] = v;
        g_masked[b * 160 + tid] = v * y[b * 10 + o];
    }
}

// ---------------- FC: C = act(A @ W + bias) ----------------
template <int ACT>
__global__ __launch_bounds__(256) void fc_kernel(
    const float* __restrict__ A, const float* __restrict__ W,
    const float* __restrict__ bias, float* __restrict__ C,
    int M, int K, int N) {
    __shared__ float As[16][64];
    __shared__ float Ws[16][64];
    int m0 = blockIdx.y * 64, n0 = blockIdx.x * 64;
    int tid = threadIdx.x;
    int tr = tid >> 4, tc = tid & 15;
    float acc[4][4];
#pragma unroll
    for (int i = 0; i < 4; i++)
#pragma unroll
        for (int j = 0; j < 4; j++) acc[i][j] = 0.f;

    for (int k0 = 0; k0 < K; k0 += 16) {
        for (int l = tid; l < 1024; l += 256) {
            int ml = l >> 4, kl = l & 15;
            As[kl][ml] = A[(m0 + ml) * K + k0 + kl];
        }
        for (int l = tid; l < 1024; l += 256) {
            int kl = l >> 6, nl = l & 63;
            int n = n0 + nl;
            Ws[kl][nl] = (n < N) ? W[(k0 + kl) * N + n] : 0.f;
        }
        __syncthreads();
#pragma unroll
        for (int kk = 0; kk < 16; kk++) {
            float4 a4 = *(const float4*)&As[kk][tr * 4];
            float4 b4 = *(const float4*)&Ws[kk][tc * 4];
            float av[4] = {a4.x, a4.y, a4.z, a4.w};
            float bv[4] = {b4.x, b4.y, b4.z, b4.w};
#pragma unroll
            for (int i = 0; i < 4; i++)
#pragma unroll
                for (int j = 0; j < 4; j++) acc[i][j] += av[i] * bv[j];
        }
        __syncthreads();
    }
#pragma unroll
    for (int i = 0; i < 4; i++) {
        int m = m0 + tr * 4 + i;
#pragma unroll
        for (int j = 0; j < 4; j++) {
            int n = n0 + tc * 4 + j;
            if (n < N) {
                float v = acc[i][j] + bias[n];
                if (ACT == 1) v = v > 0.f ? v : 0.f;
                if (ACT == 2) v = 1.f / (1.f + expf(-v));
                C[m * N + n] = v;
            }
        }
    }
}

// ---------------- launcher ----------------
extern "C" void kernel_launch(void* const* d_in, const int* in_sizes, int n_in,
                              void* d_out, int out_size) {
    const float* x = (const float*)d_in[0];
    const float* y = (const float*)d_in[1];
    const float* conv1_w = (const float*)d_in[2];
    const float* conv1_b = (const float*)d_in[3];
    const float* prim_w = (const float*)d_in[4];
    const float* prim_bias = (const float*)d_in[5];
    const float* conv_w = (const float*)d_in[6];
    const float* conv_bias = (const float*)d_in[7];
    const float* digit_w = (const float*)d_in[8];
    const float* digit_bias = (const float*)d_in[9];
    const float* fc1_w = (const float*)d_in[10];
    const float* fc1_b = (const float*)d_in[11];
    const float* fc2_w = (const float*)d_in[12];
    const float* fc2_b = (const float*)d_in[13];
    const float* fc3_w = (const float*)d_in[14];
    const float* fc3_b = (const float*)d_in[15];
    float* out = (float*)d_out;              // [0:81920) dcap, [81920:483328) recon

    static float *p_masked = nullptr, *p_r1 = nullptr, *p_r2 = nullptr;
    static float *g_cwT_p = nullptr;
    static bool attrs_set = false;
    if (!p_masked) {
        cudaGetSymbolAddress((void**)&p_masked, g_masked);
        cudaGetSymbolAddress((void**)&p_r1, g_r1);
        cudaGetSymbolAddress((void**)&p_r2, g_r2);
        cudaGetSymbolAddress((void**)&g_cwT_p, g_cwT);
    }
    if (!attrs_set) {
        cudaFuncSetAttribute(prim_mma_kernel, cudaFuncAttributeMaxDynamicSharedMemorySize,
                             PRIM_SMEM);
        cudaFuncSetAttribute(cc_votes_kernel, cudaFuncAttributeMaxDynamicSharedMemorySize,
                             (16384 + 12800) * 4);
        attrs_set = true;
    }

    // weight prep
    prepack_W<<<(25 * 4 * 256 * 64 + 255) / 256, 256>>>(prim_w);
    transpose_oc<<<200, 256>>>(conv_w, g_cwT_p, 256, 200);

    // conv1 + relu (writes bf16 hi/lo, pixel-major)
    conv1_kernel<<<dim3(512, 16), 256>>>(x, conv1_w, conv1_b);

    // primary caps conv via mma.sync + ldmatrix (R8 best) + fused squash
    prim_mma_kernel<<<256, 512, PRIM_SMEM>>>(prim_bias);

    // conv caps votes (R6 best: smem-staged weights)
    cc_votes_kernel<<<512, 256, (16384 + 12800) * 4>>>();

    // conv caps routing
    cc_routing_kernel<<<2048, 256>>>(conv_bias);

    // digit caps
    digit_kernel<<<512, 256>>>(digit_w, digit_bias, y, out);

    // FC reconstruction chain
    fc_kernel<1><<<dim3(8, 8), 256>>>(p_masked, fc1_w, fc1_b, p_r1, 512, 160, 512);
    fc_kernel<1><<<dim3(16, 8), 256>>>(p_r1, fc2_w, fc2_b, p_r2, 512, 512, 1024);
    fc_kernel<2><<<dim3(13, 8), 256>>>(p_r2, fc3_w, fc3_b, out + 81920, 512, 1024, 784);
}

// round 11
// speedup vs baseline: 1.1582x; 1.0361x over previous
#include <cuda_runtime.h>
#include <cuda_bf16.h>
#include <math.h>
#include <stdint.h>

// ---------------- problem constants ----------------
#define BATCH 512
#define NPRIM 32
#define NCLASS 10

// ---------------- scratch (static device memory; no allocs allowed) ----------------
// conv1 output as bf16 hi/lo split, layout [b][pixel(400)][ic(256)]
__device__ __align__(256) unsigned short g_h1h[BATCH * 400 * 256];   // 100 MB
__device__ __align__(256) unsigned short g_h1l[BATCH * 400 * 256];   // 100 MB
// prim weights prepacked: [kpos25][chunk4][oc256][ic64] bf16 hi/lo
__device__ __align__(256) unsigned short g_Wph[25 * 4 * 256 * 64];   // 3.3 MB
__device__ __align__(256) unsigned short g_Wpl[25 * 4 * 256 * 64];   // 3.3 MB
// conv1 weights prepacked: [oc256][k96] bf16 hi/lo (taps 81..95 zero)
__device__ __align__(256) unsigned short g_c1Wh[256 * 96];
__device__ __align__(256) unsigned short g_c1Wl[256 * 96];
__device__ float g_cwT[8 * 25 * 256];                    // conv_w transposed [c*25+k][oc]
__device__ float g_p[BATCH * NPRIM * 8 * 64];            // primary caps acts [b][i][a][pos]
__device__ float g_votes2[BATCH * 4 * 32 * 256];         // [b][pos][i][oc]
__device__ float g_c[BATCH * 32 * 8 * 4];                // [b][o][a][pos]
__device__ float g_masked[BATCH * 160];
__device__ float g_r1[BATCH * 512];
__device__ float g_r2[BATCH * 1024];

// ---------------- f32x2 helpers ----------------
__device__ __forceinline__ unsigned long long bcast2(float v) {
    unsigned long long r;
    asm("mov.b64 %0, {%1, %1};" : "=l"(r) : "f"(v));
    return r;
}
__device__ __forceinline__ void fma2(unsigned long long& acc, unsigned long long a,
                                     unsigned long long b) {
    asm("fma.rn.f32x2 %0, %1, %2, %0;" : "+l"(acc) : "l"(a), "l"(b));
}
__device__ __forceinline__ float2 unpk(unsigned long long v) {
    float2 r;
    asm("mov.b64 {%0, %1}, %2;" : "=f"(r.x), "=f"(r.y) : "l"(v));
    return r;
}

// ---------------- cp.async helpers ----------------
__device__ __forceinline__ void cp16(void* smem, const void* g) {
    unsigned s;
    asm("{ .reg .u64 t; cvta.to.shared.u64 t, %1; cvt.u32.u64 %0, t; }"
        : "=r"(s) : "l"(smem));
    asm volatile("cp.async.cg.shared.global [%0], [%1], 16;" :: "r"(s), "l"(g));
}
__device__ __forceinline__ void cp_commit() { asm volatile("cp.async.commit_group;"); }
__device__ __forceinline__ void cp_wait0() {
    asm volatile("cp.async.wait_group 0;" ::: "memory");
}

// ---------------- mma.sync bf16 + ldmatrix (sm_80+ legacy tensor path) ----------------
__device__ __forceinline__ void mma_bf16(float* d, const uint32_t* a, uint32_t b0,
                                         uint32_t b1) {
    asm volatile(
        "mma.sync.aligned.m16n8k16.row.col.f32.bf16.bf16.f32 "
        "{%0,%1,%2,%3}, {%4,%5,%6,%7}, {%8,%9}, {%0,%1,%2,%3};"
        : "+f"(d[0]), "+f"(d[1]), "+f"(d[2]), "+f"(d[3])
        : "r"(a[0]), "r"(a[1]), "r"(a[2]), "r"(a[3]), "r"(b0), "r"(b1));
}
__device__ __forceinline__ void ldm_x4(uint32_t* r, uint32_t addr) {
    asm volatile("ldmatrix.sync.aligned.m8n8.x4.shared.b16 {%0,%1,%2,%3}, [%4];"
        : "=r"(r[0]), "=r"(r[1]), "=r"(r[2]), "=r"(r[3]) : "r"(addr));
}
__device__ __forceinline__ uint32_t smem_u32(const void* p) {
    uint32_t a;
    asm("{ .reg .u64 t; cvta.to.shared.u64 t, %1; cvt.u32.u64 %0, t; }" : "=r"(a) : "l"(p));
    return a;
}
__device__ __forceinline__ uint32_t pack_bf16x2(float v0, float v1) {
    __nv_bfloat16 h0 = __float2bfloat16(v0);
    __nv_bfloat16 h1 = __float2bfloat16(v1);
    return (uint32_t)__bfloat16_as_ushort(h0) | ((uint32_t)__bfloat16_as_ushort(h1) << 16);
}

// ---------------- weight transpose: w[oc][ick] -> wt[ick][oc] ----------------
__global__ void transpose_oc(const float* __restrict__ w, float* __restrict__ wt,
                             int OC, int ICK) {
    int idx = blockIdx.x * 256 + threadIdx.x;
    if (idx >= OC * ICK) return;
    int ick = idx / OC, oc = idx % OC;
    wt[idx] = w[oc * ICK + ick];
}

// ---------------- prepack prim weights: [kpos][chunk][oc][ic64] bf16 hi/lo ------------
__global__ void prepack_W(const float* __restrict__ w) {
    int idx = blockIdx.x * 256 + threadIdx.x;
    if (idx >= 25 * 4 * 256 * 64) return;
    int ic = idx & 63;
    int oc = (idx >> 6) & 255;
    int chunk = (idx >> 14) & 3;
    int kpos = idx >> 16;
    float v = w[oc * 6400 + (chunk * 64 + ic) * 25 + kpos];
    __nv_bfloat16 hi = __float2bfloat16(v);
    __nv_bfloat16 lo = __float2bfloat16(v - __bfloat162float(hi));
    g_Wph[idx] = __bfloat16_as_ushort(hi);
    g_Wpl[idx] = __bfloat16_as_ushort(lo);
}

// ---------------- prepack conv1 weights: [oc256][k96] bf16 hi/lo ----------------------
__global__ void prepack_c1(const float* __restrict__ w) {
    int idx = blockIdx.x * 256 + threadIdx.x;
    if (idx >= 256 * 96) return;
    int k = idx % 96, oc = idx / 96;
    float v = (k < 81) ? w[oc * 81 + k] : 0.f;
    __nv_bfloat16 hi = __float2bfloat16(v);
    __nv_bfloat16 lo = __float2bfloat16(v - __bfloat162float(hi));
    g_c1Wh[idx] = __bfloat16_as_ushort(hi);
    g_c1Wl[idx] = __bfloat16_as_ushort(lo);
}

// ---------------- conv1 via mma.sync: M=512*400 rows, N=256 ch, K=96 (81 taps) --------
// grid 1600 (128 rows/block), 512 threads (16 warps: warpM 0/1 x warpN 0..7 of 32 ch).
// smem: img 2x784 fl | A hi/lo 128x208B | B hi/lo 256x208B. Pitch 208 = LDSM conflict-free.
#define C1P 208
#define C1_IMG 0
#define C1_AH 6400
#define C1_AL (C1_AH + 128 * C1P)      // 33024
#define C1_BH (C1_AL + 128 * C1P)      // 59648
#define C1_BL (C1_BH + 256 * C1P)      // 112896
#define C1_SMEM (C1_BL + 256 * C1P)    // 166144

__global__ __launch_bounds__(512, 1) void conv1_mma_kernel(
    const float* __restrict__ x, const float* __restrict__ bias) {
    extern __shared__ char c1s[];
    int tid = threadIdx.x;
    int blk = blockIdx.x;
    int r0 = blk * 128;                 // first global row
    int b0 = r0 / 400;

    // B: cp.async both planes (256 rows x 192B payload each)
    for (int i = 0; i < 6; i++) {
        int q = tid + i * 512;          // 0..3071
        int row = q / 12, seg = q % 12;
        cp16(c1s + C1_BH + row * C1P + seg * 16, &g_c1Wh[row * 96 + seg * 8]);
        cp16(c1s + C1_BL + row * C1P + seg * 16, &g_c1Wl[row * 96 + seg * 8]);
    }
    cp_commit();

    // images: up to 2 batches covered by 128 rows
    float* img = (float*)(c1s + C1_IMG);
    int b1 = (r0 + 127) / 400;
    for (int i = tid; i < 784; i += 512) {
        img[i] = x[(size_t)b0 * 784 + i];
        img[784 + i] = (b1 != b0) ? x[(size_t)b1 * 784 + i] : 0.f;
    }
    __syncthreads();

    // build im2col A (hi/lo): 128 rows x 48 u32 words
    uint32_t* ah = (uint32_t*)(c1s + C1_AH);
    uint32_t* al = (uint32_t*)(c1s + C1_AL);
#pragma unroll
    for (int i = 0; i < 12; i++) {
        int w = tid + i * 512;          // 0..6143
        int r = w / 48, cw = w % 48;
        int R = r0 + r;
        int b = R / 400, pos = R - b * 400;
        int y = pos / 20, xx = pos - y * 20;
        const float* ip = img + (b - b0) * 784;
        float v[2];
#pragma unroll
        for (int h = 0; h < 2; h++) {
            int c = cw * 2 + h;
            float val = 0.f;
            if (c < 81) {
                int kh = c / 9, kw = c - kh * 9;
                val = ip[(y + kh) * 28 + xx + kw];
            }
            v[h] = val;
        }
        __nv_bfloat16 h0 = __float2bfloat16(v[0]);
        __nv_bfloat16 h1 = __float2bfloat16(v[1]);
        float l0 = v[0] - __bfloat162float(h0);
        float l1 = v[1] - __bfloat162float(h1);
        int off = (r * C1P >> 2) + cw;
        ah[off] = (uint32_t)__bfloat16_as_ushort(h0) |
                  ((uint32_t)__bfloat16_as_ushort(h1) << 16);
        al[off] = pack_bf16x2(l0, l1);
    }
    cp_wait0();
    __syncthreads();

    // MMA: 6 k-steps x (Ah*Bh + Ah*Bl + Al*Bh)
    int wid = tid >> 5, lane = tid & 31;
    int g = lane >> 2, c = lane & 3;
    int warpM = wid & 1;
    int warpN = wid >> 1;
    uint32_t sbase = smem_u32(c1s);
    uint32_t aBase = sbase + C1_AH +
                     (uint32_t)(warpM * 64 + (lane & 15)) * C1P + ((lane >> 4) << 4);
    uint32_t bBase = sbase + C1_BH +
                     (uint32_t)(warpN * 32 + (lane & 7) + ((lane & 16) >> 1)) * C1P +
                     ((lane & 8) ? 16u : 0u);

    float acc[4][4][4];
#pragma unroll
    for (int mt = 0; mt < 4; mt++)
#pragma unroll
        for (int j = 0; j < 4; j++)
#pragma unroll
            for (int q = 0; q < 4; q++) acc[mt][j][q] = 0.f;

#pragma unroll
    for (int kk = 0; kk < 6; kk++) {
        uint32_t bh[2][4], bl[2][4];
#pragma unroll
        for (int np = 0; np < 2; np++) {
            ldm_x4(bh[np], bBase + np * (16 * C1P) + kk * 32);
            ldm_x4(bl[np], bBase + (C1_BL - C1_BH) + np * (16 * C1P) + kk * 32);
        }
#pragma unroll
        for (int mt = 0; mt < 4; mt++) {
            uint32_t ahf[4], alf[4];
            ldm_x4(ahf, aBase + mt * (16 * C1P) + kk * 32);
            ldm_x4(alf, aBase + (C1_AL - C1_AH) + mt * (16 * C1P) + kk * 32);
#pragma unroll
            for (int np = 0; np < 2; np++)
#pragma unroll
                for (int nt = 0; nt < 2; nt++) {
                    float* d = acc[mt][np * 2 + nt];
                    mma_bf16(d, ahf, bh[np][nt * 2], bh[np][nt * 2 + 1]);
                    mma_bf16(d, ahf, bl[np][nt * 2], bl[np][nt * 2 + 1]);
                    mma_bf16(d, alf, bh[np][nt * 2], bh[np][nt * 2 + 1]);
                }
        }
    }

    // epilogue: +bias, relu, bf16 hi/lo split, store [b][pix][ic]
#pragma unroll
    for (int mt = 0; mt < 4; mt++) {
        int R1 = r0 + warpM * 64 + mt * 16 + g;
        int R2 = R1 + 8;
#pragma unroll
        for (int j = 0; j < 4; j++) {
            int ch = warpN * 32 + j * 8 + 2 * c;
            float bv0 = __ldg(&bias[ch]);
            float bv1 = __ldg(&bias[ch + 1]);
            float v0 = acc[mt][j][0] + bv0; v0 = v0 > 0.f ? v0 : 0.f;
            float v1 = acc[mt][j][1] + bv1; v1 = v1 > 0.f ? v1 : 0.f;
            float v2 = acc[mt][j][2] + bv0; v2 = v2 > 0.f ? v2 : 0.f;
            float v3 = acc[mt][j][3] + bv1; v3 = v3 > 0.f ? v3 : 0.f;
            __nv_bfloat16 h0 = __float2bfloat16(v0);
            __nv_bfloat16 h1 = __float2bfloat16(v1);
            __nv_bfloat16 h2 = __float2bfloat16(v2);
            __nv_bfloat16 h3 = __float2bfloat16(v3);
            uint32_t hw1 = (uint32_t)__bfloat16_as_ushort(h0) |
                           ((uint32_t)__bfloat16_as_ushort(h1) << 16);
            uint32_t hw2 = (uint32_t)__bfloat16_as_ushort(h2) |
                           ((uint32_t)__bfloat16_as_ushort(h3) << 16);
            uint32_t lw1 = pack_bf16x2(v0 - __bfloat162float(h0), v1 - __bfloat162float(h1));
            uint32_t lw2 = pack_bf16x2(v2 - __bfloat162float(h2), v3 - __bfloat162float(h3));
            size_t o1 = ((size_t)R1 * 256 + ch) >> 1;
            size_t o2 = ((size_t)R2 * 256 + ch) >> 1;
            ((uint32_t*)g_h1h)[o1] = hw1;
            ((uint32_t*)g_h1l)[o1] = lw1;
            ((uint32_t*)g_h1h)[o2] = hw2;
            ((uint32_t*)g_h1l)[o2] = lw2;
        }
    }
}

// ---------------- primary caps conv via mma.sync + ldmatrix (R8 best: 1 sync/step) ----
#define PITCH 144
#define OFF_AH 0
#define OFF_AL 18432                   // 128*144
#define OFF_BH 36864
#define OFF_BL 73728                   // OFF_BH + 256*144
#define PBUF 110592
#define PRIM_SMEM (2 * PBUF)           // 221184

extern __shared__ char psmem[];

__device__ __forceinline__ void prim_load_step(int buf, int s, int tid, int b0) {
    int kpos = s >> 2, chunk = s & 3;
    int kh = kpos / 5, kw = kpos - kh * 5;
    char* base = psmem + buf * PBUF;
#pragma unroll
    for (int ii = 0; ii < 2; ii++) {
        int i = tid + ii * 512;
        int r = i >> 3, seg = i & 7;
        int batch = r >> 6, pos = r & 63;
        int y = pos >> 3, xx = pos & 7;
        int pix = (2 * y + kh) * 20 + 2 * xx + kw;
        size_t src = ((size_t)(b0 + batch) * 400 + pix) * 256 + chunk * 64 + seg * 8;
        char* d = base + r * PITCH + seg * 16;
        cp16(d + OFF_AH, &g_h1h[src]);
        cp16(d + OFF_AL, &g_h1l[src]);
    }
    size_t wbase = (size_t)s * 16384;
#pragma unroll
    for (int ii = 0; ii < 4; ii++) {
        int i = tid + ii * 512;
        int r = i >> 3, seg = i & 7;
        size_t src = wbase + r * 64 + seg * 8;
        char* d = base + r * PITCH + seg * 16;
        cp16(d + OFF_BH, &g_Wph[src]);
        cp16(d + OFF_BL, &g_Wpl[src]);
    }
}

__global__ __launch_bounds__(512, 1) void prim_mma_kernel(const float* __restrict__ prim_bias) {
    int tid = threadIdx.x;
    int b0 = blockIdx.x * 2;
    int wid = tid >> 5, lane = tid & 31;
    int g = lane >> 2, c = lane & 3;
    int warpM = wid & 1;
    int warpN = wid >> 1;

    uint32_t sbase = smem_u32(psmem);
    uint32_t aOff = (uint32_t)(warpM * 64 + (lane & 15)) * PITCH + ((lane >> 4) << 4);
    uint32_t bRow = (uint32_t)(warpN * 32 + (lane & 7) + ((lane & 16) >> 1));
    uint32_t bOff = bRow * PITCH + ((lane & 8) ? 16u : 0u);

    float acc[4][4][4];
#pragma unroll
    for (int mt = 0; mt < 4; mt++)
#pragma unroll
        for (int j = 0; j < 4; j++)
#pragma unroll
            for (int q = 0; q < 4; q++) acc[mt][j][q] = 0.f;

    prim_load_step(0, 0, tid, b0);
    cp_commit();

    for (int s = 0; s < 100; s++) {
        int buf = s & 1;
        cp_wait0();
        __syncthreads();
        if (s + 1 < 100) {
            prim_load_step(buf ^ 1, s + 1, tid, b0);
            cp_commit();
        }
        uint32_t tbase = sbase + buf * PBUF;
        uint32_t aBase = tbase + OFF_AH + aOff;
        uint32_t bBase = tbase + OFF_BH + bOff;
#pragma unroll
        for (int kk = 0; kk < 4; kk++) {
            uint32_t bh[2][4], bl[2][4];
#pragma unroll
            for (int np = 0; np < 2; np++) {
                ldm_x4(bh[np], bBase + np * (16 * PITCH) + kk * 32);
                ldm_x4(bl[np], bBase + (OFF_BL - OFF_BH) + np * (16 * PITCH) + kk * 32);
            }
#pragma unroll
            for (int mt = 0; mt < 4; mt++) {
                uint32_t ah[4], al[4];
                ldm_x4(ah, aBase + mt * (16 * PITCH) + kk * 32);
                ldm_x4(al, aBase + (OFF_AL - OFF_AH) + mt * (16 * PITCH) + kk * 32);
#pragma unroll
                for (int np = 0; np < 2; np++)
#pragma unroll
                    for (int nt = 0; nt < 2; nt++) {
                        float* d = acc[mt][np * 2 + nt];
                        mma_bf16(d, ah, bh[np][nt * 2], bh[np][nt * 2 + 1]);
                        mma_bf16(d, ah, bl[np][nt * 2], bl[np][nt * 2 + 1]);
                        mma_bf16(d, al, bh[np][nt * 2], bh[np][nt * 2 + 1]);
                    }
            }
        }
    }

    int b_ = b0 + warpM;
#pragma unroll
    for (int mt = 0; mt < 4; mt++) {
        int pos1 = mt * 16 + g;
        int pos2 = pos1 + 8;
#pragma unroll
        for (int j = 0; j < 4; j++) {
            int caps = warpN * 4 + j;
            float bv0 = __ldg(&prim_bias[caps * 8 + 2 * c]);
            float bv1 = __ldg(&prim_bias[caps * 8 + 2 * c + 1]);
            float v0 = acc[mt][j][0] * (1.f / 32.f) + bv0;
            float v1 = acc[mt][j][1] * (1.f / 32.f) + bv1;
            float v2 = acc[mt][j][2] * (1.f / 32.f) + bv0;
            float v3 = acc[mt][j][3] * (1.f / 32.f) + bv1;
            float na = v0 * v0 + v1 * v1;
            float nb = v2 * v2 + v3 * v3;
            na += __shfl_xor_sync(0xFFFFFFFFu, na, 1);
            na += __shfl_xor_sync(0xFFFFFFFFu, na, 2);
            nb += __shfl_xor_sync(0xFFFFFFFFu, nb, 1);
            nb += __shfl_xor_sync(0xFFFFFFFFu, nb, 2);
            float fa = (na / (1.f + na)) * rsqrtf(na + 1e-8f);
            float fb = (nb / (1.f + nb)) * rsqrtf(nb + 1e-8f);
            size_t base = ((size_t)(b_ * 32 + caps) * 8) * 64;
            g_p[base + (2 * c) * 64 + pos1] = v0 * fa;
            g_p[base + (2 * c + 1) * 64 + pos1] = v1 * fa;
            g_p[base + (2 * c) * 64 + pos2] = v2 * fb;
            g_p[base + (2 * c + 1) * 64 + pos2] = v3 * fb;
        }
    }
}

// ---------------- conv-caps votes (R6 best: f32x2, smem-staged weights) ----------------
__global__ __launch_bounds__(256) void cc_votes_kernel() {
    extern __shared__ float smem[];
    float* sp = smem;
    float* swc = smem + 16384;
    int b = blockIdx.x, tid = threadIdx.x;
    for (int idx = tid; idx < 16384; idx += 256) sp[idx] = g_p[b * 16384 + idx];

    int ocg = tid & 7;
    int i = tid >> 3;
    for (int occ = 0; occ < 4; occ++) {
        __syncthreads();
        for (int idx = tid; idx < 12800; idx += 256)
            swc[idx] = g_cwT[(idx >> 6) * 256 + occ * 64 + (idx & 63)];
        __syncthreads();
        unsigned long long acc[4][4];
#pragma unroll
        for (int p = 0; p < 4; p++)
#pragma unroll
            for (int j = 0; j < 4; j++) acc[p][j] = 0ULL;
#pragma unroll
        for (int cc = 0; cc < 8; cc++) {
            const float* spc = &sp[(i * 8 + cc) * 64];
#pragma unroll
            for (int kh = 0; kh < 5; kh++) {
#pragma unroll
                for (int kw = 0; kw < 5; kw++) {
                    unsigned long long d00 = bcast2(spc[kh * 8 + kw]);
                    unsigned long long d01 = bcast2(spc[kh * 8 + kw + 2]);
                    unsigned long long d10 = bcast2(spc[(kh + 2) * 8 + kw]);
                    unsigned long long d11 = bcast2(spc[(kh + 2) * 8 + kw + 2]);
                    const ulonglong2* wp =
                        (const ulonglong2*)&swc[(cc * 25 + kh * 5 + kw) * 64 + ocg * 8];
                    ulonglong2 wA = wp[0], wB = wp[1];
                    fma2(acc[0][0], d00, wA.x); fma2(acc[0][1], d00, wA.y);
                    fma2(acc[0][2], d00, wB.x); fma2(acc[0][3], d00, wB.y);
                    fma2(acc[1][0], d01, wA.x); fma2(acc[1][1], d01, wA.y);
                    fma2(acc[1][2], d01, wB.x); fma2(acc[1][3], d01, wB.y);
                    fma2(acc[2][0], d10, wA.x); fma2(acc[2][1], d10, wA.y);
                    fma2(acc[2][2], d10, wB.x); fma2(acc[2][3], d10, wB.y);
                    fma2(acc[3][0], d11, wA.x); fma2(acc[3][1], d11, wA.y);
                    fma2(acc[3][2], d11, wB.x); fma2(acc[3][3], d11, wB.y);
                }
            }
        }
#pragma unroll
        for (int p = 0; p < 4; p++) {
            float2 q0 = unpk(acc[p][0]), q1 = unpk(acc[p][1]);
            float2 q2 = unpk(acc[p][2]), q3 = unpk(acc[p][3]);
            float4* dst = (float4*)&g_votes2[((b * 4 + p) * 32 + i) * 256 + occ * 64 + ocg * 8];
            dst[0] = make_float4(q0.x, q0.y, q1.x, q1.y);
            dst[1] = make_float4(q2.x, q2.y, q3.x, q3.y);
        }
    }
}

// ---------------- conv-caps routing (3 iters) ----------------
__global__ __launch_bounds__(256) void cc_routing_kernel(const float* __restrict__ conv_bias) {
    __shared__ float sv[8192];
    __shared__ float slog[1024];
    __shared__ float sroute[1024];
    __shared__ float spre[256];
    __shared__ float sact[256];
    int blk = blockIdx.x;
    int b = blk >> 2, pos = blk & 3;
    int tid = threadIdx.x;
    for (int idx = tid; idx < 8192; idx += 256)
        sv[idx] = g_votes2[(b * 4 + pos) * 8192 + idx];
    for (int e = tid; e < 1024; e += 256) slog[e] = 0.f;
    __syncthreads();

    for (int it = 0; it < 3; it++) {
        if (tid < 32) {
            int i = tid;
            float m = slog[i * 32];
            for (int o = 1; o < 32; o++) m = fmaxf(m, slog[i * 32 + o]);
            float z = 0.f;
            for (int o = 0; o < 32; o++) {
                float e = expf(slog[i * 32 + o] - m);
                sroute[i * 32 + o] = e;
                z += e;
            }
            float inv = 1.f / z;
            for (int o = 0; o < 32; o++) sroute[i * 32 + o] *= inv;
        }
        __syncthreads();
        {
            int o = tid >> 3, a = tid & 7;
            float s = conv_bias[o * 8 + a];
            for (int i = 0; i < 32; i++)
                s += sroute[i * 32 + o] * sv[(i * 32 + o) * 8 + a];
            spre[tid] = s;
        }
        __syncthreads();
        {
            int o = tid >> 3;
            float n2 = 0.f;
#pragma unroll
            for (int a = 0; a < 8; a++) { float v = spre[o * 8 + a]; n2 += v * v; }
            float f = (n2 / (1.f + n2)) * rsqrtf(n2 + 1e-8f);
            sact[tid] = spre[tid] * f;
        }
        __syncthreads();
        if (it < 2) {
            for (int e = tid; e < 1024; e += 256) {
                int o = e & 31;
                float d = 0.f;
#pragma unroll
                for (int a = 0; a < 8; a++) d += sv[e * 8 + a] * sact[o * 8 + a];
                slog[e] += d;
            }
            __syncthreads();
        }
    }
    {
        int o = tid >> 3, a = tid & 7;
        g_c[((b * 32 + o) * 8 + a) * 4 + pos] = sact[tid];
    }
}

// ---------------- digit caps: votes + routing + mask ----------------
__global__ __launch_bounds__(256) void digit_kernel(
    const float* __restrict__ digit_w, const float* __restrict__ digit_bias,
    const float* __restrict__ y, float* __restrict__ out_dcap) {
    __shared__ float smem[11264];
    float* sc = smem;
    float* sdw = smem + 1024;
    float* sv = smem + 6144;
    int b = blockIdx.x, tid = threadIdx.x;
    for (int idx = tid; idx < 1024; idx += 256) sc[idx] = g_c[b * 1024 + idx];
    for (int idx = tid; idx < 5120; idx += 256) sdw[idx] = digit_w[idx];
    __syncthreads();
    for (int idx = tid; idx < 5120; idx += 256) {
        int i = idx / 160, oa = idx % 160;
        float s = 0.f;
        const float* ci = &sc[i * 32];
        const float* wv = &sdw[oa * 32];
#pragma unroll
        for (int z = 0; z < 32; z++) s += ci[z] * wv[z];
        sv[(i * 10 + (oa >> 4)) * 16 + (oa & 15)] = s;
    }
    __syncthreads();
    float* slog = smem;
    float* sroute = smem + 320;
    float* spre = smem + 640;
    float* sact = smem + 800;
    float* sbias = smem + 960;
    for (int e = tid; e < 320; e += 256) slog[e] = 0.f;
    if (tid < 160) sbias[tid] = digit_bias[tid];
    __syncthreads();

    for (int it = 0; it < 3; it++) {
        if (tid < 32) {
            int i = tid;
            float m = slog[i * 10];
            for (int o = 1; o < 10; o++) m = fmaxf(m, slog[i * 10 + o]);
            float z = 0.f;
            for (int o = 0; o < 10; o++) {
                float e = expf(slog[i * 10 + o] - m);
                sroute[i * 10 + o] = e;
                z += e;
            }
            float inv = 1.f / z;
            for (int o = 0; o < 10; o++) sroute[i * 10 + o] *= inv;
        }
        __syncthreads();
        if (tid < 160) {
            int o = tid >> 4, a = tid & 15;
            float s = sbias[tid];
            for (int i = 0; i < 32; i++)
                s += sroute[i * 10 + o] * sv[(i * 10 + o) * 16 + a];
            spre[tid] = s;
        }
        __syncthreads();
        if (tid < 160) {
            int o = tid >> 4;
            float n2 = 0.f;
#pragma unroll
            for (int a = 0; a < 16; a++) { float v = spre[o * 16 + a]; n2 += v * v; }
            float f = (n2 / (1.f + n2)) * rsqrtf(n2 + 1e-8f);
            sact[tid] = spre[tid] * f;
        }
        __syncthreads();
        if (it < 2) {
            for (int e = tid; e < 320; e += 256) {
                int o = e % 10;
                float d = 0.f;
#pragma unroll
                for (int a = 0; a < 16; a++) d += sv[e * 16 + a] * sact[o * 16 + a];
                slog[e] += d;
            }
            __syncthreads();
        }
    }
    if (tid < 160) {
        int o = tid >> 4;
        float v = sact[tid];
        out_dcap[b * 160 + tid] = v;
        g_masked[b * 160 + tid] = v * y[b * 10 + o];
    }
}

// ---------------- FC: C = act(A @ W + bias) ----------------
template <int ACT>
__global__ __launch_bounds__(256) void fc_kernel(
    const float* __restrict__ A, const float* __restrict__ W,
    const float* __restrict__ bias, float* __restrict__ C,
    int M, int K, int N) {
    __shared__ float As[16][64];
    __shared__ float Ws[16][64];
    int m0 = blockIdx.y * 64, n0 = blockIdx.x * 64;
    int tid = threadIdx.x;
    int tr = tid >> 4, tc = tid & 15;
    float acc[4][4];
#pragma unroll
    for (int i = 0; i < 4; i++)
#pragma unroll
        for (int j = 0; j < 4; j++) acc[i][j] = 0.f;

    for (int k0 = 0; k0 < K; k0 += 16) {
        for (int l = tid; l < 1024; l += 256) {
            int ml = l >> 4, kl = l & 15;
            As[kl][ml] = A[(m0 + ml) * K + k0 + kl];
        }
        for (int l = tid; l < 1024; l += 256) {
            int kl = l >> 6, nl = l & 63;
            int n = n0 + nl;
            Ws[kl][nl] = (n < N) ? W[(k0 + kl) * N + n] : 0.f;
        }
        __syncthreads();
#pragma unroll
        for (int kk = 0; kk < 16; kk++) {
            float4 a4 = *(const float4*)&As[kk][tr * 4];
            float4 b4 = *(const float4*)&Ws[kk][tc * 4];
            float av[4] = {a4.x, a4.y, a4.z, a4.w};
            float bv[4] = {b4.x, b4.y, b4.z, b4.w};
#pragma unroll
            for (int i = 0; i < 4; i++)
#pragma unroll
                for (int j = 0; j < 4; j++) acc[i][j] += av[i] * bv[j];
        }
        __syncthreads();
    }
#pragma unroll
    for (int i = 0; i < 4; i++) {
        int m = m0 + tr * 4 + i;
#pragma unroll
        for (int j = 0; j < 4; j++) {
            int n = n0 + tc * 4 + j;
            if (n < N) {
                float v = acc[i][j] + bias[n];
                if (ACT == 1) v = v > 0.f ? v : 0.f;
                if (ACT == 2) v = 1.f / (1.f + expf(-v));
                C[m * N + n] = v;
            }
        }
    }
}

// ---------------- launcher ----------------
extern "C" void kernel_launch(void* const* d_in, const int* in_sizes, int n_in,
                              void* d_out, int out_size) {
    const float* x = (const float*)d_in[0];
    const float* y = (const float*)d_in[1];
    const float* conv1_w = (const float*)d_in[2];
    const float* conv1_b = (const float*)d_in[3];
    const float* prim_w = (const float*)d_in[4];
    const float* prim_bias = (const float*)d_in[5];
    const float* conv_w = (const float*)d_in[6];
    const float* conv_bias = (const float*)d_in[7];
    const float* digit_w = (const float*)d_in[8];
    const float* digit_bias = (const float*)d_in[9];
    const float* fc1_w = (const float*)d_in[10];
    const float* fc1_b = (const float*)d_in[11];
    const float* fc2_w = (const float*)d_in[12];
    const float* fc2_b = (const float*)d_in[13];
    const float* fc3_w = (const float*)d_in[14];
    const float* fc3_b = (const float*)d_in[15];
    float* out = (float*)d_out;              // [0:81920) dcap, [81920:483328) recon

    static float *p_masked = nullptr, *p_r1 = nullptr, *p_r2 = nullptr;
    static float *g_cwT_p = nullptr;
    static bool attrs_set = false;
    if (!p_masked) {
        cudaGetSymbolAddress((void**)&p_masked, g_masked);
        cudaGetSymbolAddress((void**)&p_r1, g_r1);
        cudaGetSymbolAddress((void**)&p_r2, g_r2);
        cudaGetSymbolAddress((void**)&g_cwT_p, g_cwT);
    }
    if (!attrs_set) {
        cudaFuncSetAttribute(prim_mma_kernel, cudaFuncAttributeMaxDynamicSharedMemorySize,
                             PRIM_SMEM);
        cudaFuncSetAttribute(conv1_mma_kernel, cudaFuncAttributeMaxDynamicSharedMemorySize,
                             C1_SMEM);
        cudaFuncSetAttribute(cc_votes_kernel, cudaFuncAttributeMaxDynamicSharedMemorySize,
                             (16384 + 12800) * 4);
        attrs_set = true;
    }

    // weight prep
    prepack_W<<<(25 * 4 * 256 * 64 + 255) / 256, 256>>>(prim_w);
    prepack_c1<<<(256 * 96 + 255) / 256, 256>>>(conv1_w);
    transpose_oc<<<200, 256>>>(conv_w, g_cwT_p, 256, 200);

    // conv1 + relu via tensor cores (writes bf16 hi/lo, pixel-major)
    conv1_mma_kernel<<<1600, 512, C1_SMEM>>>(x, conv1_b);

    // primary caps conv via mma.sync + ldmatrix (R8 best) + fused squash
    prim_mma_kernel<<<256, 512, PRIM_SMEM>>>(prim_bias);

    // conv caps votes (R6 best: smem-staged weights)
    cc_votes_kernel<<<512, 256, (16384 + 12800) * 4>>>();

    // conv caps routing
    cc_routing_kernel<<<2048, 256>>>(conv_bias);

    // digit caps
    digit_kernel<<<512, 256>>>(digit_w, digit_bias, y, out);

    // FC reconstruction chain
    fc_kernel<1><<<dim3(8, 8), 256>>>(p_masked, fc1_w, fc1_b, p_r1, 512, 160, 512);
    fc_kernel<1><<<dim3(16, 8), 256>>>(p_r1, fc2_w, fc2_b, p_r2, 512, 512, 1024);
    fc_kernel<2><<<dim3(13, 8), 256>>>(p_r2, fc3_w, fc3_b, out + 81920, 512, 1024, 784);
}

// round 12
// speedup vs baseline: 1.1605x; 1.0020x over previous
#include <cuda_runtime.h>
#include <cuda_bf16.h>
#include <math.h>
#include <stdint.h>

// ---------------- problem constants ----------------
#define BATCH 512
#define NPRIM 32
#define NCLASS 10

// ---------------- scratch (static device memory; no allocs allowed) ----------------
// conv1 output as bf16 hi/lo split, layout [b][pixel(400)][ic(256)]
__device__ __align__(256) unsigned short g_h1h[BATCH * 400 * 256];   // 100 MB
__device__ __align__(256) unsigned short g_h1l[BATCH * 400 * 256];   // 100 MB
// prim weights prepacked: [kpos25][chunk4][oc256][ic64] bf16 hi/lo
__device__ __align__(256) unsigned short g_Wph[25 * 4 * 256 * 64];   // 3.3 MB
__device__ __align__(256) unsigned short g_Wpl[25 * 4 * 256 * 64];   // 3.3 MB
// conv1 weights prepacked: [oc256][k96] bf16 hi/lo (taps 81..95 zero)
__device__ __align__(256) unsigned short g_c1Wh[256 * 96];
__device__ __align__(256) unsigned short g_c1Wl[256 * 96];
__device__ float g_cwT[8 * 25 * 256];                    // conv_w transposed [c*25+k][oc]
__device__ float g_p[BATCH * NPRIM * 8 * 64];            // primary caps acts [b][i][a][pos]
__device__ float g_votes2[BATCH * 4 * 32 * 256];         // [b][pos][i][oc]
__device__ float g_c[BATCH * 32 * 8 * 4];                // [b][o][a][pos]
__device__ float g_masked[BATCH * 160];
__device__ float g_r1[BATCH * 512];
__device__ float g_r2[BATCH * 1024];

// ---------------- f32x2 helpers ----------------
__device__ __forceinline__ unsigned long long bcast2(float v) {
    unsigned long long r;
    asm("mov.b64 %0, {%1, %1};" : "=l"(r) : "f"(v));
    return r;
}
__device__ __forceinline__ void fma2(unsigned long long& acc, unsigned long long a,
                                     unsigned long long b) {
    asm("fma.rn.f32x2 %0, %1, %2, %0;" : "+l"(acc) : "l"(a), "l"(b));
}
__device__ __forceinline__ float2 unpk(unsigned long long v) {
    float2 r;
    asm("mov.b64 {%0, %1}, %2;" : "=f"(r.x), "=f"(r.y) : "l"(v));
    return r;
}

// ---------------- cp.async helpers ----------------
__device__ __forceinline__ void cp16(void* smem, const void* g) {
    unsigned s;
    asm("{ .reg .u64 t; cvta.to.shared.u64 t, %1; cvt.u32.u64 %0, t; }"
        : "=r"(s) : "l"(smem));
    asm volatile("cp.async.cg.shared.global [%0], [%1], 16;" :: "r"(s), "l"(g));
}
__device__ __forceinline__ void cp_commit() { asm volatile("cp.async.commit_group;"); }
__device__ __forceinline__ void cp_wait0() {
    asm volatile("cp.async.wait_group 0;" ::: "memory");
}

// ---------------- mma.sync bf16 + ldmatrix (sm_80+ legacy tensor path) ----------------
__device__ __forceinline__ void mma_bf16(float* d, const uint32_t* a, uint32_t b0,
                                         uint32_t b1) {
    asm volatile(
        "mma.sync.aligned.m16n8k16.row.col.f32.bf16.bf16.f32 "
        "{%0,%1,%2,%3}, {%4,%5,%6,%7}, {%8,%9}, {%0,%1,%2,%3};"
        : "+f"(d[0]), "+f"(d[1]), "+f"(d[2]), "+f"(d[3])
        : "r"(a[0]), "r"(a[1]), "r"(a[2]), "r"(a[3]), "r"(b0), "r"(b1));
}
__device__ __forceinline__ void ldm_x4(uint32_t* r, uint32_t addr) {
    asm volatile("ldmatrix.sync.aligned.m8n8.x4.shared.b16 {%0,%1,%2,%3}, [%4];"
        : "=r"(r[0]), "=r"(r[1]), "=r"(r[2]), "=r"(r[3]) : "r"(addr));
}
__device__ __forceinline__ uint32_t smem_u32(const void* p) {
    uint32_t a;
    asm("{ .reg .u64 t; cvta.to.shared.u64 t, %1; cvt.u32.u64 %0, t; }" : "=r"(a) : "l"(p));
    return a;
}
__device__ __forceinline__ uint32_t pack_bf16x2(float v0, float v1) {
    __nv_bfloat16 h0 = __float2bfloat16(v0);
    __nv_bfloat16 h1 = __float2bfloat16(v1);
    return (uint32_t)__bfloat16_as_ushort(h0) | ((uint32_t)__bfloat16_as_ushort(h1) << 16);
}

// ---------------- weight transpose: w[oc][ick] -> wt[ick][oc] ----------------
__global__ void transpose_oc(const float* __restrict__ w, float* __restrict__ wt,
                             int OC, int ICK) {
    int idx = blockIdx.x * 256 + threadIdx.x;
    if (idx >= OC * ICK) return;
    int ick = idx / OC, oc = idx % OC;
    wt[idx] = w[oc * ICK + ick];
}

// ---------------- prepack prim weights: [kpos][chunk][oc][ic64] bf16 hi/lo ------------
__global__ void prepack_W(const float* __restrict__ w) {
    int idx = blockIdx.x * 256 + threadIdx.x;
    if (idx >= 25 * 4 * 256 * 64) return;
    int ic = idx & 63;
    int oc = (idx >> 6) & 255;
    int chunk = (idx >> 14) & 3;
    int kpos = idx >> 16;
    float v = w[oc * 6400 + (chunk * 64 + ic) * 25 + kpos];
    __nv_bfloat16 hi = __float2bfloat16(v);
    __nv_bfloat16 lo = __float2bfloat16(v - __bfloat162float(hi));
    g_Wph[idx] = __bfloat16_as_ushort(hi);
    g_Wpl[idx] = __bfloat16_as_ushort(lo);
}

// ---------------- prepack conv1 weights: [oc256][k96] bf16 hi/lo ----------------------
__global__ void prepack_c1(const float* __restrict__ w) {
    int idx = blockIdx.x * 256 + threadIdx.x;
    if (idx >= 256 * 96) return;
    int k = idx % 96, oc = idx / 96;
    float v = (k < 81) ? w[oc * 81 + k] : 0.f;
    __nv_bfloat16 hi = __float2bfloat16(v);
    __nv_bfloat16 lo = __float2bfloat16(v - __bfloat162float(hi));
    g_c1Wh[idx] = __bfloat16_as_ushort(hi);
    g_c1Wl[idx] = __bfloat16_as_ushort(lo);
}

// ---------------- conv1 via mma.sync: M=512*400 rows, N=256 ch, K=96 (81 taps) --------
#define C1P 208
#define C1_IMG 0
#define C1_AH 6400
#define C1_AL (C1_AH + 128 * C1P)      // 33024
#define C1_BH (C1_AL + 128 * C1P)      // 59648
#define C1_BL (C1_BH + 256 * C1P)      // 112896
#define C1_SMEM (C1_BL + 256 * C1P)    // 166144

__global__ __launch_bounds__(512, 1) void conv1_mma_kernel(
    const float* __restrict__ x, const float* __restrict__ bias) {
    extern __shared__ char c1s[];
    int tid = threadIdx.x;
    int blk = blockIdx.x;
    int r0 = blk * 128;
    int b0 = r0 / 400;

    for (int i = 0; i < 6; i++) {
        int q = tid + i * 512;
        int row = q / 12, seg = q % 12;
        cp16(c1s + C1_BH + row * C1P + seg * 16, &g_c1Wh[row * 96 + seg * 8]);
        cp16(c1s + C1_BL + row * C1P + seg * 16, &g_c1Wl[row * 96 + seg * 8]);
    }
    cp_commit();

    float* img = (float*)(c1s + C1_IMG);
    int b1 = (r0 + 127) / 400;
    for (int i = tid; i < 784; i += 512) {
        img[i] = x[(size_t)b0 * 784 + i];
        img[784 + i] = (b1 != b0) ? x[(size_t)b1 * 784 + i] : 0.f;
    }
    __syncthreads();

    uint32_t* ah = (uint32_t*)(c1s + C1_AH);
    uint32_t* al = (uint32_t*)(c1s + C1_AL);
#pragma unroll
    for (int i = 0; i < 12; i++) {
        int w = tid + i * 512;
        int r = w / 48, cw = w % 48;
        int R = r0 + r;
        int b = R / 400, pos = R - b * 400;
        int y = pos / 20, xx = pos - y * 20;
        const float* ip = img + (b - b0) * 784;
        float v[2];
#pragma unroll
        for (int h = 0; h < 2; h++) {
            int c = cw * 2 + h;
            float val = 0.f;
            if (c < 81) {
                int kh = c / 9, kw = c - kh * 9;
                val = ip[(y + kh) * 28 + xx + kw];
            }
            v[h] = val;
        }
        __nv_bfloat16 h0 = __float2bfloat16(v[0]);
        __nv_bfloat16 h1 = __float2bfloat16(v[1]);
        float l0 = v[0] - __bfloat162float(h0);
        float l1 = v[1] - __bfloat162float(h1);
        int off = (r * C1P >> 2) + cw;
        ah[off] = (uint32_t)__bfloat16_as_ushort(h0) |
                  ((uint32_t)__bfloat16_as_ushort(h1) << 16);
        al[off] = pack_bf16x2(l0, l1);
    }
    cp_wait0();
    __syncthreads();

    int wid = tid >> 5, lane = tid & 31;
    int g = lane >> 2, c = lane & 3;
    int warpM = wid & 1;
    int warpN = wid >> 1;
    uint32_t sbase = smem_u32(c1s);
    uint32_t aBase = sbase + C1_AH +
                     (uint32_t)(warpM * 64 + (lane & 15)) * C1P + ((lane >> 4) << 4);
    uint32_t bBase = sbase + C1_BH +
                     (uint32_t)(warpN * 32 + (lane & 7) + ((lane & 16) >> 1)) * C1P +
                     ((lane & 8) ? 16u : 0u);

    float acc[4][4][4];
#pragma unroll
    for (int mt = 0; mt < 4; mt++)
#pragma unroll
        for (int j = 0; j < 4; j++)
#pragma unroll
            for (int q = 0; q < 4; q++) acc[mt][j][q] = 0.f;

#pragma unroll
    for (int kk = 0; kk < 6; kk++) {
        uint32_t bh[2][4], bl[2][4];
#pragma unroll
        for (int np = 0; np < 2; np++) {
            ldm_x4(bh[np], bBase + np * (16 * C1P) + kk * 32);
            ldm_x4(bl[np], bBase + (C1_BL - C1_BH) + np * (16 * C1P) + kk * 32);
        }
#pragma unroll
        for (int mt = 0; mt < 4; mt++) {
            uint32_t ahf[4], alf[4];
            ldm_x4(ahf, aBase + mt * (16 * C1P) + kk * 32);
            ldm_x4(alf, aBase + (C1_AL - C1_AH) + mt * (16 * C1P) + kk * 32);
            // product-major ordering: 4 independent accumulators between RAW reuses
#pragma unroll
            for (int np = 0; np < 2; np++)
#pragma unroll
                for (int nt = 0; nt < 2; nt++)
                    mma_bf16(acc[mt][np * 2 + nt], ahf, bh[np][nt * 2], bh[np][nt * 2 + 1]);
#pragma unroll
            for (int np = 0; np < 2; np++)
#pragma unroll
                for (int nt = 0; nt < 2; nt++)
                    mma_bf16(acc[mt][np * 2 + nt], ahf, bl[np][nt * 2], bl[np][nt * 2 + 1]);
#pragma unroll
            for (int np = 0; np < 2; np++)
#pragma unroll
                for (int nt = 0; nt < 2; nt++)
                    mma_bf16(acc[mt][np * 2 + nt], alf, bh[np][nt * 2], bh[np][nt * 2 + 1]);
        }
    }

#pragma unroll
    for (int mt = 0; mt < 4; mt++) {
        int R1 = r0 + warpM * 64 + mt * 16 + g;
        int R2 = R1 + 8;
#pragma unroll
        for (int j = 0; j < 4; j++) {
            int ch = warpN * 32 + j * 8 + 2 * c;
            float bv0 = __ldg(&bias[ch]);
            float bv1 = __ldg(&bias[ch + 1]);
            float v0 = acc[mt][j][0] + bv0; v0 = v0 > 0.f ? v0 : 0.f;
            float v1 = acc[mt][j][1] + bv1; v1 = v1 > 0.f ? v1 : 0.f;
            float v2 = acc[mt][j][2] + bv0; v2 = v2 > 0.f ? v2 : 0.f;
            float v3 = acc[mt][j][3] + bv1; v3 = v3 > 0.f ? v3 : 0.f;
            __nv_bfloat16 h0 = __float2bfloat16(v0);
            __nv_bfloat16 h1 = __float2bfloat16(v1);
            __nv_bfloat16 h2 = __float2bfloat16(v2);
            __nv_bfloat16 h3 = __float2bfloat16(v3);
            uint32_t hw1 = (uint32_t)__bfloat16_as_ushort(h0) |
                           ((uint32_t)__bfloat16_as_ushort(h1) << 16);
            uint32_t hw2 = (uint32_t)__bfloat16_as_ushort(h2) |
                           ((uint32_t)__bfloat16_as_ushort(h3) << 16);
            uint32_t lw1 = pack_bf16x2(v0 - __bfloat162float(h0), v1 - __bfloat162float(h1));
            uint32_t lw2 = pack_bf16x2(v2 - __bfloat162float(h2), v3 - __bfloat162float(h3));
            size_t o1 = ((size_t)R1 * 256 + ch) >> 1;
            size_t o2 = ((size_t)R2 * 256 + ch) >> 1;
            ((uint32_t*)g_h1h)[o1] = hw1;
            ((uint32_t*)g_h1l)[o1] = lw1;
            ((uint32_t*)g_h1h)[o2] = hw2;
            ((uint32_t*)g_h1l)[o2] = lw2;
        }
    }
}

// ---------------- primary caps conv via mma.sync + ldmatrix (1 sync/step) -------------
#define PITCH 144
#define OFF_AH 0
#define OFF_AL 18432                   // 128*144
#define OFF_BH 36864
#define OFF_BL 73728                   // OFF_BH + 256*144
#define PBUF 110592
#define PRIM_SMEM (2 * PBUF)           // 221184

extern __shared__ char psmem[];

__device__ __forceinline__ void prim_load_step(int buf, int s, int tid, int b0) {
    int kpos = s >> 2, chunk = s & 3;
    int kh = kpos / 5, kw = kpos - kh * 5;
    char* base = psmem + buf * PBUF;
#pragma unroll
    for (int ii = 0; ii < 2; ii++) {
        int i = tid + ii * 512;
        int r = i >> 3, seg = i & 7;
        int batch = r >> 6, pos = r & 63;
        int y = pos >> 3, xx = pos & 7;
        int pix = (2 * y + kh) * 20 + 2 * xx + kw;
        size_t src = ((size_t)(b0 + batch) * 400 + pix) * 256 + chunk * 64 + seg * 8;
        char* d = base + r * PITCH + seg * 16;
        cp16(d + OFF_AH, &g_h1h[src]);
        cp16(d + OFF_AL, &g_h1l[src]);
    }
    size_t wbase = (size_t)s * 16384;
#pragma unroll
    for (int ii = 0; ii < 4; ii++) {
        int i = tid + ii * 512;
        int r = i >> 3, seg = i & 7;
        size_t src = wbase + r * 64 + seg * 8;
        char* d = base + r * PITCH + seg * 16;
        cp16(d + OFF_BH, &g_Wph[src]);
        cp16(d + OFF_BL, &g_Wpl[src]);
    }
}

__global__ __launch_bounds__(512, 1) void prim_mma_kernel(const float* __restrict__ prim_bias) {
    int tid = threadIdx.x;
    int b0 = blockIdx.x * 2;
    int wid = tid >> 5, lane = tid & 31;
    int g = lane >> 2, c = lane & 3;
    int warpM = wid & 1;
    int warpN = wid >> 1;

    uint32_t sbase = smem_u32(psmem);
    uint32_t aOff = (uint32_t)(warpM * 64 + (lane & 15)) * PITCH + ((lane >> 4) << 4);
    uint32_t bRow = (uint32_t)(warpN * 32 + (lane & 7) + ((lane & 16) >> 1));
    uint32_t bOff = bRow * PITCH + ((lane & 8) ? 16u : 0u);

    float acc[4][4][4];
#pragma unroll
    for (int mt = 0; mt < 4; mt++)
#pragma unroll
        for (int j = 0; j < 4; j++)
#pragma unroll
            for (int q = 0; q < 4; q++) acc[mt][j][q] = 0.f;

    prim_load_step(0, 0, tid, b0);
    cp_commit();

    for (int s = 0; s < 100; s++) {
        int buf = s & 1;
        cp_wait0();
        __syncthreads();
        if (s + 1 < 100) {
            prim_load_step(buf ^ 1, s + 1, tid, b0);
            cp_commit();
        }
        uint32_t tbase = sbase + buf * PBUF;
        uint32_t aBase = tbase + OFF_AH + aOff;
        uint32_t bBase = tbase + OFF_BH + bOff;
#pragma unroll
        for (int kk = 0; kk < 4; kk++) {
            uint32_t bh[2][4], bl[2][4];
#pragma unroll
            for (int np = 0; np < 2; np++) {
                ldm_x4(bh[np], bBase + np * (16 * PITCH) + kk * 32);
                ldm_x4(bl[np], bBase + (OFF_BL - OFF_BH) + np * (16 * PITCH) + kk * 32);
            }
#pragma unroll
            for (int mt = 0; mt < 4; mt++) {
                uint32_t ah[4], al[4];
                ldm_x4(ah, aBase + mt * (16 * PITCH) + kk * 32);
                ldm_x4(al, aBase + (OFF_AL - OFF_AH) + mt * (16 * PITCH) + kk * 32);
                // product-major ordering: 4 independent accumulators between RAW reuses
#pragma unroll
                for (int np = 0; np < 2; np++)
#pragma unroll
                    for (int nt = 0; nt < 2; nt++)
                        mma_bf16(acc[mt][np * 2 + nt], ah, bh[np][nt * 2], bh[np][nt * 2 + 1]);
#pragma unroll
                for (int np = 0; np < 2; np++)
#pragma unroll
                    for (int nt = 0; nt < 2; nt++)
                        mma_bf16(acc[mt][np * 2 + nt], ah, bl[np][nt * 2], bl[np][nt * 2 + 1]);
#pragma unroll
                for (int np = 0; np < 2; np++)
#pragma unroll
                    for (int nt = 0; nt < 2; nt++)
                        mma_bf16(acc[mt][np * 2 + nt], al, bh[np][nt * 2], bh[np][nt * 2 + 1]);
            }
        }
    }

    int b_ = b0 + warpM;
#pragma unroll
    for (int mt = 0; mt < 4; mt++) {
        int pos1 = mt * 16 + g;
        int pos2 = pos1 + 8;
#pragma unroll
        for (int j = 0; j < 4; j++) {
            int caps = warpN * 4 + j;
            float bv0 = __ldg(&prim_bias[caps * 8 + 2 * c]);
            float bv1 = __ldg(&prim_bias[caps * 8 + 2 * c + 1]);
            float v0 = acc[mt][j][0] * (1.f / 32.f) + bv0;
            float v1 = acc[mt][j][1] * (1.f / 32.f) + bv1;
            float v2 = acc[mt][j][2] * (1.f / 32.f) + bv0;
            float v3 = acc[mt][j][3] * (1.f / 32.f) + bv1;
            float na = v0 * v0 + v1 * v1;
            float nb = v2 * v2 + v3 * v3;
            na += __shfl_xor_sync(0xFFFFFFFFu, na, 1);
            na += __shfl_xor_sync(0xFFFFFFFFu, na, 2);
            nb += __shfl_xor_sync(0xFFFFFFFFu, nb, 1);
            nb += __shfl_xor_sync(0xFFFFFFFFu, nb, 2);
            float fa = (na / (1.f + na)) * rsqrtf(na + 1e-8f);
            float fb = (nb / (1.f + nb)) * rsqrtf(nb + 1e-8f);
            size_t base = ((size_t)(b_ * 32 + caps) * 8) * 64;
            g_p[base + (2 * c) * 64 + pos1] = v0 * fa;
            g_p[base + (2 * c + 1) * 64 + pos1] = v1 * fa;
            g_p[base + (2 * c) * 64 + pos2] = v2 * fb;
            g_p[base + (2 * c + 1) * 64 + pos2] = v3 * fb;
        }
    }
}

// ---------------- conv-caps votes (f32x2, smem-staged weights) ----------------
__global__ __launch_bounds__(256) void cc_votes_kernel() {
    extern __shared__ float smem[];
    float* sp = smem;
    float* swc = smem + 16384;
    int b = blockIdx.x, tid = threadIdx.x;
    for (int idx = tid; idx < 16384; idx += 256) sp[idx] = g_p[b * 16384 + idx];

    int ocg = tid & 7;
    int i = tid >> 3;
    for (int occ = 0; occ < 4; occ++) {
        __syncthreads();
        for (int idx = tid; idx < 12800; idx += 256)
            swc[idx] = g_cwT[(idx >> 6) * 256 + occ * 64 + (idx & 63)];
        __syncthreads();
        unsigned long long acc[4][4];
#pragma unroll
        for (int p = 0; p < 4; p++)
#pragma unroll
            for (int j = 0; j < 4; j++) acc[p][j] = 0ULL;
#pragma unroll
        for (int cc = 0; cc < 8; cc++) {
            const float* spc = &sp[(i * 8 + cc) * 64];
#pragma unroll
            for (int kh = 0; kh < 5; kh++) {
#pragma unroll
                for (int kw = 0; kw < 5; kw++) {
                    unsigned long long d00 = bcast2(spc[kh * 8 + kw]);
                    unsigned long long d01 = bcast2(spc[kh * 8 + kw + 2]);
                    unsigned long long d10 = bcast2(spc[(kh + 2) * 8 + kw]);
                    unsigned long long d11 = bcast2(spc[(kh + 2) * 8 + kw + 2]);
                    const ulonglong2* wp =
                        (const ulonglong2*)&swc[(cc * 25 + kh * 5 + kw) * 64 + ocg * 8];
                    ulonglong2 wA = wp[0], wB = wp[1];
                    fma2(acc[0][0], d00, wA.x); fma2(acc[0][1], d00, wA.y);
                    fma2(acc[0][2], d00, wB.x); fma2(acc[0][3], d00, wB.y);
                    fma2(acc[1][0], d01, wA.x); fma2(acc[1][1], d01, wA.y);
                    fma2(acc[1][2], d01, wB.x); fma2(acc[1][3], d01, wB.y);
                    fma2(acc[2][0], d10, wA.x); fma2(acc[2][1], d10, wA.y);
                    fma2(acc[2][2], d10, wB.x); fma2(acc[2][3], d10, wB.y);
                    fma2(acc[3][0], d11, wA.x); fma2(acc[3][1], d11, wA.y);
                    fma2(acc[3][2], d11, wB.x); fma2(acc[3][3], d11, wB.y);
                }
            }
        }
#pragma unroll
        for (int p = 0; p < 4; p++) {
            float2 q0 = unpk(acc[p][0]), q1 = unpk(acc[p][1]);
            float2 q2 = unpk(acc[p][2]), q3 = unpk(acc[p][3]);
            float4* dst = (float4*)&g_votes2[((b * 4 + p) * 32 + i) * 256 + occ * 64 + ocg * 8];
            dst[0] = make_float4(q0.x, q0.y, q1.x, q1.y);
            dst[1] = make_float4(q2.x, q2.y, q3.x, q3.y);
        }
    }
}

// ---------------- conv-caps routing (3 iters) ----------------
__global__ __launch_bounds__(256) void cc_routing_kernel(const float* __restrict__ conv_bias) {
    __shared__ float sv[8192];
    __shared__ float slog[1024];
    __shared__ float sroute[1024];
    __shared__ float spre[256];
    __shared__ float sact[256];
    int blk = blockIdx.x;
    int b = blk >> 2, pos = blk & 3;
    int tid = threadIdx.x;
    for (int idx = tid; idx < 8192; idx += 256)
        sv[idx] = g_votes2[(b * 4 + pos) * 8192 + idx];
    for (int e = tid; e < 1024; e += 256) slog[e] = 0.f;
    __syncthreads();

    for (int it = 0; it < 3; it++) {
        if (tid < 32) {
            int i = tid;
            float m = slog[i * 32];
            for (int o = 1; o < 32; o++) m = fmaxf(m, slog[i * 32 + o]);
            float z = 0.f;
            for (int o = 0; o < 32; o++) {
                float e = expf(slog[i * 32 + o] - m);
                sroute[i * 32 + o] = e;
                z += e;
            }
            float inv = 1.f / z;
            for (int o = 0; o < 32; o++) sroute[i * 32 + o] *= inv;
        }
        __syncthreads();
        {
            int o = tid >> 3, a = tid & 7;
            float s = conv_bias[o * 8 + a];
            for (int i = 0; i < 32; i++)
                s += sroute[i * 32 + o] * sv[(i * 32 + o) * 8 + a];
            spre[tid] = s;
        }
        __syncthreads();
        {
            int o = tid >> 3;
            float n2 = 0.f;
#pragma unroll
            for (int a = 0; a < 8; a++) { float v = spre[o * 8 + a]; n2 += v * v; }
            float f = (n2 / (1.f + n2)) * rsqrtf(n2 + 1e-8f);
            sact[tid] = spre[tid] * f;
        }
        __syncthreads();
        if (it < 2) {
            for (int e = tid; e < 1024; e += 256) {
                int o = e & 31;
                float d = 0.f;
#pragma unroll
                for (int a = 0; a < 8; a++) d += sv[e * 8 + a] * sact[o * 8 + a];
                slog[e] += d;
            }
            __syncthreads();
        }
    }
    {
        int o = tid >> 3, a = tid & 7;
        g_c[((b * 32 + o) * 8 + a) * 4 + pos] = sact[tid];
    }
}

// ---------------- digit caps: votes + routing + mask ----------------
__global__ __launch_bounds__(256) void digit_kernel(
    const float* __restrict__ digit_w, const float* __restrict__ digit_bias,
    const float* __restrict__ y, float* __restrict__ out_dcap) {
    __shared__ float smem[11264];
    float* sc = smem;
    float* sdw = smem + 1024;
    float* sv = smem + 6144;
    int b = blockIdx.x, tid = threadIdx.x;
    for (int idx = tid; idx < 1024; idx += 256) sc[idx] = g_c[b * 1024 + idx];
    for (int idx = tid; idx < 5120; idx += 256) sdw[idx] = digit_w[idx];
    __syncthreads();
    for (int idx = tid; idx < 5120; idx += 256) {
        int i = idx / 160, oa = idx % 160;
        float s = 0.f;
        const float* ci = &sc[i * 32];
        const float* wv = &sdw[oa * 32];
#pragma unroll
        for (int z = 0; z < 32; z++) s += ci[z] * wv[z];
        sv[(i * 10 + (oa >> 4)) * 16 + (oa & 15)] = s;
    }
    __syncthreads();
    float* slog = smem;
    float* sroute = smem + 320;
    float* spre = smem + 640;
    float* sact = smem + 800;
    float* sbias = smem + 960;
    for (int e = tid; e < 320; e += 256) slog[e] = 0.f;
    if (tid < 160) sbias[tid] = digit_bias[tid];
    __syncthreads();

    for (int it = 0; it < 3; it++) {
        if (tid < 32) {
            int i = tid;
            float m = slog[i * 10];
            for (int o = 1; o < 10; o++) m = fmaxf(m, slog[i * 10 + o]);
            float z = 0.f;
            for (int o = 0; o < 10; o++) {
                float e = expf(slog[i * 10 + o] - m);
                sroute[i * 10 + o] = e;
                z += e;
            }
            float inv = 1.f / z;
            for (int o = 0; o < 10; o++) sroute[i * 10 + o] *= inv;
        }
        __syncthreads();
        if (tid < 160) {
            int o = tid >> 4, a = tid & 15;
            float s = sbias[tid];
            for (int i = 0; i < 32; i++)
                s += sroute[i * 10 + o] * sv[(i * 10 + o) * 16 + a];
            spre[tid] = s;
        }
        __syncthreads();
        if (tid < 160) {
            int o = tid >> 4;
            float n2 = 0.f;
#pragma unroll
            for (int a = 0; a < 16; a++) { float v = spre[o * 16 + a]; n2 += v * v; }
            float f = (n2 / (1.f + n2)) * rsqrtf(n2 + 1e-8f);
            sact[tid] = spre[tid] * f;
        }
        __syncthreads();
        if (it < 2) {
            for (int e = tid; e < 320; e += 256) {
                int o = e % 10;
                float d = 0.f;
#pragma unroll
                for (int a = 0; a < 16; a++) d += sv[e * 16 + a] * sact[o * 16 + a];
                slog[e] += d;
            }
            __syncthreads();
        }
    }
    if (tid < 160) {
        int o = tid >> 4;
        float v = sact[tid];
        out_dcap[b * 160 + tid] = v;
        g_masked[b * 160 + tid] = v * y[b * 10 + o];
    }
}

// ---------------- FC: C = act(A @ W + bias) ----------------
template <int ACT>
__global__ __launch_bounds__(256) void fc_kernel(
    const float* __restrict__ A, const float* __restrict__ W,
    const float* __restrict__ bias, float* __restrict__ C,
    int M, int K, int N) {
    __shared__ float As[16][64];
    __shared__ float Ws[16][64];
    int m0 = blockIdx.y * 64, n0 = blockIdx.x * 64;
    int tid = threadIdx.x;
    int tr = tid >> 4, tc = tid & 15;
    float acc[4][4];
#pragma unroll
    for (int i = 0; i < 4; i++)
#pragma unroll
        for (int j = 0; j < 4; j++) acc[i][j] = 0.f;

    for (int k0 = 0; k0 < K; k0 += 16) {
        for (int l = tid; l < 1024; l += 256) {
            int ml = l >> 4, kl = l & 15;
            As[kl][ml] = A[(m0 + ml) * K + k0 + kl];
        }
        for (int l = tid; l < 1024; l += 256) {
            int kl = l >> 6, nl = l & 63;
            int n = n0 + nl;
            Ws[kl][nl] = (n < N) ? W[(k0 + kl) * N + n] : 0.f;
        }
        __syncthreads();
#pragma unroll
        for (int kk = 0; kk < 16; kk++) {
            float4 a4 = *(const float4*)&As[kk][tr * 4];
            float4 b4 = *(const float4*)&Ws[kk][tc * 4];
            float av[4] = {a4.x, a4.y, a4.z, a4.w};
            float bv[4] = {b4.x, b4.y, b4.z, b4.w};
#pragma unroll
            for (int i = 0; i < 4; i++)
#pragma unroll
                for (int j = 0; j < 4; j++) acc[i][j] += av[i] * bv[j];
        }
        __syncthreads();
    }
#pragma unroll
    for (int i = 0; i < 4; i++) {
        int m = m0 + tr * 4 + i;
#pragma unroll
        for (int j = 0; j < 4; j++) {
            int n = n0 + tc * 4 + j;
            if (n < N) {
                float v = acc[i][j] + bias[n];
                if (ACT == 1) v = v > 0.f ? v : 0.f;
                if (ACT == 2) v = 1.f / (1.f + expf(-v));
                C[m * N + n] = v;
            }
        }
    }
}

// ---------------- launcher ----------------
extern "C" void kernel_launch(void* const* d_in, const int* in_sizes, int n_in,
                              void* d_out, int out_size) {
    const float* x = (const float*)d_in[0];
    const float* y = (const float*)d_in[1];
    const float* conv1_w = (const float*)d_in[2];
    const float* conv1_b = (const float*)d_in[3];
    const float* prim_w = (const float*)d_in[4];
    const float* prim_bias = (const float*)d_in[5];
    const float* conv_w = (const float*)d_in[6];
    const float* conv_bias = (const float*)d_in[7];
    const float* digit_w = (const float*)d_in[8];
    const float* digit_bias = (const float*)d_in[9];
    const float* fc1_w = (const float*)d_in[10];
    const float* fc1_b = (const float*)d_in[11];
    const float* fc2_w = (const float*)d_in[12];
    const float* fc2_b = (const float*)d_in[13];
    const float* fc3_w = (const float*)d_in[14];
    const float* fc3_b = (const float*)d_in[15];
    float* out = (float*)d_out;              // [0:81920) dcap, [81920:483328) recon

    static float *p_masked = nullptr, *p_r1 = nullptr, *p_r2 = nullptr;
    static float *g_cwT_p = nullptr;
    static bool attrs_set = false;
    if (!p_masked) {
        cudaGetSymbolAddress((void**)&p_masked, g_masked);
        cudaGetSymbolAddress((void**)&p_r1, g_r1);
        cudaGetSymbolAddress((void**)&p_r2, g_r2);
        cudaGetSymbolAddress((void**)&g_cwT_p, g_cwT);
    }
    if (!attrs_set) {
        cudaFuncSetAttribute(prim_mma_kernel, cudaFuncAttributeMaxDynamicSharedMemorySize,
                             PRIM_SMEM);
        cudaFuncSetAttribute(conv1_mma_kernel, cudaFuncAttributeMaxDynamicSharedMemorySize,
                             C1_SMEM);
        cudaFuncSetAttribute(cc_votes_kernel, cudaFuncAttributeMaxDynamicSharedMemorySize,
                             (16384 + 12800) * 4);
        attrs_set = true;
    }

    // weight prep
    prepack_W<<<(25 * 4 * 256 * 64 + 255) / 256, 256>>>(prim_w);
    prepack_c1<<<(256 * 96 + 255) / 256, 256>>>(conv1_w);
    transpose_oc<<<200, 256>>>(conv_w, g_cwT_p, 256, 200);

    // conv1 + relu via tensor cores (writes bf16 hi/lo, pixel-major)
    conv1_mma_kernel<<<1600, 512, C1_SMEM>>>(x, conv1_b);

    // primary caps conv via mma.sync + ldmatrix + fused squash
    prim_mma_kernel<<<256, 512, PRIM_SMEM>>>(prim_bias);

    // conv caps votes (smem-staged weights)
    cc_votes_kernel<<<512, 256, (16384 + 12800) * 4>>>();

    // conv caps routing
    cc_routing_kernel<<<2048, 256>>>(conv_bias);

    // digit caps
    digit_kernel<<<512, 256>>>(digit_w, digit_bias, y, out);

    // FC reconstruction chain
    fc_kernel<1><<<dim3(8, 8), 256>>>(p_masked, fc1_w, fc1_b, p_r1, 512, 160, 512);
    fc_kernel<1><<<dim3(16, 8), 256>>>(p_r1, fc2_w, fc2_b, p_r2, 512, 512, 1024);
    fc_kernel<2><<<dim3(13, 8), 256>>>(p_r2, fc3_w, fc3_b, out + 81920, 512, 1024, 784);
}

// round 13
// speedup vs baseline: 1.3539x; 1.1666x over previous
#include <cuda_runtime.h>
#include <cuda_bf16.h>
#include <math.h>
#include <stdint.h>

// ---------------- problem constants ----------------
#define BATCH 512
#define NPRIM 32
#define NCLASS 10

// ---------------- scratch (static device memory; no allocs allowed) ----------------
// conv1 output as bf16 hi/lo split, layout [b][pixel(400)][ic(256)]
__device__ __align__(256) unsigned short g_h1h[BATCH * 400 * 256];   // 100 MB
__device__ __align__(256) unsigned short g_h1l[BATCH * 400 * 256];   // 100 MB
// prim weights prepacked: [kpos25][chunk4][oc256][ic64] bf16 hi (lo dropped: 2-product)
__device__ __align__(256) unsigned short g_Wph[25 * 4 * 256 * 64];   // 3.3 MB
// conv1 weights prepacked: [oc256][k96] bf16 hi
__device__ __align__(256) unsigned short g_c1Wh[256 * 96];
__device__ float g_cwT[8 * 25 * 256];                    // conv_w transposed [c*25+k][oc]
__device__ float g_p[BATCH * NPRIM * 8 * 64];            // primary caps acts [b][i][a][pos]
__device__ float g_votes2[BATCH * 4 * 32 * 256];         // [b][pos][i][oc]
__device__ float g_c[BATCH * 32 * 8 * 4];                // [b][o][a][pos]
__device__ float g_masked[BATCH * 160];
__device__ float g_r1[BATCH * 512];
__device__ float g_r2[BATCH * 1024];

// ---------------- f32x2 helpers ----------------
__device__ __forceinline__ unsigned long long bcast2(float v) {
    unsigned long long r;
    asm("mov.b64 %0, {%1, %1};" : "=l"(r) : "f"(v));
    return r;
}
__device__ __forceinline__ void fma2(unsigned long long& acc, unsigned long long a,
                                     unsigned long long b) {
    asm("fma.rn.f32x2 %0, %1, %2, %0;" : "+l"(acc) : "l"(a), "l"(b));
}
__device__ __forceinline__ float2 unpk(unsigned long long v) {
    float2 r;
    asm("mov.b64 {%0, %1}, %2;" : "=f"(r.x), "=f"(r.y) : "l"(v));
    return r;
}

// ---------------- cp.async helpers ----------------
__device__ __forceinline__ void cp16(void* smem, const void* g) {
    unsigned s;
    asm("{ .reg .u64 t; cvta.to.shared.u64 t, %1; cvt.u32.u64 %0, t; }"
        : "=r"(s) : "l"(smem));
    asm volatile("cp.async.cg.shared.global [%0], [%1], 16;" :: "r"(s), "l"(g));
}
__device__ __forceinline__ void cp_commit() { asm volatile("cp.async.commit_group;"); }
__device__ __forceinline__ void cp_wait0() {
    asm volatile("cp.async.wait_group 0;" ::: "memory");
}

// ---------------- mma.sync bf16 + ldmatrix (sm_80+ legacy tensor path) ----------------
__device__ __forceinline__ void mma_bf16(float* d, const uint32_t* a, uint32_t b0,
                                         uint32_t b1) {
    asm volatile(
        "mma.sync.aligned.m16n8k16.row.col.f32.bf16.bf16.f32 "
        "{%0,%1,%2,%3}, {%4,%5,%6,%7}, {%8,%9}, {%0,%1,%2,%3};"
        : "+f"(d[0]), "+f"(d[1]), "+f"(d[2]), "+f"(d[3])
        : "r"(a[0]), "r"(a[1]), "r"(a[2]), "r"(a[3]), "r"(b0), "r"(b1));
}
__device__ __forceinline__ void ldm_x4(uint32_t* r, uint32_t addr) {
    asm volatile("ldmatrix.sync.aligned.m8n8.x4.shared.b16 {%0,%1,%2,%3}, [%4];"
        : "=r"(r[0]), "=r"(r[1]), "=r"(r[2]), "=r"(r[3]) : "r"(addr));
}
__device__ __forceinline__ uint32_t smem_u32(const void* p) {
    uint32_t a;
    asm("{ .reg .u64 t; cvta.to.shared.u64 t, %1; cvt.u32.u64 %0, t; }" : "=r"(a) : "l"(p));
    return a;
}
__device__ __forceinline__ uint32_t pack_bf16x2(float v0, float v1) {
    __nv_bfloat16 h0 = __float2bfloat16(v0);
    __nv_bfloat16 h1 = __float2bfloat16(v1);
    return (uint32_t)__bfloat16_as_ushort(h0) | ((uint32_t)__bfloat16_as_ushort(h1) << 16);
}

// ---------------- weight transpose: w[oc][ick] -> wt[ick][oc] ----------------
__global__ void transpose_oc(const float* __restrict__ w, float* __restrict__ wt,
                             int OC, int ICK) {
    int idx = blockIdx.x * 256 + threadIdx.x;
    if (idx >= OC * ICK) return;
    int ick = idx / OC, oc = idx % OC;
    wt[idx] = w[oc * ICK + ick];
}

// ---------------- prepack prim weights: [kpos][chunk][oc][ic64] bf16 hi ---------------
__global__ void prepack_W(const float* __restrict__ w) {
    int idx = blockIdx.x * 256 + threadIdx.x;
    if (idx >= 25 * 4 * 256 * 64) return;
    int ic = idx & 63;
    int oc = (idx >> 6) & 255;
    int chunk = (idx >> 14) & 3;
    int kpos = idx >> 16;
    float v = w[oc * 6400 + (chunk * 64 + ic) * 25 + kpos];
    g_Wph[idx] = __bfloat16_as_ushort(__float2bfloat16(v));
}

// ---------------- prepack conv1 weights: [oc256][k96] bf16 hi --------------------------
__global__ void prepack_c1(const float* __restrict__ w) {
    int idx = blockIdx.x * 256 + threadIdx.x;
    if (idx >= 256 * 96) return;
    int k = idx % 96, oc = idx / 96;
    float v = (k < 81) ? w[oc * 81 + k] : 0.f;
    g_c1Wh[idx] = __bfloat16_as_ushort(__float2bfloat16(v));
}

// ---------------- conv1 via mma.sync: M=512*400 rows, N=256 ch, K=96 (81 taps) --------
#define C1P 208
#define C1_IMG 0
#define C1_AH 6400
#define C1_AL (C1_AH + 128 * C1P)      // 33024
#define C1_BH (C1_AL + 128 * C1P)      // 59648
#define C1_SMEM (C1_BH + 256 * C1P)    // 112896

__global__ __launch_bounds__(512, 1) void conv1_mma_kernel(
    const float* __restrict__ x, const float* __restrict__ bias) {
    extern __shared__ char c1s[];
    int tid = threadIdx.x;
    int blk = blockIdx.x;
    int r0 = blk * 128;
    int b0 = r0 / 400;

    for (int i = 0; i < 6; i++) {
        int q = tid + i * 512;
        int row = q / 12, seg = q % 12;
        cp16(c1s + C1_BH + row * C1P + seg * 16, &g_c1Wh[row * 96 + seg * 8]);
    }
    cp_commit();

    float* img = (float*)(c1s + C1_IMG);
    int b1 = (r0 + 127) / 400;
    for (int i = tid; i < 784; i += 512) {
        img[i] = x[(size_t)b0 * 784 + i];
        img[784 + i] = (b1 != b0) ? x[(size_t)b1 * 784 + i] : 0.f;
    }
    __syncthreads();

    uint32_t* ah = (uint32_t*)(c1s + C1_AH);
    uint32_t* al = (uint32_t*)(c1s + C1_AL);
#pragma unroll
    for (int i = 0; i < 12; i++) {
        int w = tid + i * 512;
        int r = w / 48, cw = w % 48;
        int R = r0 + r;
        int b = R / 400, pos = R - b * 400;
        int y = pos / 20, xx = pos - y * 20;
        const float* ip = img + (b - b0) * 784;
        float v[2];
#pragma unroll
        for (int h = 0; h < 2; h++) {
            int c = cw * 2 + h;
            float val = 0.f;
            if (c < 81) {
                int kh = c / 9, kw = c - kh * 9;
                val = ip[(y + kh) * 28 + xx + kw];
            }
            v[h] = val;
        }
        __nv_bfloat16 h0 = __float2bfloat16(v[0]);
        __nv_bfloat16 h1 = __float2bfloat16(v[1]);
        float l0 = v[0] - __bfloat162float(h0);
        float l1 = v[1] - __bfloat162float(h1);
        int off = (r * C1P >> 2) + cw;
        ah[off] = (uint32_t)__bfloat16_as_ushort(h0) |
                  ((uint32_t)__bfloat16_as_ushort(h1) << 16);
        al[off] = pack_bf16x2(l0, l1);
    }
    cp_wait0();
    __syncthreads();

    int wid = tid >> 5, lane = tid & 31;
    int g = lane >> 2, c = lane & 3;
    int warpM = wid & 1;
    int warpN = wid >> 1;
    uint32_t sbase = smem_u32(c1s);
    uint32_t aBase = sbase + C1_AH +
                     (uint32_t)(warpM * 64 + (lane & 15)) * C1P + ((lane >> 4) << 4);
    uint32_t bBase = sbase + C1_BH +
                     (uint32_t)(warpN * 32 + (lane & 7) + ((lane & 16) >> 1)) * C1P +
                     ((lane & 8) ? 16u : 0u);

    float acc[4][4][4];
#pragma unroll
    for (int mt = 0; mt < 4; mt++)
#pragma unroll
        for (int j = 0; j < 4; j++)
#pragma unroll
            for (int q = 0; q < 4; q++) acc[mt][j][q] = 0.f;

#pragma unroll
    for (int kk = 0; kk < 6; kk++) {
        uint32_t bh[2][4];
#pragma unroll
        for (int np = 0; np < 2; np++)
            ldm_x4(bh[np], bBase + np * (16 * C1P) + kk * 32);
#pragma unroll
        for (int mt = 0; mt < 4; mt++) {
            uint32_t ahf[4], alf[4];
            ldm_x4(ahf, aBase + mt * (16 * C1P) + kk * 32);
            ldm_x4(alf, aBase + (C1_AL - C1_AH) + mt * (16 * C1P) + kk * 32);
#pragma unroll
            for (int np = 0; np < 2; np++)
#pragma unroll
                for (int nt = 0; nt < 2; nt++)
                    mma_bf16(acc[mt][np * 2 + nt], ahf, bh[np][nt * 2], bh[np][nt * 2 + 1]);
#pragma unroll
            for (int np = 0; np < 2; np++)
#pragma unroll
                for (int nt = 0; nt < 2; nt++)
                    mma_bf16(acc[mt][np * 2 + nt], alf, bh[np][nt * 2], bh[np][nt * 2 + 1]);
        }
    }

#pragma unroll
    for (int mt = 0; mt < 4; mt++) {
        int R1 = r0 + warpM * 64 + mt * 16 + g;
        int R2 = R1 + 8;
#pragma unroll
        for (int j = 0; j < 4; j++) {
            int ch = warpN * 32 + j * 8 + 2 * c;
            float bv0 = __ldg(&bias[ch]);
            float bv1 = __ldg(&bias[ch + 1]);
            float v0 = acc[mt][j][0] + bv0; v0 = v0 > 0.f ? v0 : 0.f;
            float v1 = acc[mt][j][1] + bv1; v1 = v1 > 0.f ? v1 : 0.f;
            float v2 = acc[mt][j][2] + bv0; v2 = v2 > 0.f ? v2 : 0.f;
            float v3 = acc[mt][j][3] + bv1; v3 = v3 > 0.f ? v3 : 0.f;
            __nv_bfloat16 h0 = __float2bfloat16(v0);
            __nv_bfloat16 h1 = __float2bfloat16(v1);
            __nv_bfloat16 h2 = __float2bfloat16(v2);
            __nv_bfloat16 h3 = __float2bfloat16(v3);
            uint32_t hw1 = (uint32_t)__bfloat16_as_ushort(h0) |
                           ((uint32_t)__bfloat16_as_ushort(h1) << 16);
            uint32_t hw2 = (uint32_t)__bfloat16_as_ushort(h2) |
                           ((uint32_t)__bfloat16_as_ushort(h3) << 16);
            uint32_t lw1 = pack_bf16x2(v0 - __bfloat162float(h0), v1 - __bfloat162float(h1));
            uint32_t lw2 = pack_bf16x2(v2 - __bfloat162float(h2), v3 - __bfloat162float(h3));
            size_t o1 = ((size_t)R1 * 256 + ch) >> 1;
            size_t o2 = ((size_t)R2 * 256 + ch) >> 1;
            ((uint32_t*)g_h1h)[o1] = hw1;
            ((uint32_t*)g_h1l)[o1] = lw1;
            ((uint32_t*)g_h1h)[o2] = hw2;
            ((uint32_t*)g_h1l)[o2] = lw2;
        }
    }
}

// ---------------- primary caps conv via mma.sync + ldmatrix (2-product, 1 sync/step) --
#define PITCH 144
#define OFF_AH 0
#define OFF_AL 18432                   // 128*144
#define OFF_BH 36864
#define PBUF 73728                     // OFF_BH + 256*144
#define PRIM_SMEM (2 * PBUF)           // 147456

extern __shared__ char psmem[];

__device__ __forceinline__ void prim_load_step(int buf, int s, int tid, int b0) {
    int kpos = s >> 2, chunk = s & 3;
    int kh = kpos / 5, kw = kpos - kh * 5;
    char* base = psmem + buf * PBUF;
#pragma unroll
    for (int ii = 0; ii < 2; ii++) {
        int i = tid + ii * 512;
        int r = i >> 3, seg = i & 7;
        int batch = r >> 6, pos = r & 63;
        int y = pos >> 3, xx = pos & 7;
        int pix = (2 * y + kh) * 20 + 2 * xx + kw;
        size_t src = ((size_t)(b0 + batch) * 400 + pix) * 256 + chunk * 64 + seg * 8;
        char* d = base + r * PITCH + seg * 16;
        cp16(d + OFF_AH, &g_h1h[src]);
        cp16(d + OFF_AL, &g_h1l[src]);
    }
    size_t wbase = (size_t)s * 16384;
#pragma unroll
    for (int ii = 0; ii < 4; ii++) {
        int i = tid + ii * 512;
        int r = i >> 3, seg = i & 7;
        cp16(base + OFF_BH + r * PITCH + seg * 16, &g_Wph[wbase + r * 64 + seg * 8]);
    }
}

__global__ __launch_bounds__(512, 1) void prim_mma_kernel(const float* __restrict__ prim_bias) {
    int tid = threadIdx.x;
    int b0 = blockIdx.x * 2;
    int wid = tid >> 5, lane = tid & 31;
    int g = lane >> 2, c = lane & 3;
    int warpM = wid & 1;
    int warpN = wid >> 1;

    uint32_t sbase = smem_u32(psmem);
    uint32_t aOff = (uint32_t)(warpM * 64 + (lane & 15)) * PITCH + ((lane >> 4) << 4);
    uint32_t bRow = (uint32_t)(warpN * 32 + (lane & 7) + ((lane & 16) >> 1));
    uint32_t bOff = bRow * PITCH + ((lane & 8) ? 16u : 0u);

    float acc[4][4][4];
#pragma unroll
    for (int mt = 0; mt < 4; mt++)
#pragma unroll
        for (int j = 0; j < 4; j++)
#pragma unroll
            for (int q = 0; q < 4; q++) acc[mt][j][q] = 0.f;

    prim_load_step(0, 0, tid, b0);
    cp_commit();

    for (int s = 0; s < 100; s++) {
        int buf = s & 1;
        cp_wait0();
        __syncthreads();
        if (s + 1 < 100) {
            prim_load_step(buf ^ 1, s + 1, tid, b0);
            cp_commit();
        }
        uint32_t tbase = sbase + buf * PBUF;
        uint32_t aBase = tbase + OFF_AH + aOff;
        uint32_t bBase = tbase + OFF_BH + bOff;
#pragma unroll
        for (int kk = 0; kk < 4; kk++) {
            uint32_t bh[2][4];
#pragma unroll
            for (int np = 0; np < 2; np++)
                ldm_x4(bh[np], bBase + np * (16 * PITCH) + kk * 32);
#pragma unroll
            for (int mt = 0; mt < 4; mt++) {
                uint32_t ah[4], al[4];
                ldm_x4(ah, aBase + mt * (16 * PITCH) + kk * 32);
                ldm_x4(al, aBase + (OFF_AL - OFF_AH) + mt * (16 * PITCH) + kk * 32);
#pragma unroll
                for (int np = 0; np < 2; np++)
#pragma unroll
                    for (int nt = 0; nt < 2; nt++)
                        mma_bf16(acc[mt][np * 2 + nt], ah, bh[np][nt * 2], bh[np][nt * 2 + 1]);
#pragma unroll
                for (int np = 0; np < 2; np++)
#pragma unroll
                    for (int nt = 0; nt < 2; nt++)
                        mma_bf16(acc[mt][np * 2 + nt], al, bh[np][nt * 2], bh[np][nt * 2 + 1]);
            }
        }
    }

    int b_ = b0 + warpM;
#pragma unroll
    for (int mt = 0; mt < 4; mt++) {
        int pos1 = mt * 16 + g;
        int pos2 = pos1 + 8;
#pragma unroll
        for (int j = 0; j < 4; j++) {
            int caps = warpN * 4 + j;
            float bv0 = __ldg(&prim_bias[caps * 8 + 2 * c]);
            float bv1 = __ldg(&prim_bias[caps * 8 + 2 * c + 1]);
            float v0 = acc[mt][j][0] * (1.f / 32.f) + bv0;
            float v1 = acc[mt][j][1] * (1.f / 32.f) + bv1;
            float v2 = acc[mt][j][2] * (1.f / 32.f) + bv0;
            float v3 = acc[mt][j][3] * (1.f / 32.f) + bv1;
            float na = v0 * v0 + v1 * v1;
            float nb = v2 * v2 + v3 * v3;
            na += __shfl_xor_sync(0xFFFFFFFFu, na, 1);
            na += __shfl_xor_sync(0xFFFFFFFFu, na, 2);
            nb += __shfl_xor_sync(0xFFFFFFFFu, nb, 1);
            nb += __shfl_xor_sync(0xFFFFFFFFu, nb, 2);
            float fa = (na / (1.f + na)) * rsqrtf(na + 1e-8f);
            float fb = (nb / (1.f + nb)) * rsqrtf(nb + 1e-8f);
            size_t base = ((size_t)(b_ * 32 + caps) * 8) * 64;
            g_p[base + (2 * c) * 64 + pos1] = v0 * fa;
            g_p[base + (2 * c + 1) * 64 + pos1] = v1 * fa;
            g_p[base + (2 * c) * 64 + pos2] = v2 * fb;
            g_p[base + (2 * c + 1) * 64 + pos2] = v3 * fb;
        }
    }
}

// ---------------- conv-caps votes (f32x2, smem-staged weights) ----------------
__global__ __launch_bounds__(256) void cc_votes_kernel() {
    extern __shared__ float smem[];
    float* sp = smem;
    float* swc = smem + 16384;
    int b = blockIdx.x, tid = threadIdx.x;
    for (int idx = tid; idx < 16384; idx += 256) sp[idx] = g_p[b * 16384 + idx];

    int ocg = tid & 7;
    int i = tid >> 3;
    for (int occ = 0; occ < 4; occ++) {
        __syncthreads();
        for (int idx = tid; idx < 12800; idx += 256)
            swc[idx] = g_cwT[(idx >> 6) * 256 + occ * 64 + (idx & 63)];
        __syncthreads();
        unsigned long long acc[4][4];
#pragma unroll
        for (int p = 0; p < 4; p++)
#pragma unroll
            for (int j = 0; j < 4; j++) acc[p][j] = 0ULL;
#pragma unroll
        for (int cc = 0; cc < 8; cc++) {
            const float* spc = &sp[(i * 8 + cc) * 64];
#pragma unroll
            for (int kh = 0; kh < 5; kh++) {
#pragma unroll
                for (int kw = 0; kw < 5; kw++) {
                    unsigned long long d00 = bcast2(spc[kh * 8 + kw]);
                    unsigned long long d01 = bcast2(spc[kh * 8 + kw + 2]);
                    unsigned long long d10 = bcast2(spc[(kh + 2) * 8 + kw]);
                    unsigned long long d11 = bcast2(spc[(kh + 2) * 8 + kw + 2]);
                    const ulonglong2* wp =
                        (const ulonglong2*)&swc[(cc * 25 + kh * 5 + kw) * 64 + ocg * 8];
                    ulonglong2 wA = wp[0], wB = wp[1];
                    fma2(acc[0][0], d00, wA.x); fma2(acc[0][1], d00, wA.y);
                    fma2(acc[0][2], d00, wB.x); fma2(acc[0][3], d00, wB.y);
                    fma2(acc[1][0], d01, wA.x); fma2(acc[1][1], d01, wA.y);
                    fma2(acc[1][2], d01, wB.x); fma2(acc[1][3], d01, wB.y);
                    fma2(acc[2][0], d10, wA.x); fma2(acc[2][1], d10, wA.y);
                    fma2(acc[2][2], d10, wB.x); fma2(acc[2][3], d10, wB.y);
                    fma2(acc[3][0], d11, wA.x); fma2(acc[3][1], d11, wA.y);
                    fma2(acc[3][2], d11, wB.x); fma2(acc[3][3], d11, wB.y);
                }
            }
        }
#pragma unroll
        for (int p = 0; p < 4; p++) {
            float2 q0 = unpk(acc[p][0]), q1 = unpk(acc[p][1]);
            float2 q2 = unpk(acc[p][2]), q3 = unpk(acc[p][3]);
            float4* dst = (float4*)&g_votes2[((b * 4 + p) * 32 + i) * 256 + occ * 64 + ocg * 8];
            dst[0] = make_float4(q0.x, q0.y, q1.x, q1.y);
            dst[1] = make_float4(q2.x, q2.y, q3.x, q3.y);
        }
    }
}

// ---------------- conv-caps routing (3 iters) ----------------
__global__ __launch_bounds__(256) void cc_routing_kernel(const float* __restrict__ conv_bias) {
    __shared__ float sv[8192];
    __shared__ float slog[1024];
    __shared__ float sroute[1024];
    __shared__ float spre[256];
    __shared__ float sact[256];
    int blk = blockIdx.x;
    int b = blk >> 2, pos = blk & 3;
    int tid = threadIdx.x;
    for (int idx = tid; idx < 8192; idx += 256)
        sv[idx] = g_votes2[(b * 4 + pos) * 8192 + idx];
    for (int e = tid; e < 1024; e += 256) slog[e] = 0.f;
    __syncthreads();

    for (int it = 0; it < 3; it++) {
        if (tid < 32) {
            int i = tid;
            float m = slog[i * 32];
            for (int o = 1; o < 32; o++) m = fmaxf(m, slog[i * 32 + o]);
            float z = 0.f;
            for (int o = 0; o < 32; o++) {
                float e = expf(slog[i * 32 + o] - m);
                sroute[i * 32 + o] = e;
                z += e;
            }
            float inv = 1.f / z;
            for (int o = 0; o < 32; o++) sroute[i * 32 + o] *= inv;
        }
        __syncthreads();
        {
            int o = tid >> 3, a = tid & 7;
            float s = conv_bias[o * 8 + a];
            for (int i = 0; i < 32; i++)
                s += sroute[i * 32 + o] * sv[(i * 32 + o) * 8 + a];
            spre[tid] = s;
        }
        __syncthreads();
        {
            int o = tid >> 3;
            float n2 = 0.f;
#pragma unroll
            for (int a = 0; a < 8; a++) { float v = spre[o * 8 + a]; n2 += v * v; }
            float f = (n2 / (1.f + n2)) * rsqrtf(n2 + 1e-8f);
            sact[tid] = spre[tid] * f;
        }
        __syncthreads();
        if (it < 2) {
            for (int e = tid; e < 1024; e += 256) {
                int o = e & 31;
                float d = 0.f;
#pragma unroll
                for (int a = 0; a < 8; a++) d += sv[e * 8 + a] * sact[o * 8 + a];
                slog[e] += d;
            }
            __syncthreads();
        }
    }
    {
        int o = tid >> 3, a = tid & 7;
        g_c[((b * 32 + o) * 8 + a) * 4 + pos] = sact[tid];
    }
}

// ---------------- digit caps: votes + routing + mask ----------------
__global__ __launch_bounds__(256) void digit_kernel(
    const float* __restrict__ digit_w, const float* __restrict__ digit_bias,
    const float* __restrict__ y, float* __restrict__ out_dcap) {
    __shared__ float smem[11264];
    float* sc = smem;
    float* sdw = smem + 1024;
    float* sv = smem + 6144;
    int b = blockIdx.x, tid = threadIdx.x;
    for (int idx = tid; idx < 1024; idx += 256) sc[idx] = g_c[b * 1024 + idx];
    for (int idx = tid; idx < 5120; idx += 256) sdw[idx] = digit_w[idx];
    __syncthreads();
    for (int idx = tid; idx < 5120; idx += 256) {
        int i = idx / 160, oa = idx % 160;
        float s = 0.f;
        const float* ci = &sc[i * 32];
        const float* wv = &sdw[oa * 32];
#pragma unroll
        for (int z = 0; z < 32; z++) s += ci[z] * wv[z];
        sv[(i * 10 + (oa >> 4)) * 16 + (oa & 15)] = s;
    }
    __syncthreads();
    float* slog = smem;
    float* sroute = smem + 320;
    float* spre = smem + 640;
    float* sact = smem + 800;
    float* sbias = smem + 960;
    for (int e = tid; e < 320; e += 256) slog[e] = 0.f;
    if (tid < 160) sbias[tid] = digit_bias[tid];
    __syncthreads();

    for (int it = 0; it < 3; it++) {
        if (tid < 32) {
            int i = tid;
            float m = slog[i * 10];
            for (int o = 1; o < 10; o++) m = fmaxf(m, slog[i * 10 + o]);
            float z = 0.f;
            for (int o = 0; o < 10; o++) {
                float e = expf(slog[i * 10 + o] - m);
                sroute[i * 10 + o] = e;
                z += e;
            }
            float inv = 1.f / z;
            for (int o = 0; o < 10; o++) sroute[i * 10 + o] *= inv;
        }
        __syncthreads();
        if (tid < 160) {
            int o = tid >> 4, a = tid & 15;
            float s = sbias[tid];
            for (int i = 0; i < 32; i++)
                s += sroute[i * 10 + o] * sv[(i * 10 + o) * 16 + a];
            spre[tid] = s;
        }
        __syncthreads();
        if (tid < 160) {
            int o = tid >> 4;
            float n2 = 0.f;
#pragma unroll
            for (int a = 0; a < 16; a++) { float v = spre[o * 16 + a]; n2 += v * v; }
            float f = (n2 / (1.f + n2)) * rsqrtf(n2 + 1e-8f);
            sact[tid] = spre[tid] * f;
        }
        __syncthreads();
        if (it < 2) {
            for (int e = tid; e < 320; e += 256) {
                int o = e % 10;
                float d = 0.f;
#pragma unroll
                for (int a = 0; a < 16; a++) d += sv[e * 16 + a] * sact[o * 16 + a];
                slog[e] += d;
            }
            __syncthreads();
        }
    }
    if (tid < 160) {
        int o = tid >> 4;
        float v = sact[tid];
        out_dcap[b * 160 + tid] = v;
        g_masked[b * 160 + tid] = v * y[b * 10 + o];
    }
}

// ---------------- FC: C = act(A @ W + bias) ----------------
template <int ACT>
__global__ __launch_bounds__(256) void fc_kernel(
    const float* __restrict__ A, const float* __restrict__ W,
    const float* __restrict__ bias, float* __restrict__ C,
    int M, int K, int N) {
    __shared__ float As[16][64];
    __shared__ float Ws[16][64];
    int m0 = blockIdx.y * 64, n0 = blockIdx.x * 64;
    int tid = threadIdx.x;
    int tr = tid >> 4, tc = tid & 15;
    float acc[4][4];
#pragma unroll
    for (int i = 0; i < 4; i++)
#pragma unroll
        for (int j = 0; j < 4; j++) acc[i][j] = 0.f;

    for (int k0 = 0; k0 < K; k0 += 16) {
        for (int l = tid; l < 1024; l += 256) {
            int ml = l >> 4, kl = l & 15;
            As[kl][ml] = A[(m0 + ml) * K + k0 + kl];
        }
        for (int l = tid; l < 1024; l += 256) {
            int kl = l >> 6, nl = l & 63;
            int n = n0 + nl;
            Ws[kl][nl] = (n < N) ? W[(k0 + kl) * N + n] : 0.f;
        }
        __syncthreads();
#pragma unroll
        for (int kk = 0; kk < 16; kk++) {
            float4 a4 = *(const float4*)&As[kk][tr * 4];
            float4 b4 = *(const float4*)&Ws[kk][tc * 4];
            float av[4] = {a4.x, a4.y, a4.z, a4.w};
            float bv[4] = {b4.x, b4.y, b4.z, b4.w};
#pragma unroll
            for (int i = 0; i < 4; i++)
#pragma unroll
                for (int j = 0; j < 4; j++) acc[i][j] += av[i] * bv[j];
        }
        __syncthreads();
    }
#pragma unroll
    for (int i = 0; i < 4; i++) {
        int m = m0 + tr * 4 + i;
#pragma unroll
        for (int j = 0; j < 4; j++) {
            int n = n0 + tc * 4 + j;
            if (n < N) {
                float v = acc[i][j] + bias[n];
                if (ACT == 1) v = v > 0.f ? v : 0.f;
                if (ACT == 2) v = 1.f / (1.f + expf(-v));
                C[m * N + n] = v;
            }
        }
    }
}

// ---------------- launcher ----------------
extern "C" void kernel_launch(void* const* d_in, const int* in_sizes, int n_in,
                              void* d_out, int out_size) {
    const float* x = (const float*)d_in[0];
    const float* y = (const float*)d_in[1];
    const float* conv1_w = (const float*)d_in[2];
    const float* conv1_b = (const float*)d_in[3];
    const float* prim_w = (const float*)d_in[4];
    const float* prim_bias = (const float*)d_in[5];
    const float* conv_w = (const float*)d_in[6];
    const float* conv_bias = (const float*)d_in[7];
    const float* digit_w = (const float*)d_in[8];
    const float* digit_bias = (const float*)d_in[9];
    const float* fc1_w = (const float*)d_in[10];
    const float* fc1_b = (const float*)d_in[11];
    const float* fc2_w = (const float*)d_in[12];
    const float* fc2_b = (const float*)d_in[13];
    const float* fc3_w = (const float*)d_in[14];
    const float* fc3_b = (const float*)d_in[15];
    float* out = (float*)d_out;              // [0:81920) dcap, [81920:483328) recon

    static float *p_masked = nullptr, *p_r1 = nullptr, *p_r2 = nullptr;
    static float *g_cwT_p = nullptr;
    static bool attrs_set = false;
    if (!p_masked) {
        cudaGetSymbolAddress((void**)&p_masked, g_masked);
        cudaGetSymbolAddress((void**)&p_r1, g_r1);
        cudaGetSymbolAddress((void**)&p_r2, g_r2);
        cudaGetSymbolAddress((void**)&g_cwT_p, g_cwT);
    }
    if (!attrs_set) {
        cudaFuncSetAttribute(prim_mma_kernel, cudaFuncAttributeMaxDynamicSharedMemorySize,
                             PRIM_SMEM);
        cudaFuncSetAttribute(conv1_mma_kernel, cudaFuncAttributeMaxDynamicSharedMemorySize,
                             C1_SMEM);
        cudaFuncSetAttribute(cc_votes_kernel, cudaFuncAttributeMaxDynamicSharedMemorySize,
                             (16384 + 12800) * 4);
        attrs_set = true;
    }

    // weight prep
    prepack_W<<<(25 * 4 * 256 * 64 + 255) / 256, 256>>>(prim_w);
    prepack_c1<<<(256 * 96 + 255) / 256, 256>>>(conv1_w);
    transpose_oc<<<200, 256>>>(conv_w, g_cwT_p, 256, 200);

    // conv1 + relu via tensor cores (2-product split, writes bf16 hi/lo pixel-major)
    conv1_mma_kernel<<<1600, 512, C1_SMEM>>>(x, conv1_b);

    // primary caps conv via mma.sync (2-product split) + fused squash
    prim_mma_kernel<<<256, 512, PRIM_SMEM>>>(prim_bias);

    // conv caps votes (smem-staged weights)
    cc_votes_kernel<<<512, 256, (16384 + 12800) * 4>>>();

    // conv caps routing
    cc_routing_kernel<<<2048, 256>>>(conv_bias);

    // digit caps
    digit_kernel<<<512, 256>>>(digit_w, digit_bias, y, out);

    // FC reconstruction chain
    fc_kernel<1><<<dim3(8, 8), 256>>>(p_masked, fc1_w, fc1_b, p_r1, 512, 160, 512);
    fc_kernel<1><<<dim3(16, 8), 256>>>(p_r1, fc2_w, fc2_b, p_r2, 512, 512, 1024);
    fc_kernel<2><<<dim3(13, 8), 256>>>(p_r2, fc3_w, fc3_b, out + 81920, 512, 1024, 784);
}

// round 14
// speedup vs baseline: 1.5873x; 1.1724x over previous
#include <cuda_runtime.h>
#include <cuda_bf16.h>
#include <math.h>
#include <stdint.h>

// ---------------- problem constants ----------------
#define BATCH 512
#define NPRIM 32
#define NCLASS 10

// ---------------- scratch (static device memory; no allocs allowed) ----------------
// conv1 output as bf16 hi/lo split, layout [b][pixel(400)][ic(256)]
__device__ __align__(256) unsigned short g_h1h[BATCH * 400 * 256];   // 100 MB
__device__ __align__(256) unsigned short g_h1l[BATCH * 400 * 256];   // 100 MB
// prim weights prepacked: [kpos25][chunk4][oc256][ic64] bf16 hi
__device__ __align__(256) unsigned short g_Wph[25 * 4 * 256 * 64];   // 3.3 MB
// conv1 weights prepacked: [oc256][k96] bf16 hi
__device__ __align__(256) unsigned short g_c1Wh[256 * 96];
// conv-caps weights prepacked: [chunk4][oc256][k64] bf16 (k = kpos*8+c, pad >=200)
__device__ __align__(256) unsigned short g_cWb[4 * 256 * 64];
// primary caps activations bf16 hi/lo, layout [b][pix64][i32][c8]
__device__ __align__(256) unsigned short g_pbh[BATCH * 64 * 32 * 8]; // 16.8 MB
__device__ __align__(256) unsigned short g_pbl[BATCH * 64 * 32 * 8]; // 16.8 MB
__device__ float g_votes2[BATCH * 4 * 32 * 256];         // [b][pos][i][oc]
__device__ float g_c[BATCH * 32 * 8 * 4];                // [b][o][a][pos]
__device__ float g_masked[BATCH * 160];
__device__ float g_r1[BATCH * 512];
__device__ float g_r2[BATCH * 1024];

// ---------------- cp.async helpers ----------------
__device__ __forceinline__ void cp16(void* smem, const void* g) {
    unsigned s;
    asm("{ .reg .u64 t; cvta.to.shared.u64 t, %1; cvt.u32.u64 %0, t; }"
        : "=r"(s) : "l"(smem));
    asm volatile("cp.async.cg.shared.global [%0], [%1], 16;" :: "r"(s), "l"(g));
}
// zero-fill variant: src-size 0 -> 16B of zeros
__device__ __forceinline__ void cp16z(void* smem, const void* g, int valid) {
    unsigned s;
    asm("{ .reg .u64 t; cvta.to.shared.u64 t, %1; cvt.u32.u64 %0, t; }"
        : "=r"(s) : "l"(smem));
    asm volatile("cp.async.cg.shared.global [%0], [%1], 16, %2;"
        :: "r"(s), "l"(g), "r"(valid ? 16 : 0));
}
__device__ __forceinline__ void cp_commit() { asm volatile("cp.async.commit_group;"); }
__device__ __forceinline__ void cp_wait0() {
    asm volatile("cp.async.wait_group 0;" ::: "memory");
}

// ---------------- mma.sync bf16 + ldmatrix (sm_80+ legacy tensor path) ----------------
__device__ __forceinline__ void mma_bf16(float* d, const uint32_t* a, uint32_t b0,
                                         uint32_t b1) {
    asm volatile(
        "mma.sync.aligned.m16n8k16.row.col.f32.bf16.bf16.f32 "
        "{%0,%1,%2,%3}, {%4,%5,%6,%7}, {%8,%9}, {%0,%1,%2,%3};"
        : "+f"(d[0]), "+f"(d[1]), "+f"(d[2]), "+f"(d[3])
        : "r"(a[0]), "r"(a[1]), "r"(a[2]), "r"(a[3]), "r"(b0), "r"(b1));
}
__device__ __forceinline__ void ldm_x4(uint32_t* r, uint32_t addr) {
    asm volatile("ldmatrix.sync.aligned.m8n8.x4.shared.b16 {%0,%1,%2,%3}, [%4];"
        : "=r"(r[0]), "=r"(r[1]), "=r"(r[2]), "=r"(r[3]) : "r"(addr));
}
__device__ __forceinline__ uint32_t smem_u32(const void* p) {
    uint32_t a;
    asm("{ .reg .u64 t; cvta.to.shared.u64 t, %1; cvt.u32.u64 %0, t; }" : "=r"(a) : "l"(p));
    return a;
}
__device__ __forceinline__ uint32_t pack_bf16x2(float v0, float v1) {
    __nv_bfloat16 h0 = __float2bfloat16(v0);
    __nv_bfloat16 h1 = __float2bfloat16(v1);
    return (uint32_t)__bfloat16_as_ushort(h0) | ((uint32_t)__bfloat16_as_ushort(h1) << 16);
}

// ---------------- prepack prim weights: [kpos][chunk][oc][ic64] bf16 hi ---------------
__global__ void prepack_W(const float* __restrict__ w) {
    int idx = blockIdx.x * 256 + threadIdx.x;
    if (idx >= 25 * 4 * 256 * 64) return;
    int ic = idx & 63;
    int oc = (idx >> 6) & 255;
    int chunk = (idx >> 14) & 3;
    int kpos = idx >> 16;
    float v = w[oc * 6400 + (chunk * 64 + ic) * 25 + kpos];
    g_Wph[idx] = __bfloat16_as_ushort(__float2bfloat16(v));
}

// ---------------- prepack conv1 weights: [oc256][k96] bf16 hi --------------------------
__global__ void prepack_c1(const float* __restrict__ w) {
    int idx = blockIdx.x * 256 + threadIdx.x;
    if (idx >= 256 * 96) return;
    int k = idx % 96, oc = idx / 96;
    float v = (k < 81) ? w[oc * 81 + k] : 0.f;
    g_c1Wh[idx] = __bfloat16_as_ushort(__float2bfloat16(v));
}

// ---------------- prepack conv-caps weights: [chunk4][oc256][k64] bf16 ----------------
// k in chunk: global kk = chunk*64 + j; kpos = kk>>3, c = kk&7; valid kpos<25
__global__ void prepack_cc(const float* __restrict__ w) {
    int idx = blockIdx.x * 256 + threadIdx.x;
    if (idx >= 4 * 256 * 64) return;
    int j = idx & 63;
    int oc = (idx >> 6) & 255;
    int q = idx >> 14;
    int kk = q * 64 + j;
    int kpos = kk >> 3, c = kk & 7;
    float v = (kpos < 25) ? w[oc * 200 + c * 25 + kpos] : 0.f;
    g_cWb[idx] = __bfloat16_as_ushort(__float2bfloat16(v));
}

// ---------------- conv1 via mma.sync: M=512*400 rows, N=256 ch, K=96 (81 taps) --------
#define C1P 208
#define C1_IMG 0
#define C1_AH 6400
#define C1_AL (C1_AH + 128 * C1P)      // 33024
#define C1_BH (C1_AL + 128 * C1P)      // 59648
#define C1_SMEM (C1_BH + 256 * C1P)    // 112896

__global__ __launch_bounds__(512, 1) void conv1_mma_kernel(
    const float* __restrict__ x, const float* __restrict__ bias) {
    extern __shared__ char c1s[];
    int tid = threadIdx.x;
    int blk = blockIdx.x;
    int r0 = blk * 128;
    int b0 = r0 / 400;

    for (int i = 0; i < 6; i++) {
        int q = tid + i * 512;
        int row = q / 12, seg = q % 12;
        cp16(c1s + C1_BH + row * C1P + seg * 16, &g_c1Wh[row * 96 + seg * 8]);
    }
    cp_commit();

    float* img = (float*)(c1s + C1_IMG);
    int b1 = (r0 + 127) / 400;
    for (int i = tid; i < 784; i += 512) {
        img[i] = x[(size_t)b0 * 784 + i];
        img[784 + i] = (b1 != b0) ? x[(size_t)b1 * 784 + i] : 0.f;
    }
    __syncthreads();

    uint32_t* ah = (uint32_t*)(c1s + C1_AH);
    uint32_t* al = (uint32_t*)(c1s + C1_AL);
#pragma unroll
    for (int i = 0; i < 12; i++) {
        int w = tid + i * 512;
        int r = w / 48, cw = w % 48;
        int R = r0 + r;
        int b = R / 400, pos = R - b * 400;
        int y = pos / 20, xx = pos - y * 20;
        const float* ip = img + (b - b0) * 784;
        float v[2];
#pragma unroll
        for (int h = 0; h < 2; h++) {
            int c = cw * 2 + h;
            float val = 0.f;
            if (c < 81) {
                int kh = c / 9, kw = c - kh * 9;
                val = ip[(y + kh) * 28 + xx + kw];
            }
            v[h] = val;
        }
        __nv_bfloat16 h0 = __float2bfloat16(v[0]);
        __nv_bfloat16 h1 = __float2bfloat16(v[1]);
        float l0 = v[0] - __bfloat162float(h0);
        float l1 = v[1] - __bfloat162float(h1);
        int off = (r * C1P >> 2) + cw;
        ah[off] = (uint32_t)__bfloat16_as_ushort(h0) |
                  ((uint32_t)__bfloat16_as_ushort(h1) << 16);
        al[off] = pack_bf16x2(l0, l1);
    }
    cp_wait0();
    __syncthreads();

    int wid = tid >> 5, lane = tid & 31;
    int g = lane >> 2, c = lane & 3;
    int warpM = wid & 1;
    int warpN = wid >> 1;
    uint32_t sbase = smem_u32(c1s);
    uint32_t aBase = sbase + C1_AH +
                     (uint32_t)(warpM * 64 + (lane & 15)) * C1P + ((lane >> 4) << 4);
    uint32_t bBase = sbase + C1_BH +
                     (uint32_t)(warpN * 32 + (lane & 7) + ((lane & 16) >> 1)) * C1P +
                     ((lane & 8) ? 16u : 0u);

    float acc[4][4][4];
#pragma unroll
    for (int mt = 0; mt < 4; mt++)
#pragma unroll
        for (int j = 0; j < 4; j++)
#pragma unroll
            for (int q = 0; q < 4; q++) acc[mt][j][q] = 0.f;

#pragma unroll
    for (int kk = 0; kk < 6; kk++) {
        uint32_t bh[2][4];
#pragma unroll
        for (int np = 0; np < 2; np++)
            ldm_x4(bh[np], bBase + np * (16 * C1P) + kk * 32);
#pragma unroll
        for (int mt = 0; mt < 4; mt++) {
            uint32_t ahf[4], alf[4];
            ldm_x4(ahf, aBase + mt * (16 * C1P) + kk * 32);
            ldm_x4(alf, aBase + (C1_AL - C1_AH) + mt * (16 * C1P) + kk * 32);
#pragma unroll
            for (int np = 0; np < 2; np++)
#pragma unroll
                for (int nt = 0; nt < 2; nt++)
                    mma_bf16(acc[mt][np * 2 + nt], ahf, bh[np][nt * 2], bh[np][nt * 2 + 1]);
#pragma unroll
            for (int np = 0; np < 2; np++)
#pragma unroll
                for (int nt = 0; nt < 2; nt++)
                    mma_bf16(acc[mt][np * 2 + nt], alf, bh[np][nt * 2], bh[np][nt * 2 + 1]);
        }
    }

#pragma unroll
    for (int mt = 0; mt < 4; mt++) {
        int R1 = r0 + warpM * 64 + mt * 16 + g;
        int R2 = R1 + 8;
#pragma unroll
        for (int j = 0; j < 4; j++) {
            int ch = warpN * 32 + j * 8 + 2 * c;
            float bv0 = __ldg(&bias[ch]);
            float bv1 = __ldg(&bias[ch + 1]);
            float v0 = acc[mt][j][0] + bv0; v0 = v0 > 0.f ? v0 : 0.f;
            float v1 = acc[mt][j][1] + bv1; v1 = v1 > 0.f ? v1 : 0.f;
            float v2 = acc[mt][j][2] + bv0; v2 = v2 > 0.f ? v2 : 0.f;
            float v3 = acc[mt][j][3] + bv1; v3 = v3 > 0.f ? v3 : 0.f;
            __nv_bfloat16 h0 = __float2bfloat16(v0);
            __nv_bfloat16 h1 = __float2bfloat16(v1);
            __nv_bfloat16 h2 = __float2bfloat16(v2);
            __nv_bfloat16 h3 = __float2bfloat16(v3);
            uint32_t hw1 = (uint32_t)__bfloat16_as_ushort(h0) |
                           ((uint32_t)__bfloat16_as_ushort(h1) << 16);
            uint32_t hw2 = (uint32_t)__bfloat16_as_ushort(h2) |
                           ((uint32_t)__bfloat16_as_ushort(h3) << 16);
            uint32_t lw1 = pack_bf16x2(v0 - __bfloat162float(h0), v1 - __bfloat162float(h1));
            uint32_t lw2 = pack_bf16x2(v2 - __bfloat162float(h2), v3 - __bfloat162float(h3));
            size_t o1 = ((size_t)R1 * 256 + ch) >> 1;
            size_t o2 = ((size_t)R2 * 256 + ch) >> 1;
            ((uint32_t*)g_h1h)[o1] = hw1;
            ((uint32_t*)g_h1l)[o1] = lw1;
            ((uint32_t*)g_h1h)[o2] = hw2;
            ((uint32_t*)g_h1l)[o2] = lw2;
        }
    }
}

// ---------------- primary caps conv via mma.sync + ldmatrix (2-product, 1 sync/step) --
#define PITCH 144
#define OFF_AH 0
#define OFF_AL 18432                   // 128*144
#define OFF_BH 36864
#define PBUF 73728                     // OFF_BH + 256*144
#define PRIM_SMEM (2 * PBUF)           // 147456

extern __shared__ char psmem[];

__device__ __forceinline__ void prim_load_step(int buf, int s, int tid, int b0) {
    int kpos = s >> 2, chunk = s & 3;
    int kh = kpos / 5, kw = kpos - kh * 5;
    char* base = psmem + buf * PBUF;
#pragma unroll
    for (int ii = 0; ii < 2; ii++) {
        int i = tid + ii * 512;
        int r = i >> 3, seg = i & 7;
        int batch = r >> 6, pos = r & 63;
        int y = pos >> 3, xx = pos & 7;
        int pix = (2 * y + kh) * 20 + 2 * xx + kw;
        size_t src = ((size_t)(b0 + batch) * 400 + pix) * 256 + chunk * 64 + seg * 8;
        char* d = base + r * PITCH + seg * 16;
        cp16(d + OFF_AH, &g_h1h[src]);
        cp16(d + OFF_AL, &g_h1l[src]);
    }
    size_t wbase = (size_t)s * 16384;
#pragma unroll
    for (int ii = 0; ii < 4; ii++) {
        int i = tid + ii * 512;
        int r = i >> 3, seg = i & 7;
        cp16(base + OFF_BH + r * PITCH + seg * 16, &g_Wph[wbase + r * 64 + seg * 8]);
    }
}

__global__ __launch_bounds__(512, 1) void prim_mma_kernel(const float* __restrict__ prim_bias) {
    int tid = threadIdx.x;
    int b0 = blockIdx.x * 2;
    int wid = tid >> 5, lane = tid & 31;
    int g = lane >> 2, c = lane & 3;
    int warpM = wid & 1;
    int warpN = wid >> 1;

    uint32_t sbase = smem_u32(psmem);
    uint32_t aOff = (uint32_t)(warpM * 64 + (lane & 15)) * PITCH + ((lane >> 4) << 4);
    uint32_t bRow = (uint32_t)(warpN * 32 + (lane & 7) + ((lane & 16) >> 1));
    uint32_t bOff = bRow * PITCH + ((lane & 8) ? 16u : 0u);

    float acc[4][4][4];
#pragma unroll
    for (int mt = 0; mt < 4; mt++)
#pragma unroll
        for (int j = 0; j < 4; j++)
#pragma unroll
            for (int q = 0; q < 4; q++) acc[mt][j][q] = 0.f;

    prim_load_step(0, 0, tid, b0);
    cp_commit();

    for (int s = 0; s < 100; s++) {
        int buf = s & 1;
        cp_wait0();
        __syncthreads();
        if (s + 1 < 100) {
            prim_load_step(buf ^ 1, s + 1, tid, b0);
            cp_commit();
        }
        uint32_t tbase = sbase + buf * PBUF;
        uint32_t aBase = tbase + OFF_AH + aOff;
        uint32_t bBase = tbase + OFF_BH + bOff;
#pragma unroll
        for (int kk = 0; kk < 4; kk++) {
            uint32_t bh[2][4];
#pragma unroll
            for (int np = 0; np < 2; np++)
                ldm_x4(bh[np], bBase + np * (16 * PITCH) + kk * 32);
#pragma unroll
            for (int mt = 0; mt < 4; mt++) {
                uint32_t ah[4], al[4];
                ldm_x4(ah, aBase + mt * (16 * PITCH) + kk * 32);
                ldm_x4(al, aBase + (OFF_AL - OFF_AH) + mt * (16 * PITCH) + kk * 32);
#pragma unroll
                for (int np = 0; np < 2; np++)
#pragma unroll
                    for (int nt = 0; nt < 2; nt++)
                        mma_bf16(acc[mt][np * 2 + nt], ah, bh[np][nt * 2], bh[np][nt * 2 + 1]);
#pragma unroll
                for (int np = 0; np < 2; np++)
#pragma unroll
                    for (int nt = 0; nt < 2; nt++)
                        mma_bf16(acc[mt][np * 2 + nt], al, bh[np][nt * 2], bh[np][nt * 2 + 1]);
            }
        }
    }

    // fused epilogue: route=1/32, +bias, squash; store bf16 hi/lo [b][pix][i][c]
    int b_ = b0 + warpM;
#pragma unroll
    for (int mt = 0; mt < 4; mt++) {
        int pos1 = mt * 16 + g;
        int pos2 = pos1 + 8;
#pragma unroll
        for (int j = 0; j < 4; j++) {
            int caps = warpN * 4 + j;
            float bv0 = __ldg(&prim_bias[caps * 8 + 2 * c]);
            float bv1 = __ldg(&prim_bias[caps * 8 + 2 * c + 1]);
            float v0 = acc[mt][j][0] * (1.f / 32.f) + bv0;
            float v1 = acc[mt][j][1] * (1.f / 32.f) + bv1;
            float v2 = acc[mt][j][2] * (1.f / 32.f) + bv0;
            float v3 = acc[mt][j][3] * (1.f / 32.f) + bv1;
            float na = v0 * v0 + v1 * v1;
            float nb = v2 * v2 + v3 * v3;
            na += __shfl_xor_sync(0xFFFFFFFFu, na, 1);
            na += __shfl_xor_sync(0xFFFFFFFFu, na, 2);
            nb += __shfl_xor_sync(0xFFFFFFFFu, nb, 1);
            nb += __shfl_xor_sync(0xFFFFFFFFu, nb, 2);
            float fa = (na / (1.f + na)) * rsqrtf(na + 1e-8f);
            float fb = (nb / (1.f + nb)) * rsqrtf(nb + 1e-8f);
            float s0 = v0 * fa, s1 = v1 * fa, s2 = v2 * fb, s3 = v3 * fb;
            __nv_bfloat16 h0 = __float2bfloat16(s0);
            __nv_bfloat16 h1 = __float2bfloat16(s1);
            __nv_bfloat16 h2 = __float2bfloat16(s2);
            __nv_bfloat16 h3 = __float2bfloat16(s3);
            size_t i1 = (((size_t)b_ * 64 + pos1) * 32 + caps) * 8 + 2 * c;
            size_t i2 = (((size_t)b_ * 64 + pos2) * 32 + caps) * 8 + 2 * c;
            ((uint32_t*)g_pbh)[i1 >> 1] =
                (uint32_t)__bfloat16_as_ushort(h0) | ((uint32_t)__bfloat16_as_ushort(h1) << 16);
            ((uint32_t*)g_pbl)[i1 >> 1] =
                pack_bf16x2(s0 - __bfloat162float(h0), s1 - __bfloat162float(h1));
            ((uint32_t*)g_pbh)[i2 >> 1] =
                (uint32_t)__bfloat16_as_ushort(h2) | ((uint32_t)__bfloat16_as_ushort(h3) << 16);
            ((uint32_t*)g_pbl)[i2 >> 1] =
                pack_bf16x2(s2 - __bfloat162float(h2), s3 - __bfloat162float(h3));
        }
    }
}

// ---------------- conv-caps votes via mma.sync: M=128 (4pos x 32i), N=256, K=4x64 -----
#define V_AH 0
#define V_AL 18432
#define V_BH 36864
#define VBUF 73728
#define V_SMEM (2 * VBUF)

__device__ __forceinline__ void cc_load_step(char* vs, int buf, int q, int tid, int b) {
    char* base = vs + buf * VBUF;
    // A: 128 rows (pos*32+i) x 8 segs (kpos within chunk), 16B (8 c) each
#pragma unroll
    for (int ii = 0; ii < 2; ii++) {
        int idx = tid + ii * 512;
        int r = idx >> 3, seg = idx & 7;
        int pos = r >> 5, i = r & 31;
        int kpos = q * 8 + seg;
        int kh = kpos / 5, kw = kpos - kh * 5;
        int oy = pos >> 1, ox = pos & 1;
        int pix = (2 * oy + kh) * 8 + 2 * ox + kw;
        size_t src = (((size_t)b * 64 + pix) * 32 + i) * 8;
        int valid = (kpos < 25);
        char* d = base + r * PITCH + seg * 16;
        cp16z(d + V_AH, &g_pbh[src], valid);
        cp16z(d + V_AL, &g_pbl[src], valid);
    }
    // B: 256 rows (oc) x 8 segs from g_cWb[q]
    size_t wbase = (size_t)q * 16384;
#pragma unroll
    for (int ii = 0; ii < 4; ii++) {
        int idx = tid + ii * 512;
        int r = idx >> 3, seg = idx & 7;
        cp16(base + V_BH + r * PITCH + seg * 16, &g_cWb[wbase + r * 64 + seg * 8]);
    }
}

__global__ __launch_bounds__(512, 1) void cc_votes_mma_kernel() {
    extern __shared__ char vsm[];
    int tid = threadIdx.x;
    int b = blockIdx.x;
    int wid = tid >> 5, lane = tid & 31;
    int g = lane >> 2, c = lane & 3;
    int warpM = wid & 1;
    int warpN = wid >> 1;

    uint32_t sbase = smem_u32(vsm);
    uint32_t aOff = (uint32_t)(warpM * 64 + (lane & 15)) * PITCH + ((lane >> 4) << 4);
    uint32_t bRow = (uint32_t)(warpN * 32 + (lane & 7) + ((lane & 16) >> 1));
    uint32_t bOff = bRow * PITCH + ((lane & 8) ? 16u : 0u);

    float acc[4][4][4];
#pragma unroll
    for (int mt = 0; mt < 4; mt++)
#pragma unroll
        for (int j = 0; j < 4; j++)
#pragma unroll
            for (int q = 0; q < 4; q++) acc[mt][j][q] = 0.f;

    cc_load_step(vsm, 0, 0, tid, b);
    cp_commit();

    for (int s = 0; s < 4; s++) {
        int buf = s & 1;
        cp_wait0();
        __syncthreads();
        if (s + 1 < 4) {
            cc_load_step(vsm, buf ^ 1, s + 1, tid, b);
            cp_commit();
        }
        uint32_t tbase = sbase + buf * VBUF;
        uint32_t aBase = tbase + V_AH + aOff;
        uint32_t bBase = tbase + V_BH + bOff;
#pragma unroll
        for (int kk = 0; kk < 4; kk++) {
            uint32_t bh[2][4];
#pragma unroll
            for (int np = 0; np < 2; np++)
                ldm_x4(bh[np], bBase + np * (16 * PITCH) + kk * 32);
#pragma unroll
            for (int mt = 0; mt < 4; mt++) {
                uint32_t ah[4], al[4];
                ldm_x4(ah, aBase + mt * (16 * PITCH) + kk * 32);
                ldm_x4(al, aBase + (V_AL - V_AH) + mt * (16 * PITCH) + kk * 32);
#pragma unroll
                for (int np = 0; np < 2; np++)
#pragma unroll
                    for (int nt = 0; nt < 2; nt++)
                        mma_bf16(acc[mt][np * 2 + nt], ah, bh[np][nt * 2], bh[np][nt * 2 + 1]);
#pragma unroll
                for (int np = 0; np < 2; np++)
#pragma unroll
                    for (int nt = 0; nt < 2; nt++)
                        mma_bf16(acc[mt][np * 2 + nt], al, bh[np][nt * 2], bh[np][nt * 2 + 1]);
            }
        }
    }

    // epilogue: store votes fp32 to g_votes2[(b*4+pos)*32+i][oc]
#pragma unroll
    for (int mt = 0; mt < 4; mt++) {
        int r1 = warpM * 64 + mt * 16 + g;
        int r2 = r1 + 8;
#pragma unroll
        for (int j = 0; j < 4; j++) {
            int col = warpN * 32 + j * 8 + 2 * c;
            size_t d1 = ((size_t)(b * 4 + (r1 >> 5)) * 32 + (r1 & 31)) * 256 + col;
            size_t d2 = ((size_t)(b * 4 + (r2 >> 5)) * 32 + (r2 & 31)) * 256 + col;
            *(float2*)&g_votes2[d1] = make_float2(acc[mt][j][0], acc[mt][j][1]);
            *(float2*)&g_votes2[d2] = make_float2(acc[mt][j][2], acc[mt][j][3]);
        }
    }
}

// ---------------- conv-caps routing (3 iters) ----------------
__global__ __launch_bounds__(256) void cc_routing_kernel(const float* __restrict__ conv_bias) {
    __shared__ float sv[8192];
    __shared__ float slog[1024];
    __shared__ float sroute[1024];
    __shared__ float spre[256];
    __shared__ float sact[256];
    int blk = blockIdx.x;
    int b = blk >> 2, pos = blk & 3;
    int tid = threadIdx.x;
    for (int idx = tid; idx < 8192; idx += 256)
        sv[idx] = g_votes2[(b * 4 + pos) * 8192 + idx];
    for (int e = tid; e < 1024; e += 256) slog[e] = 0.f;
    __syncthreads();

    for (int it = 0; it < 3; it++) {
        if (tid < 32) {
            int i = tid;
            float m = slog[i * 32];
            for (int o = 1; o < 32; o++) m = fmaxf(m, slog[i * 32 + o]);
            float z = 0.f;
            for (int o = 0; o < 32; o++) {
                float e = expf(slog[i * 32 + o] - m);
                sroute[i * 32 + o] = e;
                z += e;
            }
            float inv = 1.f / z;
            for (int o = 0; o < 32; o++) sroute[i * 32 + o] *= inv;
        }
        __syncthreads();
        {
            int o = tid >> 3, a = tid & 7;
            float s = conv_bias[o * 8 + a];
            for (int i = 0; i < 32; i++)
                s += sroute[i * 32 + o] * sv[(i * 32 + o) * 8 + a];
            spre[tid] = s;
        }
        __syncthreads();
        {
            int o = tid >> 3;
            float n2 = 0.f;
#pragma unroll
            for (int a = 0; a < 8; a++) { float v = spre[o * 8 + a]; n2 += v * v; }
            float f = (n2 / (1.f + n2)) * rsqrtf(n2 + 1e-8f);
            sact[tid] = spre[tid] * f;
        }
        __syncthreads();
        if (it < 2) {
            for (int e = tid; e < 1024; e += 256) {
                int o = e & 31;
                float d = 0.f;
#pragma unroll
                for (int a = 0; a < 8; a++) d += sv[e * 8 + a] * sact[o * 8 + a];
                slog[e] += d;
            }
            __syncthreads();
        }
    }
    {
        int o = tid >> 3, a = tid & 7;
        g_c[((b * 32 + o) * 8 + a) * 4 + pos] = sact[tid];
    }
}

// NOTE: routing consumes votes in [i][o][a] order via sv[(i*32+o)*8+a]; g_votes2 layout
// is [pos][i][oc] with oc = o*8+a, so sv index (i*32+o)*8+a == i*256 + o*8 + a. Same.

// ---------------- digit caps: votes + routing + mask ----------------
__global__ __launch_bounds__(256) void digit_kernel(
    const float* __restrict__ digit_w, const float* __restrict__ digit_bias,
    const float* __restrict__ y, float* __restrict__ out_dcap) {
    __shared__ float smem[11264];
    float* sc = smem;
    float* sdw = smem + 1024;
    float* sv = smem + 6144;
    int b = blockIdx.x, tid = threadIdx.x;
    for (int idx = tid; idx < 1024; idx += 256) sc[idx] = g_c[b * 1024 + idx];
    for (int idx = tid; idx < 5120; idx += 256) sdw[idx] = digit_w[idx];
    __syncthreads();
    for (int idx = tid; idx < 5120; idx += 256) {
        int i = idx / 160, oa = idx % 160;
        float s = 0.f;
        const float* ci = &sc[i * 32];
        const float* wv = &sdw[oa * 32];
#pragma unroll
        for (int z = 0; z < 32; z++) s += ci[z] * wv[z];
        sv[(i * 10 + (oa >> 4)) * 16 + (oa & 15)] = s;
    }
    __syncthreads();
    float* slog = smem;
    float* sroute = smem + 320;
    float* spre = smem + 640;
    float* sact = smem + 800;
    float* sbias = smem + 960;
    for (int e = tid; e < 320; e += 256) slog[e] = 0.f;
    if (tid < 160) sbias[tid] = digit_bias[tid];
    __syncthreads();

    for (int it = 0; it < 3; it++) {
        if (tid < 32) {
            int i = tid;
            float m = slog[i * 10];
            for (int o = 1; o < 10; o++) m = fmaxf(m, slog[i * 10 + o]);
            float z = 0.f;
            for (int o = 0; o < 10; o++) {
                float e = expf(slog[i * 10 + o] - m);
                sroute[i * 10 + o] = e;
                z += e;
            }
            float inv = 1.f / z;
            for (int o = 0; o < 10; o++) sroute[i * 10 + o] *= inv;
        }
        __syncthreads();
        if (tid < 160) {
            int o = tid >> 4, a = tid & 15;
            float s = sbias[tid];
            for (int i = 0; i < 32; i++)
                s += sroute[i * 10 + o] * sv[(i * 10 + o) * 16 + a];
            spre[tid] = s;
        }
        __syncthreads();
        if (tid < 160) {
            int o = tid >> 4;
            float n2 = 0.f;
#pragma unroll
            for (int a = 0; a < 16; a++) { float v = spre[o * 16 + a]; n2 += v * v; }
            float f = (n2 / (1.f + n2)) * rsqrtf(n2 + 1e-8f);
            sact[tid] = spre[tid] * f;
        }
        __syncthreads();
        if (it < 2) {
            for (int e = tid; e < 320; e += 256) {
                int o = e % 10;
                float d = 0.f;
#pragma unroll
                for (int a = 0; a < 16; a++) d += sv[e * 16 + a] * sact[o * 16 + a];
                slog[e] += d;
            }
            __syncthreads();
        }
    }
    if (tid < 160) {
        int o = tid >> 4;
        float v = sact[tid];
        out_dcap[b * 160 + tid] = v;
        g_masked[b * 160 + tid] = v * y[b * 10 + o];
    }
}

// ---------------- FC: C = act(A @ W + bias) ----------------
template <int ACT>
__global__ __launch_bounds__(256) void fc_kernel(
    const float* __restrict__ A, const float* __restrict__ W,
    const float* __restrict__ bias, float* __restrict__ C,
    int M, int K, int N) {
    __shared__ float As[16][64];
    __shared__ float Ws[16][64];
    int m0 = blockIdx.y * 64, n0 = blockIdx.x * 64;
    int tid = threadIdx.x;
    int tr = tid >> 4, tc = tid & 15;
    float acc[4][4];
#pragma unroll
    for (int i = 0; i < 4; i++)
#pragma unroll
        for (int j = 0; j < 4; j++) acc[i][j] = 0.f;

    for (int k0 = 0; k0 < K; k0 += 16) {
        for (int l = tid; l < 1024; l += 256) {
            int ml = l >> 4, kl = l & 15;
            As[kl][ml] = A[(m0 + ml) * K + k0 + kl];
        }
        for (int l = tid; l < 1024; l += 256) {
            int kl = l >> 6, nl = l & 63;
            int n = n0 + nl;
            Ws[kl][nl] = (n < N) ? W[(k0 + kl) * N + n] : 0.f;
        }
        __syncthreads();
#pragma unroll
        for (int kk = 0; kk < 16; kk++) {
            float4 a4 = *(const float4*)&As[kk][tr * 4];
            float4 b4 = *(const float4*)&Ws[kk][tc * 4];
            float av[4] = {a4.x, a4.y, a4.z, a4.w};
            float bv[4] = {b4.x, b4.y, b4.z, b4.w};
#pragma unroll
            for (int i = 0; i < 4; i++)
#pragma unroll
                for (int j = 0; j < 4; j++) acc[i][j] += av[i] * bv[j];
        }
        __syncthreads();
    }
#pragma unroll
    for (int i = 0; i < 4; i++) {
        int m = m0 + tr * 4 + i;
#pragma unroll
        for (int j = 0; j < 4; j++) {
            int n = n0 + tc * 4 + j;
            if (n < N) {
                float v = acc[i][j] + bias[n];
                if (ACT == 1) v = v > 0.f ? v : 0.f;
                if (ACT == 2) v = 1.f / (1.f + expf(-v));
                C[m * N + n] = v;
            }
        }
    }
}

// ---------------- launcher ----------------
extern "C" void kernel_launch(void* const* d_in, const int* in_sizes, int n_in,
                              void* d_out, int out_size) {
    const float* x = (const float*)d_in[0];
    const float* y = (const float*)d_in[1];
    const float* conv1_w = (const float*)d_in[2];
    const float* conv1_b = (const float*)d_in[3];
    const float* prim_w = (const float*)d_in[4];
    const float* prim_bias = (const float*)d_in[5];
    const float* conv_w = (const float*)d_in[6];
    const float* conv_bias = (const float*)d_in[7];
    const float* digit_w = (const float*)d_in[8];
    const float* digit_bias = (const float*)d_in[9];
    const float* fc1_w = (const float*)d_in[10];
    const float* fc1_b = (const float*)d_in[11];
    const float* fc2_w = (const float*)d_in[12];
    const float* fc2_b = (const float*)d_in[13];
    const float* fc3_w = (const float*)d_in[14];
    const float* fc3_b = (const float*)d_in[15];
    float* out = (float*)d_out;              // [0:81920) dcap, [81920:483328) recon

    static float *p_masked = nullptr, *p_r1 = nullptr, *p_r2 = nullptr;
    static bool attrs_set = false;
    if (!p_masked) {
        cudaGetSymbolAddress((void**)&p_masked, g_masked);
        cudaGetSymbolAddress((void**)&p_r1, g_r1);
        cudaGetSymbolAddress((void**)&p_r2, g_r2);
    }
    if (!attrs_set) {
        cudaFuncSetAttribute(prim_mma_kernel, cudaFuncAttributeMaxDynamicSharedMemorySize,
                             PRIM_SMEM);
        cudaFuncSetAttribute(conv1_mma_kernel, cudaFuncAttributeMaxDynamicSharedMemorySize,
                             C1_SMEM);
        cudaFuncSetAttribute(cc_votes_mma_kernel, cudaFuncAttributeMaxDynamicSharedMemorySize,
                             V_SMEM);
        attrs_set = true;
    }

    // weight prep
    prepack_W<<<(25 * 4 * 256 * 64 + 255) / 256, 256>>>(prim_w);
    prepack_c1<<<(256 * 96 + 255) / 256, 256>>>(conv1_w);
    prepack_cc<<<(4 * 256 * 64 + 255) / 256, 256>>>(conv_w);

    // conv1 + relu via tensor cores (writes bf16 hi/lo pixel-major)
    conv1_mma_kernel<<<1600, 512, C1_SMEM>>>(x, conv1_b);

    // primary caps conv via mma.sync + fused squash (writes bf16 hi/lo [b][pix][i][c])
    prim_mma_kernel<<<256, 512, PRIM_SMEM>>>(prim_bias);

    // conv caps votes via mma.sync
    cc_votes_mma_kernel<<<512, 512, V_SMEM>>>();

    // conv caps routing
    cc_routing_kernel<<<2048, 256>>>(conv_bias);

    // digit caps
    digit_kernel<<<512, 256>>>(digit_w, digit_bias, y, out);

    // FC reconstruction chain
    fc_kernel<1><<<dim3(8, 8), 256>>>(p_masked, fc1_w, fc1_b, p_r1, 512, 160, 512);
    fc_kernel<1><<<dim3(16, 8), 256>>>(p_r1, fc2_w, fc2_b, p_r2, 512, 512, 1024);
    fc_kernel<2><<<dim3(13, 8), 256>>>(p_r2, fc3_w, fc3_b, out + 81920, 512, 1024, 784);
}

// round 15
// speedup vs baseline: 1.8388x; 1.1585x over previous
#include <cuda_runtime.h>
#include <cuda_bf16.h>
#include <math.h>
#include <stdint.h>

// ---------------- problem constants ----------------
#define BATCH 512
#define NPRIM 32
#define NCLASS 10

// ---------------- scratch (static device memory; no allocs allowed) ----------------
__device__ __align__(256) unsigned short g_h1h[BATCH * 400 * 256];   // 100 MB
__device__ __align__(256) unsigned short g_h1l[BATCH * 400 * 256];   // 100 MB
__device__ __align__(256) unsigned short g_Wph[25 * 4 * 256 * 64];   // 3.3 MB
__device__ __align__(256) unsigned short g_c1Wh[256 * 96];
__device__ __align__(256) unsigned short g_cWb[4 * 256 * 64];
// primary caps activations bf16 hi/lo, layout [b][pix64][i32][c8]
__device__ __align__(256) unsigned short g_pbh[BATCH * 64 * 32 * 8]; // 16.8 MB
__device__ __align__(256) unsigned short g_pbl[BATCH * 64 * 32 * 8]; // 16.8 MB
// FC weights prepacked: [ktile][n_pad][k64] bf16
__device__ __align__(256) unsigned short g_fw1[3 * 512 * 64];
__device__ __align__(256) unsigned short g_fw2[8 * 1024 * 64];
__device__ __align__(256) unsigned short g_fw3[16 * 1024 * 64];
__device__ float g_votes2[BATCH * 4 * 32 * 256];         // [b][pos][i][oc]
__device__ float g_c[BATCH * 32 * 8 * 4];                // [b][o][a][pos]
__device__ float g_masked[BATCH * 160];
__device__ float g_r1[BATCH * 512];
__device__ float g_r2[BATCH * 1024];

// ---------------- cp.async helpers ----------------
__device__ __forceinline__ void cp16(void* smem, const void* g) {
    unsigned s;
    asm("{ .reg .u64 t; cvta.to.shared.u64 t, %1; cvt.u32.u64 %0, t; }"
        : "=r"(s) : "l"(smem));
    asm volatile("cp.async.cg.shared.global [%0], [%1], 16;" :: "r"(s), "l"(g));
}
__device__ __forceinline__ void cp16z(void* smem, const void* g, int valid) {
    unsigned s;
    asm("{ .reg .u64 t; cvta.to.shared.u64 t, %1; cvt.u32.u64 %0, t; }"
        : "=r"(s) : "l"(smem));
    asm volatile("cp.async.cg.shared.global [%0], [%1], 16, %2;"
        :: "r"(s), "l"(g), "r"(valid ? 16 : 0));
}
__device__ __forceinline__ void cp_commit() { asm volatile("cp.async.commit_group;"); }
__device__ __forceinline__ void cp_wait0() {
    asm volatile("cp.async.wait_group 0;" ::: "memory");
}

// ---------------- mma.sync bf16 + ldmatrix (sm_80+ legacy tensor path) ----------------
__device__ __forceinline__ void mma_bf16(float* d, const uint32_t* a, uint32_t b0,
                                         uint32_t b1) {
    asm volatile(
        "mma.sync.aligned.m16n8k16.row.col.f32.bf16.bf16.f32 "
        "{%0,%1,%2,%3}, {%4,%5,%6,%7}, {%8,%9}, {%0,%1,%2,%3};"
        : "+f"(d[0]), "+f"(d[1]), "+f"(d[2]), "+f"(d[3])
        : "r"(a[0]), "r"(a[1]), "r"(a[2]), "r"(a[3]), "r"(b0), "r"(b1));
}
__device__ __forceinline__ void ldm_x4(uint32_t* r, uint32_t addr) {
    asm volatile("ldmatrix.sync.aligned.m8n8.x4.shared.b16 {%0,%1,%2,%3}, [%4];"
        : "=r"(r[0]), "=r"(r[1]), "=r"(r[2]), "=r"(r[3]) : "r"(addr));
}
__device__ __forceinline__ uint32_t smem_u32(const void* p) {
    uint32_t a;
    asm("{ .reg .u64 t; cvta.to.shared.u64 t, %1; cvt.u32.u64 %0, t; }" : "=r"(a) : "l"(p));
    return a;
}
__device__ __forceinline__ uint32_t pack_bf16x2(float v0, float v1) {
    __nv_bfloat16 h0 = __float2bfloat16(v0);
    __nv_bfloat16 h1 = __float2bfloat16(v1);
    return (uint32_t)__bfloat16_as_ushort(h0) | ((uint32_t)__bfloat16_as_ushort(h1) << 16);
}

// ---------------- prepacks ----------------
__global__ void prepack_W(const float* __restrict__ w) {
    int idx = blockIdx.x * 256 + threadIdx.x;
    if (idx >= 25 * 4 * 256 * 64) return;
    int ic = idx & 63;
    int oc = (idx >> 6) & 255;
    int chunk = (idx >> 14) & 3;
    int kpos = idx >> 16;
    float v = w[oc * 6400 + (chunk * 64 + ic) * 25 + kpos];
    g_Wph[idx] = __bfloat16_as_ushort(__float2bfloat16(v));
}
__global__ void prepack_c1(const float* __restrict__ w) {
    int idx = blockIdx.x * 256 + threadIdx.x;
    if (idx >= 256 * 96) return;
    int k = idx % 96, oc = idx / 96;
    float v = (k < 81) ? w[oc * 81 + k] : 0.f;
    g_c1Wh[idx] = __bfloat16_as_ushort(__float2bfloat16(v));
}
__global__ void prepack_cc(const float* __restrict__ w) {
    int idx = blockIdx.x * 256 + threadIdx.x;
    if (idx >= 4 * 256 * 64) return;
    int j = idx & 63;
    int oc = (idx >> 6) & 255;
    int q = idx >> 14;
    int kk = q * 64 + j;
    int kpos = kk >> 3, c = kk & 7;
    float v = (kpos < 25) ? w[oc * 200 + c * 25 + kpos] : 0.f;
    g_cWb[idx] = __bfloat16_as_ushort(__float2bfloat16(v));
}
// FC weights: W [K_real x N_real] row-major -> dst[q][n][j] = W[q*64+j][n] (0 pad)
__global__ void prepack_fc(const float* __restrict__ w, unsigned short* __restrict__ dst,
                           int K_real, int N_real, int N_pad, int total) {
    int idx = blockIdx.x * 256 + threadIdx.x;
    if (idx >= total) return;
    int j = idx & 63;
    int n = (idx >> 6) % N_pad;
    int q = idx / (N_pad * 64);
    int k = q * 64 + j;
    float v = (k < K_real && n < N_real) ? w[k * N_real + n] : 0.f;
    dst[idx] = __bfloat16_as_ushort(__float2bfloat16(v));
}

// ---------------- conv1 via mma.sync: M=512*400 rows, N=256 ch, K=96 (81 taps) --------
#define C1P 208
#define C1_IMG 0
#define C1_AH 6400
#define C1_AL (C1_AH + 128 * C1P)
#define C1_BH (C1_AL + 128 * C1P)
#define C1_SMEM (C1_BH + 256 * C1P)    // 112896

__global__ __launch_bounds__(512, 1) void conv1_mma_kernel(
    const float* __restrict__ x, const float* __restrict__ bias) {
    extern __shared__ char c1s[];
    int tid = threadIdx.x;
    int blk = blockIdx.x;
    int r0 = blk * 128;
    int b0 = r0 / 400;

    for (int i = 0; i < 6; i++) {
        int q = tid + i * 512;
        int row = q / 12, seg = q % 12;
        cp16(c1s + C1_BH + row * C1P + seg * 16, &g_c1Wh[row * 96 + seg * 8]);
    }
    cp_commit();

    float* img = (float*)(c1s + C1_IMG);
    int b1 = (r0 + 127) / 400;
    for (int i = tid; i < 784; i += 512) {
        img[i] = x[(size_t)b0 * 784 + i];
        img[784 + i] = (b1 != b0) ? x[(size_t)b1 * 784 + i] : 0.f;
    }
    __syncthreads();

    uint32_t* ah = (uint32_t*)(c1s + C1_AH);
    uint32_t* al = (uint32_t*)(c1s + C1_AL);
#pragma unroll
    for (int i = 0; i < 12; i++) {
        int w = tid + i * 512;
        int r = w / 48, cw = w % 48;
        int R = r0 + r;
        int b = R / 400, pos = R - b * 400;
        int y = pos / 20, xx = pos - y * 20;
        const float* ip = img + (b - b0) * 784;
        float v[2];
#pragma unroll
        for (int h = 0; h < 2; h++) {
            int c = cw * 2 + h;
            float val = 0.f;
            if (c < 81) {
                int kh = c / 9, kw = c - kh * 9;
                val = ip[(y + kh) * 28 + xx + kw];
            }
            v[h] = val;
        }
        __nv_bfloat16 h0 = __float2bfloat16(v[0]);
        __nv_bfloat16 h1 = __float2bfloat16(v[1]);
        float l0 = v[0] - __bfloat162float(h0);
        float l1 = v[1] - __bfloat162float(h1);
        int off = (r * C1P >> 2) + cw;
        ah[off] = (uint32_t)__bfloat16_as_ushort(h0) |
                  ((uint32_t)__bfloat16_as_ushort(h1) << 16);
        al[off] = pack_bf16x2(l0, l1);
    }
    cp_wait0();
    __syncthreads();

    int wid = tid >> 5, lane = tid & 31;
    int g = lane >> 2, c = lane & 3;
    int warpM = wid & 1;
    int warpN = wid >> 1;
    uint32_t sbase = smem_u32(c1s);
    uint32_t aBase = sbase + C1_AH +
                     (uint32_t)(warpM * 64 + (lane & 15)) * C1P + ((lane >> 4) << 4);
    uint32_t bBase = sbase + C1_BH +
                     (uint32_t)(warpN * 32 + (lane & 7) + ((lane & 16) >> 1)) * C1P +
                     ((lane & 8) ? 16u : 0u);

    float acc[4][4][4];
#pragma unroll
    for (int mt = 0; mt < 4; mt++)
#pragma unroll
        for (int j = 0; j < 4; j++)
#pragma unroll
            for (int q = 0; q < 4; q++) acc[mt][j][q] = 0.f;

#pragma unroll
    for (int kk = 0; kk < 6; kk++) {
        uint32_t bh[2][4];
#pragma unroll
        for (int np = 0; np < 2; np++)
            ldm_x4(bh[np], bBase + np * (16 * C1P) + kk * 32);
#pragma unroll
        for (int mt = 0; mt < 4; mt++) {
            uint32_t ahf[4], alf[4];
            ldm_x4(ahf, aBase + mt * (16 * C1P) + kk * 32);
            ldm_x4(alf, aBase + (C1_AL - C1_AH) + mt * (16 * C1P) + kk * 32);
#pragma unroll
            for (int np = 0; np < 2; np++)
#pragma unroll
                for (int nt = 0; nt < 2; nt++)
                    mma_bf16(acc[mt][np * 2 + nt], ahf, bh[np][nt * 2], bh[np][nt * 2 + 1]);
#pragma unroll
            for (int np = 0; np < 2; np++)
#pragma unroll
                for (int nt = 0; nt < 2; nt++)
                    mma_bf16(acc[mt][np * 2 + nt], alf, bh[np][nt * 2], bh[np][nt * 2 + 1]);
        }
    }

#pragma unroll
    for (int mt = 0; mt < 4; mt++) {
        int R1 = r0 + warpM * 64 + mt * 16 + g;
        int R2 = R1 + 8;
#pragma unroll
        for (int j = 0; j < 4; j++) {
            int ch = warpN * 32 + j * 8 + 2 * c;
            float bv0 = __ldg(&bias[ch]);
            float bv1 = __ldg(&bias[ch + 1]);
            float v0 = acc[mt][j][0] + bv0; v0 = v0 > 0.f ? v0 : 0.f;
            float v1 = acc[mt][j][1] + bv1; v1 = v1 > 0.f ? v1 : 0.f;
            float v2 = acc[mt][j][2] + bv0; v2 = v2 > 0.f ? v2 : 0.f;
            float v3 = acc[mt][j][3] + bv1; v3 = v3 > 0.f ? v3 : 0.f;
            __nv_bfloat16 h0 = __float2bfloat16(v0);
            __nv_bfloat16 h1 = __float2bfloat16(v1);
            __nv_bfloat16 h2 = __float2bfloat16(v2);
            __nv_bfloat16 h3 = __float2bfloat16(v3);
            uint32_t hw1 = (uint32_t)__bfloat16_as_ushort(h0) |
                           ((uint32_t)__bfloat16_as_ushort(h1) << 16);
            uint32_t hw2 = (uint32_t)__bfloat16_as_ushort(h2) |
                           ((uint32_t)__bfloat16_as_ushort(h3) << 16);
            uint32_t lw1 = pack_bf16x2(v0 - __bfloat162float(h0), v1 - __bfloat162float(h1));
            uint32_t lw2 = pack_bf16x2(v2 - __bfloat162float(h2), v3 - __bfloat162float(h3));
            size_t o1 = ((size_t)R1 * 256 + ch) >> 1;
            size_t o2 = ((size_t)R2 * 256 + ch) >> 1;
            ((uint32_t*)g_h1h)[o1] = hw1;
            ((uint32_t*)g_h1l)[o1] = lw1;
            ((uint32_t*)g_h1h)[o2] = hw2;
            ((uint32_t*)g_h1l)[o2] = lw2;
        }
    }
}

// ---------------- primary caps conv via mma.sync + ldmatrix (2-product, 1 sync/step) --
#define PITCH 144
#define OFF_AH 0
#define OFF_AL 18432
#define OFF_BH 36864
#define PBUF 73728
#define PRIM_SMEM (2 * PBUF)           // 147456

extern __shared__ char psmem[];

__device__ __forceinline__ void prim_load_step(int buf, int s, int tid, int b0) {
    int kpos = s >> 2, chunk = s & 3;
    int kh = kpos / 5, kw = kpos - kh * 5;
    char* base = psmem + buf * PBUF;
#pragma unroll
    for (int ii = 0; ii < 2; ii++) {
        int i = tid + ii * 512;
        int r = i >> 3, seg = i & 7;
        int batch = r >> 6, pos = r & 63;
        int y = pos >> 3, xx = pos & 7;
        int pix = (2 * y + kh) * 20 + 2 * xx + kw;
        size_t src = ((size_t)(b0 + batch) * 400 + pix) * 256 + chunk * 64 + seg * 8;
        char* d = base + r * PITCH + seg * 16;
        cp16(d + OFF_AH, &g_h1h[src]);
        cp16(d + OFF_AL, &g_h1l[src]);
    }
    size_t wbase = (size_t)s * 16384;
#pragma unroll
    for (int ii = 0; ii < 4; ii++) {
        int i = tid + ii * 512;
        int r = i >> 3, seg = i & 7;
        cp16(base + OFF_BH + r * PITCH + seg * 16, &g_Wph[wbase + r * 64 + seg * 8]);
    }
}

__global__ __launch_bounds__(512, 1) void prim_mma_kernel(const float* __restrict__ prim_bias) {
    int tid = threadIdx.x;
    int b0 = blockIdx.x * 2;
    int wid = tid >> 5, lane = tid & 31;
    int g = lane >> 2, c = lane & 3;
    int warpM = wid & 1;
    int warpN = wid >> 1;

    uint32_t sbase = smem_u32(psmem);
    uint32_t aOff = (uint32_t)(warpM * 64 + (lane & 15)) * PITCH + ((lane >> 4) << 4);
    uint32_t bRow = (uint32_t)(warpN * 32 + (lane & 7) + ((lane & 16) >> 1));
    uint32_t bOff = bRow * PITCH + ((lane & 8) ? 16u : 0u);

    float acc[4][4][4];
#pragma unroll
    for (int mt = 0; mt < 4; mt++)
#pragma unroll
        for (int j = 0; j < 4; j++)
#pragma unroll
            for (int q = 0; q < 4; q++) acc[mt][j][q] = 0.f;

    prim_load_step(0, 0, tid, b0);
    cp_commit();

    for (int s = 0; s < 100; s++) {
        int buf = s & 1;
        cp_wait0();
        __syncthreads();
        if (s + 1 < 100) {
            prim_load_step(buf ^ 1, s + 1, tid, b0);
            cp_commit();
        }
        uint32_t tbase = sbase + buf * PBUF;
        uint32_t aBase = tbase + OFF_AH + aOff;
        uint32_t bBase = tbase + OFF_BH + bOff;
#pragma unroll
        for (int kk = 0; kk < 4; kk++) {
            uint32_t bh[2][4];
#pragma unroll
            for (int np = 0; np < 2; np++)
                ldm_x4(bh[np], bBase + np * (16 * PITCH) + kk * 32);
#pragma unroll
            for (int mt = 0; mt < 4; mt++) {
                uint32_t ah[4], al[4];
                ldm_x4(ah, aBase + mt * (16 * PITCH) + kk * 32);
                ldm_x4(al, aBase + (OFF_AL - OFF_AH) + mt * (16 * PITCH) + kk * 32);
#pragma unroll
                for (int np = 0; np < 2; np++)
#pragma unroll
                    for (int nt = 0; nt < 2; nt++)
                        mma_bf16(acc[mt][np * 2 + nt], ah, bh[np][nt * 2], bh[np][nt * 2 + 1]);
#pragma unroll
                for (int np = 0; np < 2; np++)
#pragma unroll
                    for (int nt = 0; nt < 2; nt++)
                        mma_bf16(acc[mt][np * 2 + nt], al, bh[np][nt * 2], bh[np][nt * 2 + 1]);
            }
        }
    }

    int b_ = b0 + warpM;
#pragma unroll
    for (int mt = 0; mt < 4; mt++) {
        int pos1 = mt * 16 + g;
        int pos2 = pos1 + 8;
#pragma unroll
        for (int j = 0; j < 4; j++) {
            int caps = warpN * 4 + j;
            float bv0 = __ldg(&prim_bias[caps * 8 + 2 * c]);
            float bv1 = __ldg(&prim_bias[caps * 8 + 2 * c + 1]);
            float v0 = acc[mt][j][0] * (1.f / 32.f) + bv0;
            float v1 = acc[mt][j][1] * (1.f / 32.f) + bv1;
            float v2 = acc[mt][j][2] * (1.f / 32.f) + bv0;
            float v3 = acc[mt][j][3] * (1.f / 32.f) + bv1;
            float na = v0 * v0 + v1 * v1;
            float nb = v2 * v2 + v3 * v3;
            na += __shfl_xor_sync(0xFFFFFFFFu, na, 1);
            na += __shfl_xor_sync(0xFFFFFFFFu, na, 2);
            nb += __shfl_xor_sync(0xFFFFFFFFu, nb, 1);
            nb += __shfl_xor_sync(0xFFFFFFFFu, nb, 2);
            float fa = (na / (1.f + na)) * rsqrtf(na + 1e-8f);
            float fb = (nb / (1.f + nb)) * rsqrtf(nb + 1e-8f);
            float s0 = v0 * fa, s1 = v1 * fa, s2 = v2 * fb, s3 = v3 * fb;
            __nv_bfloat16 h0 = __float2bfloat16(s0);
            __nv_bfloat16 h1 = __float2bfloat16(s1);
            __nv_bfloat16 h2 = __float2bfloat16(s2);
            __nv_bfloat16 h3 = __float2bfloat16(s3);
            size_t i1 = (((size_t)b_ * 64 + pos1) * 32 + caps) * 8 + 2 * c;
            size_t i2 = (((size_t)b_ * 64 + pos2) * 32 + caps) * 8 + 2 * c;
            ((uint32_t*)g_pbh)[i1 >> 1] =
                (uint32_t)__bfloat16_as_ushort(h0) | ((uint32_t)__bfloat16_as_ushort(h1) << 16);
            ((uint32_t*)g_pbl)[i1 >> 1] =
                pack_bf16x2(s0 - __bfloat162float(h0), s1 - __bfloat162float(h1));
            ((uint32_t*)g_pbh)[i2 >> 1] =
                (uint32_t)__bfloat16_as_ushort(h2) | ((uint32_t)__bfloat16_as_ushort(h3) << 16);
            ((uint32_t*)g_pbl)[i2 >> 1] =
                pack_bf16x2(s2 - __bfloat162float(h2), s3 - __bfloat162float(h3));
        }
    }
}

// ---------------- conv-caps votes via mma.sync: M=128 (4pos x 32i), N=256, K=4x64 -----
#define V_AH 0
#define V_AL 18432
#define V_BH 36864
#define VBUF 73728
#define V_SMEM (2 * VBUF)

__device__ __forceinline__ void cc_load_step(char* vs, int buf, int q, int tid, int b) {
    char* base = vs + buf * VBUF;
#pragma unroll
    for (int ii = 0; ii < 2; ii++) {
        int idx = tid + ii * 512;
        int r = idx >> 3, seg = idx & 7;
        int pos = r >> 5, i = r & 31;
        int kpos = q * 8 + seg;
        int kh = kpos / 5, kw = kpos - kh * 5;
        int oy = pos >> 1, ox = pos & 1;
        int pix = (2 * oy + kh) * 8 + 2 * ox + kw;
        size_t src = (((size_t)b * 64 + pix) * 32 + i) * 8;
        int valid = (kpos < 25);
        char* d = base + r * PITCH + seg * 16;
        cp16z(d + V_AH, &g_pbh[src], valid);
        cp16z(d + V_AL, &g_pbl[src], valid);
    }
    size_t wbase = (size_t)q * 16384;
#pragma unroll
    for (int ii = 0; ii < 4; ii++) {
        int idx = tid + ii * 512;
        int r = idx >> 3, seg = idx & 7;
        cp16(base + V_BH + r * PITCH + seg * 16, &g_cWb[wbase + r * 64 + seg * 8]);
    }
}

__global__ __launch_bounds__(512, 1) void cc_votes_mma_kernel() {
    extern __shared__ char vsm[];
    int tid = threadIdx.x;
    int b = blockIdx.x;
    int wid = tid >> 5, lane = tid & 31;
    int g = lane >> 2, c = lane & 3;
    int warpM = wid & 1;
    int warpN = wid >> 1;

    uint32_t sbase = smem_u32(vsm);
    uint32_t aOff = (uint32_t)(warpM * 64 + (lane & 15)) * PITCH + ((lane >> 4) << 4);
    uint32_t bRow = (uint32_t)(warpN * 32 + (lane & 7) + ((lane & 16) >> 1));
    uint32_t bOff = bRow * PITCH + ((lane & 8) ? 16u : 0u);

    float acc[4][4][4];
#pragma unroll
    for (int mt = 0; mt < 4; mt++)
#pragma unroll
        for (int j = 0; j < 4; j++)
#pragma unroll
            for (int q = 0; q < 4; q++) acc[mt][j][q] = 0.f;

    cc_load_step(vsm, 0, 0, tid, b);
    cp_commit();

    for (int s = 0; s < 4; s++) {
        int buf = s & 1;
        cp_wait0();
        __syncthreads();
        if (s + 1 < 4) {
            cc_load_step(vsm, buf ^ 1, s + 1, tid, b);
            cp_commit();
        }
        uint32_t tbase = sbase + buf * VBUF;
        uint32_t aBase = tbase + V_AH + aOff;
        uint32_t bBase = tbase + V_BH + bOff;
#pragma unroll
        for (int kk = 0; kk < 4; kk++) {
            uint32_t bh[2][4];
#pragma unroll
            for (int np = 0; np < 2; np++)
                ldm_x4(bh[np], bBase + np * (16 * PITCH) + kk * 32);
#pragma unroll
            for (int mt = 0; mt < 4; mt++) {
                uint32_t ah[4], al[4];
                ldm_x4(ah, aBase + mt * (16 * PITCH) + kk * 32);
                ldm_x4(al, aBase + (V_AL - V_AH) + mt * (16 * PITCH) + kk * 32);
#pragma unroll
                for (int np = 0; np < 2; np++)
#pragma unroll
                    for (int nt = 0; nt < 2; nt++)
                        mma_bf16(acc[mt][np * 2 + nt], ah, bh[np][nt * 2], bh[np][nt * 2 + 1]);
#pragma unroll
                for (int np = 0; np < 2; np++)
#pragma unroll
                    for (int nt = 0; nt < 2; nt++)
                        mma_bf16(acc[mt][np * 2 + nt], al, bh[np][nt * 2], bh[np][nt * 2 + 1]);
            }
        }
    }

#pragma unroll
    for (int mt = 0; mt < 4; mt++) {
        int r1 = warpM * 64 + mt * 16 + g;
        int r2 = r1 + 8;
#pragma unroll
        for (int j = 0; j < 4; j++) {
            int col = warpN * 32 + j * 8 + 2 * c;
            size_t d1 = ((size_t)(b * 4 + (r1 >> 5)) * 32 + (r1 & 31)) * 256 + col;
            size_t d2 = ((size_t)(b * 4 + (r2 >> 5)) * 32 + (r2 & 31)) * 256 + col;
            *(float2*)&g_votes2[d1] = make_float2(acc[mt][j][0], acc[mt][j][1]);
            *(float2*)&g_votes2[d2] = make_float2(acc[mt][j][2], acc[mt][j][3]);
        }
    }
}

// ---------------- conv-caps routing (3 iters) ----------------
__global__ __launch_bounds__(256) void cc_routing_kernel(const float* __restrict__ conv_bias) {
    __shared__ float sv[8192];
    __shared__ float slog[1024];
    __shared__ float sroute[1024];
    __shared__ float spre[256];
    __shared__ float sact[256];
    int blk = blockIdx.x;
    int b = blk >> 2, pos = blk & 3;
    int tid = threadIdx.x;
    for (int idx = tid; idx < 8192; idx += 256)
        sv[idx] = g_votes2[(b * 4 + pos) * 8192 + idx];
    for (int e = tid; e < 1024; e += 256) slog[e] = 0.f;
    __syncthreads();

    for (int it = 0; it < 3; it++) {
        if (tid < 32) {
            int i = tid;
            float m = slog[i * 32];
            for (int o = 1; o < 32; o++) m = fmaxf(m, slog[i * 32 + o]);
            float z = 0.f;
            for (int o = 0; o < 32; o++) {
                float e = expf(slog[i * 32 + o] - m);
                sroute[i * 32 + o] = e;
                z += e;
            }
            float inv = 1.f / z;
            for (int o = 0; o < 32; o++) sroute[i * 32 + o] *= inv;
        }
        __syncthreads();
        {
            int o = tid >> 3, a = tid & 7;
            float s = conv_bias[o * 8 + a];
            for (int i = 0; i < 32; i++)
                s += sroute[i * 32 + o] * sv[(i * 32 + o) * 8 + a];
            spre[tid] = s;
        }
        __syncthreads();
        {
            int o = tid >> 3;
            float n2 = 0.f;
#pragma unroll
            for (int a = 0; a < 8; a++) { float v = spre[o * 8 + a]; n2 += v * v; }
            float f = (n2 / (1.f + n2)) * rsqrtf(n2 + 1e-8f);
            sact[tid] = spre[tid] * f;
        }
        __syncthreads();
        if (it < 2) {
            for (int e = tid; e < 1024; e += 256) {
                int o = e & 31;
                float d = 0.f;
#pragma unroll
                for (int a = 0; a < 8; a++) d += sv[e * 8 + a] * sact[o * 8 + a];
                slog[e] += d;
            }
            __syncthreads();
        }
    }
    {
        int o = tid >> 3, a = tid & 7;
        g_c[((b * 32 + o) * 8 + a) * 4 + pos] = sact[tid];
    }
}

// ---------------- digit caps: votes + routing + mask ----------------
__global__ __launch_bounds__(256) void digit_kernel(
    const float* __restrict__ digit_w, const float* __restrict__ digit_bias,
    const float* __restrict__ y, float* __restrict__ out_dcap) {
    __shared__ float smem[11264];
    float* sc = smem;
    float* sdw = smem + 1024;
    float* sv = smem + 6144;
    int b = blockIdx.x, tid = threadIdx.x;
    for (int idx = tid; idx < 1024; idx += 256) sc[idx] = g_c[b * 1024 + idx];
    for (int idx = tid; idx < 5120; idx += 256) sdw[idx] = digit_w[idx];
    __syncthreads();
    for (int idx = tid; idx < 5120; idx += 256) {
        int i = idx / 160, oa = idx % 160;
        float s = 0.f;
        const float* ci = &sc[i * 32];
        const float* wv = &sdw[oa * 32];
#pragma unroll
        for (int z = 0; z < 32; z++) s += ci[z] * wv[z];
        sv[(i * 10 + (oa >> 4)) * 16 + (oa & 15)] = s;
    }
    __syncthreads();
    float* slog = smem;
    float* sroute = smem + 320;
    float* spre = smem + 640;
    float* sact = smem + 800;
    float* sbias = smem + 960;
    for (int e = tid; e < 320; e += 256) slog[e] = 0.f;
    if (tid < 160) sbias[tid] = digit_bias[tid];
    __syncthreads();

    for (int it = 0; it < 3; it++) {
        if (tid < 32) {
            int i = tid;
            float m = slog[i * 10];
            for (int o = 1; o < 10; o++) m = fmaxf(m, slog[i * 10 + o]);
            float z = 0.f;
            for (int o = 0; o < 10; o++) {
                float e = expf(slog[i * 10 + o] - m);
                sroute[i * 10 + o] = e;
                z += e;
            }
            float inv = 1.f / z;
            for (int o = 0; o < 10; o++) sroute[i * 10 + o] *= inv;
        }
        __syncthreads();
        if (tid < 160) {
            int o = tid >> 4, a = tid & 15;
            float s = sbias[tid];
            for (int i = 0; i < 32; i++)
                s += sroute[i * 10 + o] * sv[(i * 10 + o) * 16 + a];
            spre[tid] = s;
        }
        __syncthreads();
        if (tid < 160) {
            int o = tid >> 4;
            float n2 = 0.f;
#pragma unroll
            for (int a = 0; a < 16; a++) { float v = spre[o * 16 + a]; n2 += v * v; }
            float f = (n2 / (1.f + n2)) * rsqrtf(n2 + 1e-8f);
            sact[tid] = spre[tid] * f;
        }
        __syncthreads();
        if (it < 2) {
            for (int e = tid; e < 320; e += 256) {
                int o = e % 10;
                float d = 0.f;
#pragma unroll
                for (int a = 0; a < 16; a++) d += sv[e * 16 + a] * sact[o * 16 + a];
                slog[e] += d;
            }
            __syncthreads();
        }
    }
    if (tid < 160) {
        int o = tid >> 4;
        float v = sact[tid];
        out_dcap[b * 160 + tid] = v;
        g_masked[b * 160 + tid] = v * y[b * 10 + o];
    }
}

// ---------------- FC via mma.sync: M=512, per block 128xM, 256xN, K tiles of 64 --------
// ACT: 1=relu, 2=sigmoid. A fp32 [512 x K_real], B prepacked [q][n_pad][k64] bf16.
#define F_AH 0
#define F_AL 18432
#define F_BH 36864
#define F_SMEM 73728

template <int ACT>
__global__ __launch_bounds__(512, 1) void fc_mma_kernel(
    const float* __restrict__ A, const unsigned short* __restrict__ Bw,
    const float* __restrict__ bias, float* __restrict__ C,
    int K_real, int KT, int N_pad, int N_real) {
    extern __shared__ char fsm[];
    int tid = threadIdx.x;
    int n0 = blockIdx.x * 256;
    int m0 = blockIdx.y * 128;
    int wid = tid >> 5, lane = tid & 31;
    int g = lane >> 2, c = lane & 3;
    int warpM = wid & 1;
    int warpN = wid >> 1;

    uint32_t sbase = smem_u32(fsm);
    uint32_t aBase = sbase + F_AH +
                     (uint32_t)(warpM * 64 + (lane & 15)) * PITCH + ((lane >> 4) << 4);
    uint32_t bBase = sbase + F_BH +
                     (uint32_t)(warpN * 32 + (lane & 7) + ((lane & 16) >> 1)) * PITCH +
                     ((lane & 8) ? 16u : 0u);
    uint32_t* ah = (uint32_t*)(fsm + F_AH);
    uint32_t* al = (uint32_t*)(fsm + F_AL);

    float acc[4][4][4];
#pragma unroll
    for (int mt = 0; mt < 4; mt++)
#pragma unroll
        for (int j = 0; j < 4; j++)
#pragma unroll
            for (int q = 0; q < 4; q++) acc[mt][j][q] = 0.f;

    for (int q = 0; q < KT; q++) {
        if (q > 0) __syncthreads();     // all warps done reading smem from step q-1
        // B tile via cp.async
        {
            size_t wbase = (size_t)q * N_pad * 64 + (size_t)n0 * 64;
#pragma unroll
            for (int ii = 0; ii < 4; ii++) {
                int idx = tid + ii * 512;
                int r = idx >> 3, seg = idx & 7;
                cp16(fsm + F_BH + r * PITCH + seg * 16, &Bw[wbase + r * 64 + seg * 8]);
            }
            cp_commit();
        }
        // A tile: fp32 -> bf16 hi/lo split into smem
#pragma unroll
        for (int ii = 0; ii < 8; ii++) {
            int idx = tid + ii * 512;   // 0..4095: 128 rows x 32 words
            int r = idx >> 5, cw = idx & 31;
            int k0 = q * 64 + cw * 2;
            const float* src = &A[(size_t)(m0 + r) * K_real + k0];
            float v0 = (k0 < K_real) ? src[0] : 0.f;
            float v1 = (k0 + 1 < K_real) ? src[1] : 0.f;
            __nv_bfloat16 h0 = __float2bfloat16(v0);
            __nv_bfloat16 h1 = __float2bfloat16(v1);
            int off = r * (PITCH >> 2) + cw;
            ah[off] = (uint32_t)__bfloat16_as_ushort(h0) |
                      ((uint32_t)__bfloat16_as_ushort(h1) << 16);
            al[off] = pack_bf16x2(v0 - __bfloat162float(h0), v1 - __bfloat162float(h1));
        }
        cp_wait0();
        __syncthreads();
#pragma unroll
        for (int kk = 0; kk < 4; kk++) {
            uint32_t bh[2][4];
#pragma unroll
            for (int np = 0; np < 2; np++)
                ldm_x4(bh[np], bBase + np * (16 * PITCH) + kk * 32);
#pragma unroll
            for (int mt = 0; mt < 4; mt++) {
                uint32_t ahf[4], alf[4];
                ldm_x4(ahf, aBase + mt * (16 * PITCH) + kk * 32);
                ldm_x4(alf, aBase + (F_AL - F_AH) + mt * (16 * PITCH) + kk * 32);
#pragma unroll
                for (int np = 0; np < 2; np++)
#pragma unroll
                    for (int nt = 0; nt < 2; nt++)
                        mma_bf16(acc[mt][np * 2 + nt], ahf, bh[np][nt * 2], bh[np][nt * 2 + 1]);
#pragma unroll
                for (int np = 0; np < 2; np++)
#pragma unroll
                    for (int nt = 0; nt < 2; nt++)
                        mma_bf16(acc[mt][np * 2 + nt], alf, bh[np][nt * 2], bh[np][nt * 2 + 1]);
            }
        }
    }

#pragma unroll
    for (int mt = 0; mt < 4; mt++) {
        int R1 = m0 + warpM * 64 + mt * 16 + g;
        int R2 = R1 + 8;
#pragma unroll
        for (int j = 0; j < 4; j++) {
            int col = n0 + warpN * 32 + j * 8 + 2 * c;
            if (col >= N_real) continue;
            float bv0 = __ldg(&bias[col]);
            float bv1 = __ldg(&bias[col + 1]);
            float v0 = acc[mt][j][0] + bv0;
            float v1 = acc[mt][j][1] + bv1;
            float v2 = acc[mt][j][2] + bv0;
            float v3 = acc[mt][j][3] + bv1;
            if (ACT == 1) {
                v0 = v0 > 0.f ? v0 : 0.f; v1 = v1 > 0.f ? v1 : 0.f;
                v2 = v2 > 0.f ? v2 : 0.f; v3 = v3 > 0.f ? v3 : 0.f;
            } else {
                v0 = 1.f / (1.f + expf(-v0)); v1 = 1.f / (1.f + expf(-v1));
                v2 = 1.f / (1.f + expf(-v2)); v3 = 1.f / (1.f + expf(-v3));
            }
            *(float2*)&C[(size_t)R1 * N_real + col] = make_float2(v0, v1);
            *(float2*)&C[(size_t)R2 * N_real + col] = make_float2(v2, v3);
        }
    }
}

// ---------------- launcher ----------------
extern "C" void kernel_launch(void* const* d_in, const int* in_sizes, int n_in,
                              void* d_out, int out_size) {
    const float* x = (const float*)d_in[0];
    const float* y = (const float*)d_in[1];
    const float* conv1_w = (const float*)d_in[2];
    const float* conv1_b = (const float*)d_in[3];
    const float* prim_w = (const float*)d_in[4];
    const float* prim_bias = (const float*)d_in[5];
    const float* conv_w = (const float*)d_in[6];
    const float* conv_bias = (const float*)d_in[7];
    const float* digit_w = (const float*)d_in[8];
    const float* digit_bias = (const float*)d_in[9];
    const float* fc1_w = (const float*)d_in[10];
    const float* fc1_b = (const float*)d_in[11];
    const float* fc2_w = (const float*)d_in[12];
    const float* fc2_b = (const float*)d_in[13];
    const float* fc3_w = (const float*)d_in[14];
    const float* fc3_b = (const float*)d_in[15];
    float* out = (float*)d_out;              // [0:81920) dcap, [81920:483328) recon

    static float *p_masked = nullptr, *p_r1 = nullptr, *p_r2 = nullptr;
    static unsigned short *p_fw1 = nullptr, *p_fw2 = nullptr, *p_fw3 = nullptr;
    static bool attrs_set = false;
    if (!p_masked) {
        cudaGetSymbolAddress((void**)&p_masked, g_masked);
        cudaGetSymbolAddress((void**)&p_r1, g_r1);
        cudaGetSymbolAddress((void**)&p_r2, g_r2);
        cudaGetSymbolAddress((void**)&p_fw1, g_fw1);
        cudaGetSymbolAddress((void**)&p_fw2, g_fw2);
        cudaGetSymbolAddress((void**)&p_fw3, g_fw3);
    }
    if (!attrs_set) {
        cudaFuncSetAttribute(prim_mma_kernel, cudaFuncAttributeMaxDynamicSharedMemorySize,
                             PRIM_SMEM);
        cudaFuncSetAttribute(conv1_mma_kernel, cudaFuncAttributeMaxDynamicSharedMemorySize,
                             C1_SMEM);
        cudaFuncSetAttribute(cc_votes_mma_kernel, cudaFuncAttributeMaxDynamicSharedMemorySize,
                             V_SMEM);
        cudaFuncSetAttribute(fc_mma_kernel<1>, cudaFuncAttributeMaxDynamicSharedMemorySize,
                             F_SMEM);
        cudaFuncSetAttribute(fc_mma_kernel<2>, cudaFuncAttributeMaxDynamicSharedMemorySize,
                             F_SMEM);
        attrs_set = true;
    }

    // weight prep
    prepack_W<<<(25 * 4 * 256 * 64 + 255) / 256, 256>>>(prim_w);
    prepack_c1<<<(256 * 96 + 255) / 256, 256>>>(conv1_w);
    prepack_cc<<<(4 * 256 * 64 + 255) / 256, 256>>>(conv_w);
    prepack_fc<<<(3 * 512 * 64 + 255) / 256, 256>>>(fc1_w, p_fw1, 160, 512, 512,
                                                    3 * 512 * 64);
    prepack_fc<<<(8 * 1024 * 64 + 255) / 256, 256>>>(fc2_w, p_fw2, 512, 1024, 1024,
                                                     8 * 1024 * 64);
    prepack_fc<<<(16 * 1024 * 64 + 255) / 256, 256>>>(fc3_w, p_fw3, 1024, 784, 1024,
                                                      16 * 1024 * 64);

    // conv1 + relu via tensor cores
    conv1_mma_kernel<<<1600, 512, C1_SMEM>>>(x, conv1_b);

    // primary caps conv via mma.sync + fused squash
    prim_mma_kernel<<<256, 512, PRIM_SMEM>>>(prim_bias);

    // conv caps votes via mma.sync
    cc_votes_mma_kernel<<<512, 512, V_SMEM>>>();

    // conv caps routing
    cc_routing_kernel<<<2048, 256>>>(conv_bias);

    // digit caps
    digit_kernel<<<512, 256>>>(digit_w, digit_bias, y, out);

    // FC reconstruction chain via mma.sync
    fc_mma_kernel<1><<<dim3(2, 4), 512, F_SMEM>>>(p_masked, p_fw1, fc1_b, p_r1,
                                                  160, 3, 512, 512);
    fc_mma_kernel<1><<<dim3(4, 4), 512, F_SMEM>>>(p_r1, p_fw2, fc2_b, p_r2,
                                                  512, 8, 1024, 1024);
    fc_mma_kernel<2><<<dim3(4, 4), 512, F_SMEM>>>(p_r2, p_fw3, fc3_b, out + 81920,
                                                  1024, 16, 1024, 784);
}

// round 16
// speedup vs baseline: 1.9933x; 1.0840x over previous
#include <cuda_runtime.h>
#include <cuda_bf16.h>
#include <math.h>
#include <stdint.h>

// ---------------- problem constants ----------------
#define BATCH 512
#define NPRIM 32
#define NCLASS 10

// ---------------- scratch (static device memory; no allocs allowed) ----------------
__device__ __align__(256) unsigned short g_h1h[BATCH * 400 * 256];   // 100 MB
__device__ __align__(256) unsigned short g_h1l[BATCH * 400 * 256];   // 100 MB
__device__ __align__(256) unsigned short g_Wph[25 * 4 * 256 * 64];   // 3.3 MB
__device__ __align__(256) unsigned short g_c1Wh[256 * 96];
__device__ __align__(256) unsigned short g_cWb[4 * 256 * 64];
// primary caps activations bf16 hi/lo, layout [b][pix64][i32][c8]
__device__ __align__(256) unsigned short g_pbh[BATCH * 64 * 32 * 8]; // 16.8 MB
__device__ __align__(256) unsigned short g_pbl[BATCH * 64 * 32 * 8]; // 16.8 MB
// FC weights prepacked: [ktile][n_pad][k64] bf16
__device__ __align__(256) unsigned short g_fw1[3 * 512 * 64];
__device__ __align__(256) unsigned short g_fw2[8 * 1024 * 64];
__device__ __align__(256) unsigned short g_fw3[16 * 1024 * 64];
__device__ float g_votes2[BATCH * 4 * 32 * 256];         // [b][pos][i][oc]
__device__ float g_c[BATCH * 32 * 8 * 4];                // [b][o][a][pos]
__device__ float g_masked[BATCH * 160];
__device__ float g_r1[BATCH * 512];
__device__ float g_r2[BATCH * 1024];

// ---------------- cp.async helpers ----------------
__device__ __forceinline__ void cp16(void* smem, const void* g) {
    unsigned s;
    asm("{ .reg .u64 t; cvta.to.shared.u64 t, %1; cvt.u32.u64 %0, t; }"
        : "=r"(s) : "l"(smem));
    asm volatile("cp.async.cg.shared.global [%0], [%1], 16;" :: "r"(s), "l"(g));
}
__device__ __forceinline__ void cp16z(void* smem, const void* g, int valid) {
    unsigned s;
    asm("{ .reg .u64 t; cvta.to.shared.u64 t, %1; cvt.u32.u64 %0, t; }"
        : "=r"(s) : "l"(smem));
    asm volatile("cp.async.cg.shared.global [%0], [%1], 16, %2;"
        :: "r"(s), "l"(g), "r"(valid ? 16 : 0));
}
__device__ __forceinline__ void cp_commit() { asm volatile("cp.async.commit_group;"); }
__device__ __forceinline__ void cp_wait0() {
    asm volatile("cp.async.wait_group 0;" ::: "memory");
}

// ---------------- mma.sync bf16 + ldmatrix (sm_80+ legacy tensor path) ----------------
__device__ __forceinline__ void mma_bf16(float* d, const uint32_t* a, uint32_t b0,
                                         uint32_t b1) {
    asm volatile(
        "mma.sync.aligned.m16n8k16.row.col.f32.bf16.bf16.f32 "
        "{%0,%1,%2,%3}, {%4,%5,%6,%7}, {%8,%9}, {%0,%1,%2,%3};"
        : "+f"(d[0]), "+f"(d[1]), "+f"(d[2]), "+f"(d[3])
        : "r"(a[0]), "r"(a[1]), "r"(a[2]), "r"(a[3]), "r"(b0), "r"(b1));
}
__device__ __forceinline__ void ldm_x4(uint32_t* r, uint32_t addr) {
    asm volatile("ldmatrix.sync.aligned.m8n8.x4.shared.b16 {%0,%1,%2,%3}, [%4];"
        : "=r"(r[0]), "=r"(r[1]), "=r"(r[2]), "=r"(r[3]) : "r"(addr));
}
__device__ __forceinline__ uint32_t smem_u32(const void* p) {
    uint32_t a;
    asm("{ .reg .u64 t; cvta.to.shared.u64 t, %1; cvt.u32.u64 %0, t; }" : "=r"(a) : "l"(p));
    return a;
}
__device__ __forceinline__ uint32_t pack_bf16x2(float v0, float v1) {
    __nv_bfloat16 h0 = __float2bfloat16(v0);
    __nv_bfloat16 h1 = __float2bfloat16(v1);
    return (uint32_t)__bfloat16_as_ushort(h0) | ((uint32_t)__bfloat16_as_ushort(h1) << 16);
}

// ---------------- prepacks ----------------
__global__ void prepack_W(const float* __restrict__ w) {
    int idx = blockIdx.x * 256 + threadIdx.x;
    if (idx >= 25 * 4 * 256 * 64) return;
    int ic = idx & 63;
    int oc = (idx >> 6) & 255;
    int chunk = (idx >> 14) & 3;
    int kpos = idx >> 16;
    float v = w[oc * 6400 + (chunk * 64 + ic) * 25 + kpos];
    g_Wph[idx] = __bfloat16_as_ushort(__float2bfloat16(v));
}
__global__ void prepack_c1(const float* __restrict__ w) {
    int idx = blockIdx.x * 256 + threadIdx.x;
    if (idx >= 256 * 96) return;
    int k = idx % 96, oc = idx / 96;
    float v = (k < 81) ? w[oc * 81 + k] : 0.f;
    g_c1Wh[idx] = __bfloat16_as_ushort(__float2bfloat16(v));
}
__global__ void prepack_cc(const float* __restrict__ w) {
    int idx = blockIdx.x * 256 + threadIdx.x;
    if (idx >= 4 * 256 * 64) return;
    int j = idx & 63;
    int oc = (idx >> 6) & 255;
    int q = idx >> 14;
    int kk = q * 64 + j;
    int kpos = kk >> 3, c = kk & 7;
    float v = (kpos < 25) ? w[oc * 200 + c * 25 + kpos] : 0.f;
    g_cWb[idx] = __bfloat16_as_ushort(__float2bfloat16(v));
}
__global__ void prepack_fc(const float* __restrict__ w, unsigned short* __restrict__ dst,
                           int K_real, int N_real, int N_pad, int total) {
    int idx = blockIdx.x * 256 + threadIdx.x;
    if (idx >= total) return;
    int j = idx & 63;
    int n = (idx >> 6) % N_pad;
    int q = idx / (N_pad * 64);
    int k = q * 64 + j;
    float v = (k < K_real && n < N_real) ? w[k * N_real + n] : 0.f;
    dst[idx] = __bfloat16_as_ushort(__float2bfloat16(v));
}

// ---------------- conv1 via mma.sync: M=512*400 rows, N=256 ch, K=96 (81 taps) --------
#define C1P 208
#define C1_IMG 0
#define C1_AH 6400
#define C1_AL (C1_AH + 128 * C1P)
#define C1_BH (C1_AL + 128 * C1P)
#define C1_SMEM (C1_BH + 256 * C1P)    // 112896

__global__ __launch_bounds__(512, 1) void conv1_mma_kernel(
    const float* __restrict__ x, const float* __restrict__ bias) {
    extern __shared__ char c1s[];
    int tid = threadIdx.x;
    int blk = blockIdx.x;
    int r0 = blk * 128;
    int b0 = r0 / 400;

    for (int i = 0; i < 6; i++) {
        int q = tid + i * 512;
        int row = q / 12, seg = q % 12;
        cp16(c1s + C1_BH + row * C1P + seg * 16, &g_c1Wh[row * 96 + seg * 8]);
    }
    cp_commit();

    float* img = (float*)(c1s + C1_IMG);
    int b1 = (r0 + 127) / 400;
    for (int i = tid; i < 784; i += 512) {
        img[i] = x[(size_t)b0 * 784 + i];
        img[784 + i] = (b1 != b0) ? x[(size_t)b1 * 784 + i] : 0.f;
    }
    __syncthreads();

    uint32_t* ah = (uint32_t*)(c1s + C1_AH);
    uint32_t* al = (uint32_t*)(c1s + C1_AL);
#pragma unroll
    for (int i = 0; i < 12; i++) {
        int w = tid + i * 512;
        int r = w / 48, cw = w % 48;
        int R = r0 + r;
        int b = R / 400, pos = R - b * 400;
        int y = pos / 20, xx = pos - y * 20;
        const float* ip = img + (b - b0) * 784;
        float v[2];
#pragma unroll
        for (int h = 0; h < 2; h++) {
            int c = cw * 2 + h;
            float val = 0.f;
            if (c < 81) {
                int kh = c / 9, kw = c - kh * 9;
                val = ip[(y + kh) * 28 + xx + kw];
            }
            v[h] = val;
        }
        __nv_bfloat16 h0 = __float2bfloat16(v[0]);
        __nv_bfloat16 h1 = __float2bfloat16(v[1]);
        float l0 = v[0] - __bfloat162float(h0);
        float l1 = v[1] - __bfloat162float(h1);
        int off = (r * C1P >> 2) + cw;
        ah[off] = (uint32_t)__bfloat16_as_ushort(h0) |
                  ((uint32_t)__bfloat16_as_ushort(h1) << 16);
        al[off] = pack_bf16x2(l0, l1);
    }
    cp_wait0();
    __syncthreads();

    int wid = tid >> 5, lane = tid & 31;
    int g = lane >> 2, c = lane & 3;
    int warpM = wid & 1;
    int warpN = wid >> 1;
    uint32_t sbase = smem_u32(c1s);
    uint32_t aBase = sbase + C1_AH +
                     (uint32_t)(warpM * 64 + (lane & 15)) * C1P + ((lane >> 4) << 4);
    uint32_t bBase = sbase + C1_BH +
                     (uint32_t)(warpN * 32 + (lane & 7) + ((lane & 16) >> 1)) * C1P +
                     ((lane & 8) ? 16u : 0u);

    float acc[4][4][4];
#pragma unroll
    for (int mt = 0; mt < 4; mt++)
#pragma unroll
        for (int j = 0; j < 4; j++)
#pragma unroll
            for (int q = 0; q < 4; q++) acc[mt][j][q] = 0.f;

#pragma unroll
    for (int kk = 0; kk < 6; kk++) {
        uint32_t bh[2][4];
#pragma unroll
        for (int np = 0; np < 2; np++)
            ldm_x4(bh[np], bBase + np * (16 * C1P) + kk * 32);
#pragma unroll
        for (int mt = 0; mt < 4; mt++) {
            uint32_t ahf[4], alf[4];
            ldm_x4(ahf, aBase + mt * (16 * C1P) + kk * 32);
            ldm_x4(alf, aBase + (C1_AL - C1_AH) + mt * (16 * C1P) + kk * 32);
#pragma unroll
            for (int np = 0; np < 2; np++)
#pragma unroll
                for (int nt = 0; nt < 2; nt++)
                    mma_bf16(acc[mt][np * 2 + nt], ahf, bh[np][nt * 2], bh[np][nt * 2 + 1]);
#pragma unroll
            for (int np = 0; np < 2; np++)
#pragma unroll
                for (int nt = 0; nt < 2; nt++)
                    mma_bf16(acc[mt][np * 2 + nt], alf, bh[np][nt * 2], bh[np][nt * 2 + 1]);
        }
    }

#pragma unroll
    for (int mt = 0; mt < 4; mt++) {
        int R1 = r0 + warpM * 64 + mt * 16 + g;
        int R2 = R1 + 8;
#pragma unroll
        for (int j = 0; j < 4; j++) {
            int ch = warpN * 32 + j * 8 + 2 * c;
            float bv0 = __ldg(&bias[ch]);
            float bv1 = __ldg(&bias[ch + 1]);
            float v0 = acc[mt][j][0] + bv0; v0 = v0 > 0.f ? v0 : 0.f;
            float v1 = acc[mt][j][1] + bv1; v1 = v1 > 0.f ? v1 : 0.f;
            float v2 = acc[mt][j][2] + bv0; v2 = v2 > 0.f ? v2 : 0.f;
            float v3 = acc[mt][j][3] + bv1; v3 = v3 > 0.f ? v3 : 0.f;
            __nv_bfloat16 h0 = __float2bfloat16(v0);
            __nv_bfloat16 h1 = __float2bfloat16(v1);
            __nv_bfloat16 h2 = __float2bfloat16(v2);
            __nv_bfloat16 h3 = __float2bfloat16(v3);
            uint32_t hw1 = (uint32_t)__bfloat16_as_ushort(h0) |
                           ((uint32_t)__bfloat16_as_ushort(h1) << 16);
            uint32_t hw2 = (uint32_t)__bfloat16_as_ushort(h2) |
                           ((uint32_t)__bfloat16_as_ushort(h3) << 16);
            uint32_t lw1 = pack_bf16x2(v0 - __bfloat162float(h0), v1 - __bfloat162float(h1));
            uint32_t lw2 = pack_bf16x2(v2 - __bfloat162float(h2), v3 - __bfloat162float(h3));
            size_t o1 = ((size_t)R1 * 256 + ch) >> 1;
            size_t o2 = ((size_t)R2 * 256 + ch) >> 1;
            ((uint32_t*)g_h1h)[o1] = hw1;
            ((uint32_t*)g_h1l)[o1] = lw1;
            ((uint32_t*)g_h1h)[o2] = hw2;
            ((uint32_t*)g_h1l)[o2] = lw2;
        }
    }
}

// ---------------- primary caps conv via mma.sync + ldmatrix (2-product, 1 sync/step) --
#define PITCH 144
#define OFF_AH 0
#define OFF_AL 18432
#define OFF_BH 36864
#define PBUF 73728
#define PRIM_SMEM (2 * PBUF)           // 147456

extern __shared__ char psmem[];

__device__ __forceinline__ void prim_load_step(int buf, int s, int tid, int b0) {
    int kpos = s >> 2, chunk = s & 3;
    int kh = kpos / 5, kw = kpos - kh * 5;
    char* base = psmem + buf * PBUF;
#pragma unroll
    for (int ii = 0; ii < 2; ii++) {
        int i = tid + ii * 512;
        int r = i >> 3, seg = i & 7;
        int batch = r >> 6, pos = r & 63;
        int y = pos >> 3, xx = pos & 7;
        int pix = (2 * y + kh) * 20 + 2 * xx + kw;
        size_t src = ((size_t)(b0 + batch) * 400 + pix) * 256 + chunk * 64 + seg * 8;
        char* d = base + r * PITCH + seg * 16;
        cp16(d + OFF_AH, &g_h1h[src]);
        cp16(d + OFF_AL, &g_h1l[src]);
    }
    size_t wbase = (size_t)s * 16384;
#pragma unroll
    for (int ii = 0; ii < 4; ii++) {
        int i = tid + ii * 512;
        int r = i >> 3, seg = i & 7;
        cp16(base + OFF_BH + r * PITCH + seg * 16, &g_Wph[wbase + r * 64 + seg * 8]);
    }
}

__global__ __launch_bounds__(512, 1) void prim_mma_kernel(const float* __restrict__ prim_bias) {
    int tid = threadIdx.x;
    int b0 = blockIdx.x * 2;
    int wid = tid >> 5, lane = tid & 31;
    int g = lane >> 2, c = lane & 3;
    int warpM = wid & 1;
    int warpN = wid >> 1;

    uint32_t sbase = smem_u32(psmem);
    uint32_t aOff = (uint32_t)(warpM * 64 + (lane & 15)) * PITCH + ((lane >> 4) << 4);
    uint32_t bRow = (uint32_t)(warpN * 32 + (lane & 7) + ((lane & 16) >> 1));
    uint32_t bOff = bRow * PITCH + ((lane & 8) ? 16u : 0u);

    float acc[4][4][4];
#pragma unroll
    for (int mt = 0; mt < 4; mt++)
#pragma unroll
        for (int j = 0; j < 4; j++)
#pragma unroll
            for (int q = 0; q < 4; q++) acc[mt][j][q] = 0.f;

    prim_load_step(0, 0, tid, b0);
    cp_commit();

    for (int s = 0; s < 100; s++) {
        int buf = s & 1;
        cp_wait0();
        __syncthreads();
        if (s + 1 < 100) {
            prim_load_step(buf ^ 1, s + 1, tid, b0);
            cp_commit();
        }
        uint32_t tbase = sbase + buf * PBUF;
        uint32_t aBase = tbase + OFF_AH + aOff;
        uint32_t bBase = tbase + OFF_BH + bOff;
#pragma unroll
        for (int kk = 0; kk < 4; kk++) {
            uint32_t bh[2][4];
#pragma unroll
            for (int np = 0; np < 2; np++)
                ldm_x4(bh[np], bBase + np * (16 * PITCH) + kk * 32);
#pragma unroll
            for (int mt = 0; mt < 4; mt++) {
                uint32_t ah[4], al[4];
                ldm_x4(ah, aBase + mt * (16 * PITCH) + kk * 32);
                ldm_x4(al, aBase + (OFF_AL - OFF_AH) + mt * (16 * PITCH) + kk * 32);
#pragma unroll
                for (int np = 0; np < 2; np++)
#pragma unroll
                    for (int nt = 0; nt < 2; nt++)
                        mma_bf16(acc[mt][np * 2 + nt], ah, bh[np][nt * 2], bh[np][nt * 2 + 1]);
#pragma unroll
                for (int np = 0; np < 2; np++)
#pragma unroll
                    for (int nt = 0; nt < 2; nt++)
                        mma_bf16(acc[mt][np * 2 + nt], al, bh[np][nt * 2], bh[np][nt * 2 + 1]);
            }
        }
    }

    int b_ = b0 + warpM;
#pragma unroll
    for (int mt = 0; mt < 4; mt++) {
        int pos1 = mt * 16 + g;
        int pos2 = pos1 + 8;
#pragma unroll
        for (int j = 0; j < 4; j++) {
            int caps = warpN * 4 + j;
            float bv0 = __ldg(&prim_bias[caps * 8 + 2 * c]);
            float bv1 = __ldg(&prim_bias[caps * 8 + 2 * c + 1]);
            float v0 = acc[mt][j][0] * (1.f / 32.f) + bv0;
            float v1 = acc[mt][j][1] * (1.f / 32.f) + bv1;
            float v2 = acc[mt][j][2] * (1.f / 32.f) + bv0;
            float v3 = acc[mt][j][3] * (1.f / 32.f) + bv1;
            float na = v0 * v0 + v1 * v1;
            float nb = v2 * v2 + v3 * v3;
            na += __shfl_xor_sync(0xFFFFFFFFu, na, 1);
            na += __shfl_xor_sync(0xFFFFFFFFu, na, 2);
            nb += __shfl_xor_sync(0xFFFFFFFFu, nb, 1);
            nb += __shfl_xor_sync(0xFFFFFFFFu, nb, 2);
            float fa = (na / (1.f + na)) * rsqrtf(na + 1e-8f);
            float fb = (nb / (1.f + nb)) * rsqrtf(nb + 1e-8f);
            float s0 = v0 * fa, s1 = v1 * fa, s2 = v2 * fb, s3 = v3 * fb;
            __nv_bfloat16 h0 = __float2bfloat16(s0);
            __nv_bfloat16 h1 = __float2bfloat16(s1);
            __nv_bfloat16 h2 = __float2bfloat16(s2);
            __nv_bfloat16 h3 = __float2bfloat16(s3);
            size_t i1 = (((size_t)b_ * 64 + pos1) * 32 + caps) * 8 + 2 * c;
            size_t i2 = (((size_t)b_ * 64 + pos2) * 32 + caps) * 8 + 2 * c;
            ((uint32_t*)g_pbh)[i1 >> 1] =
                (uint32_t)__bfloat16_as_ushort(h0) | ((uint32_t)__bfloat16_as_ushort(h1) << 16);
            ((uint32_t*)g_pbl)[i1 >> 1] =
                pack_bf16x2(s0 - __bfloat162float(h0), s1 - __bfloat162float(h1));
            ((uint32_t*)g_pbh)[i2 >> 1] =
                (uint32_t)__bfloat16_as_ushort(h2) | ((uint32_t)__bfloat16_as_ushort(h3) << 16);
            ((uint32_t*)g_pbl)[i2 >> 1] =
                pack_bf16x2(s2 - __bfloat162float(h2), s3 - __bfloat162float(h3));
        }
    }
}

// ---------------- conv-caps votes via mma.sync: M=128 (4pos x 32i), N=256, K=4x64 -----
#define V_AH 0
#define V_AL 18432
#define V_BH 36864
#define VBUF 73728
#define V_SMEM (2 * VBUF)

__device__ __forceinline__ void cc_load_step(char* vs, int buf, int q, int tid, int b) {
    char* base = vs + buf * VBUF;
#pragma unroll
    for (int ii = 0; ii < 2; ii++) {
        int idx = tid + ii * 512;
        int r = idx >> 3, seg = idx & 7;
        int pos = r >> 5, i = r & 31;
        int kpos = q * 8 + seg;
        int kh = kpos / 5, kw = kpos - kh * 5;
        int oy = pos >> 1, ox = pos & 1;
        int pix = (2 * oy + kh) * 8 + 2 * ox + kw;
        size_t src = (((size_t)b * 64 + pix) * 32 + i) * 8;
        int valid = (kpos < 25);
        char* d = base + r * PITCH + seg * 16;
        cp16z(d + V_AH, &g_pbh[src], valid);
        cp16z(d + V_AL, &g_pbl[src], valid);
    }
    size_t wbase = (size_t)q * 16384;
#pragma unroll
    for (int ii = 0; ii < 4; ii++) {
        int idx = tid + ii * 512;
        int r = idx >> 3, seg = idx & 7;
        cp16(base + V_BH + r * PITCH + seg * 16, &g_cWb[wbase + r * 64 + seg * 8]);
    }
}

__global__ __launch_bounds__(512, 1) void cc_votes_mma_kernel() {
    extern __shared__ char vsm[];
    int tid = threadIdx.x;
    int b = blockIdx.x;
    int wid = tid >> 5, lane = tid & 31;
    int g = lane >> 2, c = lane & 3;
    int warpM = wid & 1;
    int warpN = wid >> 1;

    uint32_t sbase = smem_u32(vsm);
    uint32_t aOff = (uint32_t)(warpM * 64 + (lane & 15)) * PITCH + ((lane >> 4) << 4);
    uint32_t bRow = (uint32_t)(warpN * 32 + (lane & 7) + ((lane & 16) >> 1));
    uint32_t bOff = bRow * PITCH + ((lane & 8) ? 16u : 0u);

    float acc[4][4][4];
#pragma unroll
    for (int mt = 0; mt < 4; mt++)
#pragma unroll
        for (int j = 0; j < 4; j++)
#pragma unroll
            for (int q = 0; q < 4; q++) acc[mt][j][q] = 0.f;

    cc_load_step(vsm, 0, 0, tid, b);
    cp_commit();

    for (int s = 0; s < 4; s++) {
        int buf = s & 1;
        cp_wait0();
        __syncthreads();
        if (s + 1 < 4) {
            cc_load_step(vsm, buf ^ 1, s + 1, tid, b);
            cp_commit();
        }
        uint32_t tbase = sbase + buf * VBUF;
        uint32_t aBase = tbase + V_AH + aOff;
        uint32_t bBase = tbase + V_BH + bOff;
#pragma unroll
        for (int kk = 0; kk < 4; kk++) {
            uint32_t bh[2][4];
#pragma unroll
            for (int np = 0; np < 2; np++)
                ldm_x4(bh[np], bBase + np * (16 * PITCH) + kk * 32);
#pragma unroll
            for (int mt = 0; mt < 4; mt++) {
                uint32_t ah[4], al[4];
                ldm_x4(ah, aBase + mt * (16 * PITCH) + kk * 32);
                ldm_x4(al, aBase + (V_AL - V_AH) + mt * (16 * PITCH) + kk * 32);
#pragma unroll
                for (int np = 0; np < 2; np++)
#pragma unroll
                    for (int nt = 0; nt < 2; nt++)
                        mma_bf16(acc[mt][np * 2 + nt], ah, bh[np][nt * 2], bh[np][nt * 2 + 1]);
#pragma unroll
                for (int np = 0; np < 2; np++)
#pragma unroll
                    for (int nt = 0; nt < 2; nt++)
                        mma_bf16(acc[mt][np * 2 + nt], al, bh[np][nt * 2], bh[np][nt * 2 + 1]);
            }
        }
    }

#pragma unroll
    for (int mt = 0; mt < 4; mt++) {
        int r1 = warpM * 64 + mt * 16 + g;
        int r2 = r1 + 8;
#pragma unroll
        for (int j = 0; j < 4; j++) {
            int col = warpN * 32 + j * 8 + 2 * c;
            size_t d1 = ((size_t)(b * 4 + (r1 >> 5)) * 32 + (r1 & 31)) * 256 + col;
            size_t d2 = ((size_t)(b * 4 + (r2 >> 5)) * 32 + (r2 & 31)) * 256 + col;
            *(float2*)&g_votes2[d1] = make_float2(acc[mt][j][0], acc[mt][j][1]);
            *(float2*)&g_votes2[d2] = make_float2(acc[mt][j][2], acc[mt][j][3]);
        }
    }
}

// ---------------- conv-caps routing (3 iters, warp-parallel softmax + shfl squash) ----
__global__ __launch_bounds__(256) void cc_routing_kernel(const float* __restrict__ conv_bias) {
    __shared__ float sv[8192];
    __shared__ float slog[1024];
    __shared__ float sroute[1024];
    __shared__ float sact[256];
    int blk = blockIdx.x;
    int b = blk >> 2, pos = blk & 3;
    int tid = threadIdx.x;
    int warp = tid >> 5, lane = tid & 31;
    for (int idx = tid; idx < 8192; idx += 256)
        sv[idx] = g_votes2[(b * 4 + pos) * 8192 + idx];
    for (int e = tid; e < 1024; e += 256) slog[e] = 0.f;
    __syncthreads();

    int o = tid >> 3, a = tid & 7;
    float bias = conv_bias[tid];       // conv_bias[o*8+a] == conv_bias[tid]
    float act = 0.f;

    for (int it = 0; it < 3; it++) {
        // warp-parallel softmax: warp handles rows warp, warp+8, warp+16, warp+24
#pragma unroll
        for (int rr = 0; rr < 4; rr++) {
            int i = warp + rr * 8;
            float v = slog[i * 32 + lane];
            float m = v;
#pragma unroll
            for (int d = 16; d; d >>= 1) m = fmaxf(m, __shfl_xor_sync(0xFFFFFFFFu, m, d));
            float e = expf(v - m);
            float z = e;
#pragma unroll
            for (int d = 16; d; d >>= 1) z += __shfl_xor_sync(0xFFFFFFFFu, z, d);
            sroute[i * 32 + lane] = e / z;
        }
        __syncthreads();
        // preact + squash (shfl over 8-lane group = one capsule)
        float s = bias;
        for (int i = 0; i < 32; i++)
            s += sroute[i * 32 + o] * sv[(i * 32 + o) * 8 + a];
        float n2 = s * s;
        n2 += __shfl_xor_sync(0xFFFFFFFFu, n2, 1);
        n2 += __shfl_xor_sync(0xFFFFFFFFu, n2, 2);
        n2 += __shfl_xor_sync(0xFFFFFFFFu, n2, 4);
        float f = (n2 / (1.f + n2)) * rsqrtf(n2 + 1e-8f);
        act = s * f;
        sact[tid] = act;
        __syncthreads();
        if (it < 2) {
            for (int e = tid; e < 1024; e += 256) {
                int oo = e & 31;
                float d = 0.f;
#pragma unroll
                for (int aa = 0; aa < 8; aa++) d += sv[e * 8 + aa] * sact[oo * 8 + aa];
                slog[e] += d;
            }
            __syncthreads();
        }
    }
    g_c[((b * 32 + o) * 8 + a) * 4 + pos] = act;
}

// ---------------- digit caps (warp-parallel softmax + shfl squash) ----------------
__global__ __launch_bounds__(256) void digit_kernel(
    const float* __restrict__ digit_w, const float* __restrict__ digit_bias,
    const float* __restrict__ y, float* __restrict__ out_dcap) {
    __shared__ float smem[11264];
    float* sc = smem;
    float* sdw = smem + 1024;
    float* sv = smem + 6144;
    int b = blockIdx.x, tid = threadIdx.x;
    int warp = tid >> 5, lane = tid & 31;
    for (int idx = tid; idx < 1024; idx += 256) sc[idx] = g_c[b * 1024 + idx];
    for (int idx = tid; idx < 5120; idx += 256) sdw[idx] = digit_w[idx];
    __syncthreads();
    for (int idx = tid; idx < 5120; idx += 256) {
        int i = idx / 160, oa = idx % 160;
        float s = 0.f;
        const float* ci = &sc[i * 32];
        const float* wv = &sdw[oa * 32];
#pragma unroll
        for (int z = 0; z < 32; z++) s += ci[z] * wv[z];
        sv[(i * 10 + (oa >> 4)) * 16 + (oa & 15)] = s;
    }
    __syncthreads();
    float* slog = smem;
    float* sroute = smem + 320;
    float* sact = smem + 640;
    for (int e = tid; e < 320; e += 256) slog[e] = 0.f;
    __syncthreads();

    float bias = (tid < 160) ? digit_bias[tid] : 0.f;
    float act = 0.f;

    for (int it = 0; it < 3; it++) {
        // warp-parallel softmax over 10 outputs per row i (32 rows, 8 warps x 4)
#pragma unroll
        for (int rr = 0; rr < 4; rr++) {
            int i = warp + rr * 8;
            float v = (lane < 10) ? slog[i * 10 + lane] : -1e30f;
            float m = v;
#pragma unroll
            for (int d = 16; d; d >>= 1) m = fmaxf(m, __shfl_xor_sync(0xFFFFFFFFu, m, d));
            float e = (lane < 10) ? expf(v - m) : 0.f;
            float z = e;
#pragma unroll
            for (int d = 16; d; d >>= 1) z += __shfl_xor_sync(0xFFFFFFFFu, z, d);
            if (lane < 10) sroute[i * 10 + lane] = e / z;
        }
        __syncthreads();
        if (tid < 160) {   // warps 0-4 fully active
            int o = tid >> 4, a = tid & 15;
            float s = bias;
            for (int i = 0; i < 32; i++)
                s += sroute[i * 10 + o] * sv[(i * 10 + o) * 16 + a];
            float n2 = s * s;
            n2 += __shfl_xor_sync(0xFFFFFFFFu, n2, 1);
            n2 += __shfl_xor_sync(0xFFFFFFFFu, n2, 2);
            n2 += __shfl_xor_sync(0xFFFFFFFFu, n2, 4);
            n2 += __shfl_xor_sync(0xFFFFFFFFu, n2, 8);
            float f = (n2 / (1.f + n2)) * rsqrtf(n2 + 1e-8f);
            act = s * f;
            sact[tid] = act;
        }
        __syncthreads();
        if (it < 2) {
            for (int e = tid; e < 320; e += 256) {
                int o = e % 10;
                float d = 0.f;
#pragma unroll
                for (int a = 0; a < 16; a++) d += sv[e * 16 + a] * sact[o * 16 + a];
                slog[e] += d;
            }
            __syncthreads();
        }
    }
    if (tid < 160) {
        int o = tid >> 4;
        out_dcap[b * 160 + tid] = act;
        g_masked[b * 160 + tid] = act * y[b * 10 + o];
    }
}

// ---------------- FC via mma.sync: M=512, per block 128xM, 256xN, K tiles of 64 --------
#define F_AH 0
#define F_AL 18432
#define F_BH 36864
#define F_SMEM 73728

template <int ACT>
__global__ __launch_bounds__(512, 1) void fc_mma_kernel(
    const float* __restrict__ A, const unsigned short* __restrict__ Bw,
    const float* __restrict__ bias, float* __restrict__ C,
    int K_real, int KT, int N_pad, int N_real) {
    extern __shared__ char fsm[];
    int tid = threadIdx.x;
    int n0 = blockIdx.x * 256;
    int m0 = blockIdx.y * 128;
    int wid = tid >> 5, lane = tid & 31;
    int g = lane >> 2, c = lane & 3;
    int warpM = wid & 1;
    int warpN = wid >> 1;

    uint32_t sbase = smem_u32(fsm);
    uint32_t aBase = sbase + F_AH +
                     (uint32_t)(warpM * 64 + (lane & 15)) * PITCH + ((lane >> 4) << 4);
    uint32_t bBase = sbase + F_BH +
                     (uint32_t)(warpN * 32 + (lane & 7) + ((lane & 16) >> 1)) * PITCH +
                     ((lane & 8) ? 16u : 0u);
    uint32_t* ah = (uint32_t*)(fsm + F_AH);
    uint32_t* al = (uint32_t*)(fsm + F_AL);

    float acc[4][4][4];
#pragma unroll
    for (int mt = 0; mt < 4; mt++)
#pragma unroll
        for (int j = 0; j < 4; j++)
#pragma unroll
            for (int q = 0; q < 4; q++) acc[mt][j][q] = 0.f;

    for (int q = 0; q < KT; q++) {
        if (q > 0) __syncthreads();
        {
            size_t wbase = (size_t)q * N_pad * 64 + (size_t)n0 * 64;
#pragma unroll
            for (int ii = 0; ii < 4; ii++) {
                int idx = tid + ii * 512;
                int r = idx >> 3, seg = idx & 7;
                cp16(fsm + F_BH + r * PITCH + seg * 16, &Bw[wbase + r * 64 + seg * 8]);
            }
            cp_commit();
        }
#pragma unroll
        for (int ii = 0; ii < 8; ii++) {
            int idx = tid + ii * 512;
            int r = idx >> 5, cw = idx & 31;
            int k0 = q * 64 + cw * 2;
            const float* src = &A[(size_t)(m0 + r) * K_real + k0];
            float v0 = (k0 < K_real) ? src[0] : 0.f;
            float v1 = (k0 + 1 < K_real) ? src[1] : 0.f;
            __nv_bfloat16 h0 = __float2bfloat16(v0);
            __nv_bfloat16 h1 = __float2bfloat16(v1);
            int off = r * (PITCH >> 2) + cw;
            ah[off] = (uint32_t)__bfloat16_as_ushort(h0) |
                      ((uint32_t)__bfloat16_as_ushort(h1) << 16);
            al[off] = pack_bf16x2(v0 - __bfloat162float(h0), v1 - __bfloat162float(h1));
        }
        cp_wait0();
        __syncthreads();
#pragma unroll
        for (int kk = 0; kk < 4; kk++) {
            uint32_t bh[2][4];
#pragma unroll
            for (int np = 0; np < 2; np++)
                ldm_x4(bh[np], bBase + np * (16 * PITCH) + kk * 32);
#pragma unroll
            for (int mt = 0; mt < 4; mt++) {
                uint32_t ahf[4], alf[4];
                ldm_x4(ahf, aBase + mt * (16 * PITCH) + kk * 32);
                ldm_x4(alf, aBase + (F_AL - F_AH) + mt * (16 * PITCH) + kk * 32);
#pragma unroll
                for (int np = 0; np < 2; np++)
#pragma unroll
                    for (int nt = 0; nt < 2; nt++)
                        mma_bf16(acc[mt][np * 2 + nt], ahf, bh[np][nt * 2], bh[np][nt * 2 + 1]);
#pragma unroll
                for (int np = 0; np < 2; np++)
#pragma unroll
                    for (int nt = 0; nt < 2; nt++)
                        mma_bf16(acc[mt][np * 2 + nt], alf, bh[np][nt * 2], bh[np][nt * 2 + 1]);
            }
        }
    }

#pragma unroll
    for (int mt = 0; mt < 4; mt++) {
        int R1 = m0 + warpM * 64 + mt * 16 + g;
        int R2 = R1 + 8;
#pragma unroll
        for (int j = 0; j < 4; j++) {
            int col = n0 + warpN * 32 + j * 8 + 2 * c;
            if (col >= N_real) continue;
            float bv0 = __ldg(&bias[col]);
            float bv1 = __ldg(&bias[col + 1]);
            float v0 = acc[mt][j][0] + bv0;
            float v1 = acc[mt][j][1] + bv1;
            float v2 = acc[mt][j][2] + bv0;
            float v3 = acc[mt][j][3] + bv1;
            if (ACT == 1) {
                v0 = v0 > 0.f ? v0 : 0.f; v1 = v1 > 0.f ? v1 : 0.f;
                v2 = v2 > 0.f ? v2 : 0.f; v3 = v3 > 0.f ? v3 : 0.f;
            } else {
                v0 = 1.f / (1.f + expf(-v0)); v1 = 1.f / (1.f + expf(-v1));
                v2 = 1.f / (1.f + expf(-v2)); v3 = 1.f / (1.f + expf(-v3));
            }
            *(float2*)&C[(size_t)R1 * N_real + col] = make_float2(v0, v1);
            *(float2*)&C[(size_t)R2 * N_real + col] = make_float2(v2, v3);
        }
    }
}

// ---------------- launcher ----------------
extern "C" void kernel_launch(void* const* d_in, const int* in_sizes, int n_in,
                              void* d_out, int out_size) {
    const float* x = (const float*)d_in[0];
    const float* y = (const float*)d_in[1];
    const float* conv1_w = (const float*)d_in[2];
    const float* conv1_b = (const float*)d_in[3];
    const float* prim_w = (const float*)d_in[4];
    const float* prim_bias = (const float*)d_in[5];
    const float* conv_w = (const float*)d_in[6];
    const float* conv_bias = (const float*)d_in[7];
    const float* digit_w = (const float*)d_in[8];
    const float* digit_bias = (const float*)d_in[9];
    const float* fc1_w = (const float*)d_in[10];
    const float* fc1_b = (const float*)d_in[11];
    const float* fc2_w = (const float*)d_in[12];
    const float* fc2_b = (const float*)d_in[13];
    const float* fc3_w = (const float*)d_in[14];
    const float* fc3_b = (const float*)d_in[15];
    float* out = (float*)d_out;              // [0:81920) dcap, [81920:483328) recon

    static float *p_masked = nullptr, *p_r1 = nullptr, *p_r2 = nullptr;
    static unsigned short *p_fw1 = nullptr, *p_fw2 = nullptr, *p_fw3 = nullptr;
    static bool attrs_set = false;
    if (!p_masked) {
        cudaGetSymbolAddress((void**)&p_masked, g_masked);
        cudaGetSymbolAddress((void**)&p_r1, g_r1);
        cudaGetSymbolAddress((void**)&p_r2, g_r2);
        cudaGetSymbolAddress((void**)&p_fw1, g_fw1);
        cudaGetSymbolAddress((void**)&p_fw2, g_fw2);
        cudaGetSymbolAddress((void**)&p_fw3, g_fw3);
    }
    if (!attrs_set) {
        cudaFuncSetAttribute(prim_mma_kernel, cudaFuncAttributeMaxDynamicSharedMemorySize,
                             PRIM_SMEM);
        cudaFuncSetAttribute(conv1_mma_kernel, cudaFuncAttributeMaxDynamicSharedMemorySize,
                             C1_SMEM);
        cudaFuncSetAttribute(cc_votes_mma_kernel, cudaFuncAttributeMaxDynamicSharedMemorySize,
                             V_SMEM);
        cudaFuncSetAttribute(fc_mma_kernel<1>, cudaFuncAttributeMaxDynamicSharedMemorySize,
                             F_SMEM);
        cudaFuncSetAttribute(fc_mma_kernel<2>, cudaFuncAttributeMaxDynamicSharedMemorySize,
                             F_SMEM);
        attrs_set = true;
    }

    // weight prep
    prepack_W<<<(25 * 4 * 256 * 64 + 255) / 256, 256>>>(prim_w);
    prepack_c1<<<(256 * 96 + 255) / 256, 256>>>(conv1_w);
    prepack_cc<<<(4 * 256 * 64 + 255) / 256, 256>>>(conv_w);
    prepack_fc<<<(3 * 512 * 64 + 255) / 256, 256>>>(fc1_w, p_fw1, 160, 512, 512,
                                                    3 * 512 * 64);
    prepack_fc<<<(8 * 1024 * 64 + 255) / 256, 256>>>(fc2_w, p_fw2, 512, 1024, 1024,
                                                     8 * 1024 * 64);
    prepack_fc<<<(16 * 1024 * 64 + 255) / 256, 256>>>(fc3_w, p_fw3, 1024, 784, 1024,
                                                      16 * 1024 * 64);

    // conv1 + relu via tensor cores
    conv1_mma_kernel<<<1600, 512, C1_SMEM>>>(x, conv1_b);

    // primary caps conv via mma.sync + fused squash
    prim_mma_kernel<<<256, 512, PRIM_SMEM>>>(prim_bias);

    // conv caps votes via mma.sync
    cc_votes_mma_kernel<<<512, 512, V_SMEM>>>();

    // conv caps routing (warp-parallel softmax)
    cc_routing_kernel<<<2048, 256>>>(conv_bias);

    // digit caps (warp-parallel softmax)
    digit_kernel<<<512, 256>>>(digit_w, digit_bias, y, out);

    // FC reconstruction chain via mma.sync
    fc_mma_kernel<1><<<dim3(2, 4), 512, F_SMEM>>>(p_masked, p_fw1, fc1_b, p_r1,
                                                  160, 3, 512, 512);
    fc_mma_kernel<1><<<dim3(4, 4), 512, F_SMEM>>>(p_r1, p_fw2, fc2_b, p_r2,
                                                  512, 8, 1024, 1024);
    fc_mma_kernel<2><<<dim3(4, 4), 512, F_SMEM>>>(p_r2, p_fw3, fc3_b, out + 81920,
                                                  1024, 16, 1024, 784);
}